// round 5
// baseline (speedup 1.0000x reference)
#include <cuda_runtime.h>
#include <cuda_bf16.h>
#include <math.h>
#include <stdint.h>
#include <stddef.h>

#define Bc 2
#define Lc 2048
#define Dc 2048
#define Hc 32
#define HKVc 8
#define HDc 64
#define Mtok (Bc*Lc)
#define QKVN 3072          // fused projection width: 2048 Q | 512 K | 512 V

typedef __nv_bfloat16 bf16;
typedef __nv_bfloat162 bf162;

// ---------------- scratch (__device__ globals; no allocs allowed) -----------
__device__ float g_qkv[(size_t)Mtok*QKVN];              // 50 MB fused QKV out

__device__ __align__(16) bf16 g_xh[(size_t)Mtok*Dc];
__device__ __align__(16) bf16 g_xl[(size_t)Mtok*Dc];
__device__ __align__(16) bf16 g_wqkvT_h[(size_t)QKVN*Dc];
__device__ __align__(16) bf16 g_wqkvT_l[(size_t)QKVN*Dc];
__device__ __align__(16) bf16 g_woT_h[(size_t)Dc*Hc*HDc];
__device__ __align__(16) bf16 g_woT_l[(size_t)Dc*Hc*HDc];
__device__ __align__(16) bf16 g_qh[(size_t)Bc*Hc*Lc*HDc];
__device__ __align__(16) bf16 g_ql[(size_t)Bc*Hc*Lc*HDc];
__device__ __align__(16) bf16 g_kh[(size_t)Bc*HKVc*Lc*HDc];
__device__ __align__(16) bf16 g_kl[(size_t)Bc*HKVc*Lc*HDc];
__device__ __align__(16) bf16 g_vh[(size_t)Bc*HKVc*Lc*HDc];
__device__ __align__(16) bf16 g_vl[(size_t)Bc*HKVc*Lc*HDc];
__device__ __align__(16) bf16 g_ath[(size_t)Mtok*Hc*HDc];
__device__ __align__(16) bf16 g_atl[(size_t)Mtok*Hc*HDc];

// ---------------- PTX helpers ----------------------------------------------
#define MMA4(CR, A, B0, B1)                                                  \
  asm volatile(                                                              \
      "mma.sync.aligned.m16n8k16.row.col.f32.bf16.bf16.f32 "                 \
      "{%0,%1,%2,%3},{%4,%5,%6,%7},{%8,%9},{%0,%1,%2,%3};"                   \
      : "+f"((CR)[0]), "+f"((CR)[1]), "+f"((CR)[2]), "+f"((CR)[3])           \
      : "r"((A)[0]), "r"((A)[1]), "r"((A)[2]), "r"((A)[3]), "r"(B0), "r"(B1))

#define LDSM4(R0,R1,R2,R3,ADDR)                                              \
  asm volatile("ldmatrix.sync.aligned.m8n8.x4.shared.b16 {%0,%1,%2,%3},[%4];"\
      : "=r"(R0),"=r"(R1),"=r"(R2),"=r"(R3) : "r"(ADDR))

#define LDSM4T(R0,R1,R2,R3,ADDR)                                             \
  asm volatile("ldmatrix.sync.aligned.m8n8.x4.trans.shared.b16 {%0,%1,%2,%3},[%4];"\
      : "=r"(R0),"=r"(R1),"=r"(R2),"=r"(R3) : "r"(ADDR))

__device__ __forceinline__ void cp16(uint32_t dst, const void* src){
  asm volatile("cp.async.cg.shared.global [%0], [%1], 16;" :: "r"(dst), "l"(src));
}
#define CPCOMMIT() asm volatile("cp.async.commit_group;")
#define CPWAIT0()  asm volatile("cp.async.wait_group 0;")

__device__ __forceinline__ void split1(float v, bf16& h, bf16& l){
  h = __float2bfloat16_rn(v);
  l = __float2bfloat16_rn(v - __bfloat162float(h));
}

// ---------------- convert passes --------------------------------------------
__global__ void splitx(const float* __restrict__ src, bf16* __restrict__ h,
                       bf16* __restrict__ l, int n4)
{
  int i = blockIdx.x * blockDim.x + threadIdx.x;
  if (i >= n4) return;
  float4 v = ((const float4*)src)[i];
  bf16 hh[4], ll[4];
  split1(v.x, hh[0], ll[0]); split1(v.y, hh[1], ll[1]);
  split1(v.z, hh[2], ll[2]); split1(v.w, hh[3], ll[3]);
  bf162 h0; h0.x=hh[0]; h0.y=hh[1];  bf162 h1; h1.x=hh[2]; h1.y=hh[3];
  bf162 l0; l0.x=ll[0]; l0.y=ll[1];  bf162 l1; l1.x=ll[2]; l1.y=ll[3];
  ((bf162*)h)[2*i] = h0; ((bf162*)h)[2*i+1] = h1;
  ((bf162*)l)[2*i] = l0; ((bf162*)l)[2*i+1] = l1;
}

// W [K][N] -> Th/Tl [N][K] (caller offsets Th/Tl for concat)
__global__ void wsplitT(const float* __restrict__ W, bf16* __restrict__ Th,
                        bf16* __restrict__ Tl, int K, int N)
{
  __shared__ float tile[32][33];
  int k0 = blockIdx.y*32, n0 = blockIdx.x*32;
  int tx = threadIdx.x, ty = threadIdx.y;
#pragma unroll
  for (int i = 0; i < 4; i++)
    tile[ty + 8*i][tx] = W[(size_t)(k0 + ty + 8*i) * N + n0 + tx];
  __syncthreads();
#pragma unroll
  for (int i = 0; i < 4; i++){
    int n = n0 + ty + 8*i;
    float v = tile[tx][ty + 8*i];
    bf16 h, l; split1(v, h, l);
    Th[(size_t)n*K + k0 + tx] = h;
    Tl[(size_t)n*K + k0 + tx] = l;
  }
}

// ---------------- split-bf16 tensor-core GEMM -------------------------------
// C[M][N] fp32 = (Ah+Al)[M][K] @ (Bh+Bl)^T, B stored [N][K]. BK=64.
// 256 thr, 8 warps, warp tile 32x64, cp.async double buffer, swizzled smem.
__global__ __launch_bounds__(256) void gemm_split(
    const bf16* __restrict__ Ah, const bf16* __restrict__ Al,
    const bf16* __restrict__ Bh, const bf16* __restrict__ Bl,
    float* __restrict__ C, int M, int N, int K)
{
  extern __shared__ char smraw[];
  const uint32_t smb = (uint32_t)__cvta_generic_to_shared(smraw);
  const int tid = threadIdx.x, lane = tid & 31, warp = tid >> 5;
  const int wm = (warp & 3) * 32, wn = (warp >> 2) * 64;
  const int g = lane >> 2, t = lane & 3;
  const int row0 = blockIdx.y * 128, col0 = blockIdx.x * 128;
  const int KI = K >> 6;

  const bf16* gsrc[4] = { Ah + (size_t)row0 * K, Al + (size_t)row0 * K,
                          Bh + (size_t)col0 * K, Bl + (size_t)col0 * K };

  auto stage = [&](int ki, int s){
#pragma unroll
    for (int q = 0; q < 4; q++)
#pragma unroll
      for (int it = 0; it < 4; it++){
        int fid = tid + it * 256;
        int row = fid >> 3, ch = fid & 7;
        cp16(smb + s*65536 + q*16384 + row*128 + ((ch ^ (row & 7)) * 16),
             gsrc[q] + (size_t)row * K + ki*64 + ch*8);
      }
  };

  float c[2][8][4];
#pragma unroll
  for (int i=0;i<2;i++)
#pragma unroll
    for (int j=0;j<8;j++)
#pragma unroll
      for (int e=0;e<4;e++) c[i][j][e] = 0.f;

  stage(0, 0); CPCOMMIT();

  for (int ki = 0; ki < KI; ki++){
    int s = ki & 1;
    CPWAIT0();
    __syncthreads();
    if (ki + 1 < KI){ stage(ki + 1, s ^ 1); CPCOMMIT(); }

    const uint32_t ab = smb + s*65536, bb = ab + 32768;
    const int rA  = (lane & 7) + ((lane >> 3) & 1) * 8;
    const int chA = (lane >> 4);
    const int rB  = (lane & 7) + ((lane >> 4) << 3);
    const int chB = (lane >> 3) & 1;
#pragma unroll
    for (int kc = 0; kc < 4; kc++){
      uint32_t ah[2][4], al[2][4];
#pragma unroll
      for (int mt = 0; mt < 2; mt++){
        int r = wm + mt*16 + rA;
        int ch = kc*2 + chA;
        uint32_t ad = ab + r*128 + ((ch ^ (r & 7)) * 16);
        LDSM4(ah[mt][0], ah[mt][1], ah[mt][2], ah[mt][3], ad);
        LDSM4(al[mt][0], al[mt][1], al[mt][2], al[mt][3], ad + 16384);
      }
#pragma unroll
      for (int ntp = 0; ntp < 4; ntp++){
        int r = wn + ntp*16 + rB;
        int ch = kc*2 + chB;
        uint32_t ad = bb + r*128 + ((ch ^ (r & 7)) * 16);
        uint32_t bh0,bh1,bh2,bh3, bl0,bl1,bl2,bl3;
        LDSM4(bh0,bh1,bh2,bh3, ad);
        LDSM4(bl0,bl1,bl2,bl3, ad + 16384);
#pragma unroll
        for (int mt = 0; mt < 2; mt++){
          MMA4(c[mt][2*ntp],   ah[mt], bh0, bh1);
          MMA4(c[mt][2*ntp+1], ah[mt], bh2, bh3);
          MMA4(c[mt][2*ntp],   ah[mt], bl0, bl1);
          MMA4(c[mt][2*ntp+1], ah[mt], bl2, bl3);
          MMA4(c[mt][2*ntp],   al[mt], bh0, bh1);
          MMA4(c[mt][2*ntp+1], al[mt], bh2, bh3);
        }
      }
    }
    __syncthreads();
  }

#pragma unroll
  for (int mt = 0; mt < 2; mt++)
#pragma unroll
    for (int nt = 0; nt < 8; nt++){
      int r = row0 + wm + mt*16 + g;
      int cc = col0 + wn + nt*8 + 2*t;
      float2 v0 = { c[mt][nt][0], c[mt][nt][1] };
      float2 v1 = { c[mt][nt][2], c[mt][nt][3] };
      *(float2*)(C + (size_t)r * N + cc) = v0;
      *(float2*)(C + (size_t)(r + 8) * N + cc) = v1;
    }
}

// ---------------- RMSNorm + RoPE -> split bf16, head-major ------------------
__global__ __launch_bounds__(256) void rmsrope_split(
    const float* __restrict__ qkv, const float* __restrict__ w,
    bf16* __restrict__ oh, bf16* __restrict__ ol, int nh, int nrows, int coloff)
{
  int wid = (blockIdx.x * blockDim.x + threadIdx.x) >> 5;
  int lane = threadIdx.x & 31;
  if (wid >= nrows) return;
  int head = wid % nh;
  int bl = wid / nh;
  int pos = bl % Lc;
  int b = bl / Lc;

  const float* row = qkv + (size_t)bl * QKVN + coloff + head * HDc;
  float x1 = row[lane], x2 = row[lane + 32];

  float ss = x1*x1 + x2*x2;
#pragma unroll
  for (int o = 16; o > 0; o >>= 1) ss += __shfl_xor_sync(0xffffffffu, ss, o);
  float r = rsqrtf(ss * (1.0f/64.0f) + 1e-5f);

  float x1n = x1 * r * w[lane];
  float x2n = x2 * r * w[lane + 32];

  float expnt = -((float)(2*lane)) * (1.0f/64.0f);
  float invf = powf(1000000.0f, expnt);
  float ang = (float)pos * invf;
  float cth = cosf(ang), sth = sinf(ang);

  float y1 = x1n*cth - x2n*sth;
  float y2 = x2n*cth + x1n*sth;

  size_t ob = ((size_t)(b*nh + head)*Lc + pos) * HDc;
  bf16 h, l;
  split1(y1, h, l); oh[ob + lane] = h;      ol[ob + lane] = l;
  split1(y2, h, l); oh[ob + lane + 32] = h; ol[ob + lane + 32] = l;
}

__global__ __launch_bounds__(256) void vsplit_kernel(
    const float* __restrict__ qkv, bf16* __restrict__ oh, bf16* __restrict__ ol,
    int nrows)
{
  int wid = (blockIdx.x * blockDim.x + threadIdx.x) >> 5;
  int lane = threadIdx.x & 31;
  if (wid >= nrows) return;
  int head = wid % HKVc;
  int bl = wid / HKVc;
  int pos = bl % Lc;
  int b = bl / Lc;
  const float* row = qkv + (size_t)bl * QKVN + 2560 + head * HDc;
  size_t ob = ((size_t)(b*HKVc + head)*Lc + pos) * HDc;
  bf16 h, l;
  split1(row[lane],      h, l); oh[ob + lane] = h;      ol[ob + lane] = l;
  split1(row[lane + 32], h, l); oh[ob + lane + 32] = h; ol[ob + lane + 32] = l;
}

// ---------------- tensor-core flash attention (HMMA) ------------------------
// 128 q-rows x 64 kv tile, 256 threads (8 warps x 16 q-rows), 2 CTAs/SM.
// smem: Q hi 16K | Q lo 16K | 2 stages x (Khi 8K|Klo 8K|Vhi 8K|Vlo 8K)
#define FKV0   32768
#define KV_STG 32768
#define FLASH_SMEM (32768 + 2*KV_STG)

__global__ __launch_bounds__(256,2) void flash_tc(
    const bf16* __restrict__ Qh, const bf16* __restrict__ Ql,
    const bf16* __restrict__ Kh, const bf16* __restrict__ Kl,
    const bf16* __restrict__ Vh, const bf16* __restrict__ Vl,
    bf16* __restrict__ Oh, bf16* __restrict__ Ol)
{
  extern __shared__ char smraw[];
  const uint32_t smb = (uint32_t)__cvta_generic_to_shared(smraw);
  const int tid = threadIdx.x, lane = tid & 31, warp = tid >> 5;
  const int qt = gridDim.x - 1 - blockIdx.x;   // big tiles first
  const int h = blockIdx.y, b = blockIdx.z, hkv = h >> 2;
  const int g = lane >> 2, t = lane & 3;

  const bf16* qhp = Qh + ((size_t)(b*Hc + h)*Lc + qt*128) * HDc;
  const bf16* qlp = Ql + ((size_t)(b*Hc + h)*Lc + qt*128) * HDc;
  const size_t kvoff = (size_t)(b*HKVc + hkv) * Lc * HDc;
  const bf16* kvsrc[4] = { Kh + kvoff, Kl + kvoff, Vh + kvoff, Vl + kvoff };

  // stage Q (once): 128 rows x 64 cols, hi+lo
#pragma unroll
  for (int it = 0; it < 4; it++){
    int fid = tid + it * 256;           // 0..1023
    int row = fid >> 3, ch = fid & 7;
    uint4 vh4 = *(const uint4*)(qhp + row*64 + ch*8);
    uint4 vl4 = *(const uint4*)(qlp + row*64 + ch*8);
    int off = row*128 + ((ch ^ (row & 7)) * 16);
    *(uint4*)(smraw + off)         = vh4;
    *(uint4*)(smraw + 16384 + off) = vl4;
  }

  auto stageKV = [&](int j, int s){
#pragma unroll
    for (int q = 0; q < 4; q++)
#pragma unroll
      for (int it = 0; it < 2; it++){
        int fid = tid + it * 256;       // 0..511
        int row = fid >> 3, ch = fid & 7;
        cp16(smb + FKV0 + s*KV_STG + q*8192 + row*128 + ((ch ^ (row & 7))*16),
             kvsrc[q] + (size_t)(j*64 + row)*64 + ch*8);
      }
  };

  stageKV(0, 0); CPCOMMIT();
  __syncthreads();

  // Q fragments (persistent)
  uint32_t qfh[4][4], qfl[4][4];
  {
    int r = warp*16 + (lane & 7) + ((lane >> 3) & 1) * 8;
#pragma unroll
    for (int kc = 0; kc < 4; kc++){
      int ch = kc*2 + (lane >> 4);
      uint32_t ad = smb + r*128 + ((ch ^ (r & 7)) * 16);
      LDSM4(qfh[kc][0], qfh[kc][1], qfh[kc][2], qfh[kc][3], ad);
      LDSM4(qfl[kc][0], qfl[kc][1], qfl[kc][2], qfl[kc][3], ad + 16384);
    }
  }

  float o[8][4];
#pragma unroll
  for (int nt=0;nt<8;nt++)
#pragma unroll
    for (int e=0;e<4;e++) o[nt][e] = 0.f;
  float m0r = -1e30f, m1r = -1e30f, l0 = 0.f, l1 = 0.f;

  const int r0g = qt*128 + warp*16 + g;
  const int r1g = r0g + 8;
  const int rBv = (lane & 7) + ((lane >> 4) << 3);
  const int chBv = (lane >> 3) & 1;
  const int rVv = (lane & 7) + (((lane >> 3) & 1) << 3);
  const int chVv = lane >> 4;
  const int jmax = 2*qt + 1;

  for (int j = 0; j <= jmax; j++){
    int s = j & 1;
    CPWAIT0();
    __syncthreads();
    if (j < jmax){ stageKV(j + 1, s ^ 1); CPCOMMIT(); }

    const uint32_t kb = smb + FKV0 + s*KV_STG;

    float sf[8][4];
#pragma unroll
    for (int nt=0;nt<8;nt++)
#pragma unroll
      for (int e=0;e<4;e++) sf[nt][e] = 0.f;

    // S = Q K^T (3-term split)
#pragma unroll
    for (int kc = 0; kc < 4; kc++){
#pragma unroll
      for (int ntp = 0; ntp < 4; ntp++){
        int r = ntp*16 + rBv;
        int ch = kc*2 + chBv;
        uint32_t ad = kb + r*128 + ((ch ^ (r & 7)) * 16);
        uint32_t bh0,bh1,bh2,bh3, bl0,bl1,bl2,bl3;
        LDSM4(bh0,bh1,bh2,bh3, ad);
        LDSM4(bl0,bl1,bl2,bl3, ad + 8192);
        MMA4(sf[2*ntp],   qfh[kc], bh0, bh1);
        MMA4(sf[2*ntp+1], qfh[kc], bh2, bh3);
        MMA4(sf[2*ntp],   qfh[kc], bl0, bl1);
        MMA4(sf[2*ntp+1], qfh[kc], bl2, bl3);
        MMA4(sf[2*ntp],   qfl[kc], bh0, bh1);
        MMA4(sf[2*ntp+1], qfl[kc], bh2, bh3);
      }
    }

    // scale + (near-diagonal) causal mask + online softmax
    float tm0 = -1e30f, tm1 = -1e30f;
    const bool mayMask = (j*64 + 63 > r0g);
#pragma unroll
    for (int nt = 0; nt < 8; nt++){
      int c0 = j*64 + nt*8 + 2*t;
      float v0 = sf[nt][0]*0.125f, v1 = sf[nt][1]*0.125f;
      float v2 = sf[nt][2]*0.125f, v3 = sf[nt][3]*0.125f;
      if (mayMask){
        if (c0     > r0g) v0 = -1e30f;
        if (c0 + 1 > r0g) v1 = -1e30f;
        if (c0     > r1g) v2 = -1e30f;
        if (c0 + 1 > r1g) v3 = -1e30f;
      }
      sf[nt][0]=v0; sf[nt][1]=v1; sf[nt][2]=v2; sf[nt][3]=v3;
      tm0 = fmaxf(tm0, fmaxf(v0, v1));
      tm1 = fmaxf(tm1, fmaxf(v2, v3));
    }
    tm0 = fmaxf(tm0, __shfl_xor_sync(0xffffffffu, tm0, 1));
    tm0 = fmaxf(tm0, __shfl_xor_sync(0xffffffffu, tm0, 2));
    tm1 = fmaxf(tm1, __shfl_xor_sync(0xffffffffu, tm1, 1));
    tm1 = fmaxf(tm1, __shfl_xor_sync(0xffffffffu, tm1, 2));

    float mn0 = fmaxf(m0r, tm0), mn1 = fmaxf(m1r, tm1);
    float corr0 = __expf(m0r - mn0), corr1 = __expf(m1r - mn1);
    float s0 = 0.f, s1 = 0.f;
#pragma unroll
    for (int nt = 0; nt < 8; nt++){
      sf[nt][0] = __expf(sf[nt][0] - mn0);
      sf[nt][1] = __expf(sf[nt][1] - mn0);
      sf[nt][2] = __expf(sf[nt][2] - mn1);
      sf[nt][3] = __expf(sf[nt][3] - mn1);
      s0 += sf[nt][0] + sf[nt][1];
      s1 += sf[nt][2] + sf[nt][3];
    }
    s0 += __shfl_xor_sync(0xffffffffu, s0, 1);
    s0 += __shfl_xor_sync(0xffffffffu, s0, 2);
    s1 += __shfl_xor_sync(0xffffffffu, s1, 1);
    s1 += __shfl_xor_sync(0xffffffffu, s1, 2);
    l0 = l0*corr0 + s0;  l1 = l1*corr1 + s1;
    m0r = mn0;  m1r = mn1;
#pragma unroll
    for (int nt = 0; nt < 8; nt++){
      o[nt][0] *= corr0; o[nt][1] *= corr0;
      o[nt][2] *= corr1; o[nt][3] *= corr1;
    }

    // O += P V (3-term split; P C-frag -> A-frag in registers)
    const uint32_t vb = kb + 16384;
#pragma unroll
    for (int kc = 0; kc < 4; kc++){
      uint32_t ph[4], pl[4];
#pragma unroll
      for (int q2 = 0; q2 < 2; q2++){
        float c0 = sf[2*kc+q2][0], c1 = sf[2*kc+q2][1];
        float c2 = sf[2*kc+q2][2], c3 = sf[2*kc+q2][3];
        bf16 h0,h1,h2,h3, e0,e1,e2,e3;
        split1(c0,h0,e0); split1(c1,h1,e1); split1(c2,h2,e2); split1(c3,h3,e3);
        bf162 p01; p01.x=h0; p01.y=h1;  bf162 p23; p23.x=h2; p23.y=h3;
        bf162 q01; q01.x=e0; q01.y=e1;  bf162 q23; q23.x=e2; q23.y=e3;
        ph[2*q2 + 0] = *(uint32_t*)&p01;  ph[2*q2 + 1] = *(uint32_t*)&p23;
        pl[2*q2 + 0] = *(uint32_t*)&q01;  pl[2*q2 + 1] = *(uint32_t*)&q23;
      }
#pragma unroll
      for (int ntp = 0; ntp < 4; ntp++){
        int r = kc*16 + rVv;
        int ch = ntp*2 + chVv;
        uint32_t ad = vb + r*128 + ((ch ^ (r & 7)) * 16);
        uint32_t wh0,wh1,wh2,wh3, wl0,wl1,wl2,wl3;
        LDSM4T(wh0,wh1,wh2,wh3, ad);
        LDSM4T(wl0,wl1,wl2,wl3, ad + 8192);
        MMA4(o[2*ntp],   ph, wh0, wh1);
        MMA4(o[2*ntp+1], ph, wh2, wh3);
        MMA4(o[2*ntp],   ph, wl0, wl1);
        MMA4(o[2*ntp+1], ph, wl2, wl3);
        MMA4(o[2*ntp],   pl, wh0, wh1);
        MMA4(o[2*ntp+1], pl, wh2, wh3);
      }
    }
  }

  // epilogue: normalize, write split bf16 attn [b][l][h][d]
  float inv0 = 1.f / l0, inv1 = 1.f / l1;
  size_t ob0 = ((size_t)(b*Lc + qt*128 + warp*16 + g) * Hc + h) * HDc;
  size_t ob1 = ob0 + (size_t)8 * Hc * HDc;
#pragma unroll
  for (int nt = 0; nt < 8; nt++){
    int d = nt*8 + 2*t;
    float v0 = o[nt][0]*inv0, v1 = o[nt][1]*inv0;
    float v2 = o[nt][2]*inv1, v3 = o[nt][3]*inv1;
    bf16 h0,h1,h2,h3, e0,e1,e2,e3;
    split1(v0,h0,e0); split1(v1,h1,e1); split1(v2,h2,e2); split1(v3,h3,e3);
    bf162 a; a.x=h0; a.y=h1;  bf162 c; c.x=e0; c.y=e1;
    bf162 d2; d2.x=h2; d2.y=h3; bf162 f; f.x=e2; f.y=e3;
    *(bf162*)(Oh + ob0 + d) = a;  *(bf162*)(Ol + ob0 + d) = c;
    *(bf162*)(Oh + ob1 + d) = d2; *(bf162*)(Ol + ob1 + d) = f;
  }
}

// ---------------------------------------------------------------------------
extern "C" void kernel_launch(void* const* d_in, const int* in_sizes, int n_in,
                              void* d_out, int out_size)
{
  const float* x   = (const float*)d_in[0];
  const float* Wq  = (const float*)d_in[1];
  const float* Wk  = (const float*)d_in[2];
  const float* Wv  = (const float*)d_in[3];
  const float* Wo  = (const float*)d_in[4];
  const float* qnw = (const float*)d_in[5];
  const float* knw = (const float*)d_in[6];
  float* out = (float*)d_out;

  float *qkv;
  bf16 *xh,*xl,*wqkvh,*wqkvl,*woh,*wol;
  bf16 *qh,*ql,*kh,*kl,*vh,*vl,*ath,*atl;
  cudaGetSymbolAddress((void**)&qkv, g_qkv);
  cudaGetSymbolAddress((void**)&xh, g_xh);   cudaGetSymbolAddress((void**)&xl, g_xl);
  cudaGetSymbolAddress((void**)&wqkvh, g_wqkvT_h);
  cudaGetSymbolAddress((void**)&wqkvl, g_wqkvT_l);
  cudaGetSymbolAddress((void**)&woh, g_woT_h); cudaGetSymbolAddress((void**)&wol, g_woT_l);
  cudaGetSymbolAddress((void**)&qh, g_qh); cudaGetSymbolAddress((void**)&ql, g_ql);
  cudaGetSymbolAddress((void**)&kh, g_kh); cudaGetSymbolAddress((void**)&kl, g_kl);
  cudaGetSymbolAddress((void**)&vh, g_vh); cudaGetSymbolAddress((void**)&vl, g_vl);
  cudaGetSymbolAddress((void**)&ath, g_ath); cudaGetSymbolAddress((void**)&atl, g_atl);

  const int M = Mtok;

  // converts (weights concatenated into [3072][2048] transposed hi/lo)
  splitx<<<(M*Dc/4 + 255)/256, 256>>>(x, xh, xl, M*Dc/4);
  wsplitT<<<dim3((Hc*HDc)/32, Dc/32), dim3(32,8)>>>(Wq, wqkvh, wqkvl, Dc, Hc*HDc);
  wsplitT<<<dim3((HKVc*HDc)/32, Dc/32), dim3(32,8)>>>(
      Wk, wqkvh + (size_t)2048*Dc, wqkvl + (size_t)2048*Dc, Dc, HKVc*HDc);
  wsplitT<<<dim3((HKVc*HDc)/32, Dc/32), dim3(32,8)>>>(
      Wv, wqkvh + (size_t)2560*Dc, wqkvl + (size_t)2560*Dc, Dc, HKVc*HDc);
  wsplitT<<<dim3(Dc/32, (Hc*HDc)/32), dim3(32,8)>>>(Wo, woh, wol, Hc*HDc, Dc);

  // fused QKV projection: C [M][3072]
  cudaFuncSetAttribute(gemm_split, cudaFuncAttributeMaxDynamicSharedMemorySize, 131072);
  gemm_split<<<dim3(QKVN/128, M/128), 256, 131072>>>(xh, xl, wqkvh, wqkvl, qkv, M, QKVN, Dc);

  // norm + rope + split (head-major)
  rmsrope_split<<<(M*Hc)/8, 256>>>(qkv, qnw, qh, ql, Hc, M*Hc, 0);
  rmsrope_split<<<(M*HKVc)/8, 256>>>(qkv, knw, kh, kl, HKVc, M*HKVc, 2048);
  vsplit_kernel<<<(M*HKVc)/8, 256>>>(qkv, vh, vl, M*HKVc);

  // flash attention (128-row q tiles)
  cudaFuncSetAttribute(flash_tc, cudaFuncAttributeMaxDynamicSharedMemorySize, FLASH_SMEM);
  flash_tc<<<dim3(Lc/128, Hc, Bc), 256, FLASH_SMEM>>>(qh, ql, kh, kl, vh, vl, ath, atl);

  // output projection
  gemm_split<<<dim3(Dc/128, M/128), 256, 131072>>>(ath, atl, woh, wol, out, M, Dc, Dc);
}

// round 6
// speedup vs baseline: 1.2679x; 1.2679x over previous
#include <cuda_runtime.h>
#include <cuda_bf16.h>
#include <cuda_fp16.h>
#include <math.h>
#include <stdint.h>
#include <stddef.h>

#define Bc 2
#define Lc 2048
#define Dc 2048
#define Hc 32
#define HKVc 8
#define HDc 64
#define Mtok (Bc*Lc)
#define QKVN 3072          // fused projection width: 2048 Q | 512 K | 512 V

typedef __nv_bfloat16 bf16;
typedef __nv_bfloat162 bf162;
typedef __half half_t;

// ---------------- scratch (__device__ globals; no allocs allowed) -----------
__device__ float g_qkv[(size_t)Mtok*QKVN];              // 50 MB fused QKV out

__device__ __align__(16) half_t g_xh[(size_t)Mtok*Dc];
__device__ __align__(16) half_t g_xl[(size_t)Mtok*Dc];
__device__ __align__(16) half_t g_wqkvT[(size_t)QKVN*Dc];   // single fp16
__device__ __align__(16) half_t g_woT[(size_t)Dc*Hc*HDc];   // single fp16
__device__ __align__(16) bf16 g_qh[(size_t)Bc*Hc*Lc*HDc];
__device__ __align__(16) bf16 g_ql[(size_t)Bc*Hc*Lc*HDc];
__device__ __align__(16) bf16 g_kh[(size_t)Bc*HKVc*Lc*HDc];
__device__ __align__(16) bf16 g_kl[(size_t)Bc*HKVc*Lc*HDc];
__device__ __align__(16) bf16 g_vh[(size_t)Bc*HKVc*Lc*HDc];
__device__ __align__(16) bf16 g_vl[(size_t)Bc*HKVc*Lc*HDc];
__device__ __align__(16) half_t g_ath[(size_t)Mtok*Hc*HDc];
__device__ __align__(16) half_t g_atl[(size_t)Mtok*Hc*HDc];

// ---------------- PTX helpers ----------------------------------------------
#define MMA4(CR, A, B0, B1)                                                  \
  asm volatile(                                                              \
      "mma.sync.aligned.m16n8k16.row.col.f32.bf16.bf16.f32 "                 \
      "{%0,%1,%2,%3},{%4,%5,%6,%7},{%8,%9},{%0,%1,%2,%3};"                   \
      : "+f"((CR)[0]), "+f"((CR)[1]), "+f"((CR)[2]), "+f"((CR)[3])           \
      : "r"((A)[0]), "r"((A)[1]), "r"((A)[2]), "r"((A)[3]), "r"(B0), "r"(B1))

#define MMAH(CR, A, B0, B1)                                                  \
  asm volatile(                                                              \
      "mma.sync.aligned.m16n8k16.row.col.f32.f16.f16.f32 "                   \
      "{%0,%1,%2,%3},{%4,%5,%6,%7},{%8,%9},{%0,%1,%2,%3};"                   \
      : "+f"((CR)[0]), "+f"((CR)[1]), "+f"((CR)[2]), "+f"((CR)[3])           \
      : "r"((A)[0]), "r"((A)[1]), "r"((A)[2]), "r"((A)[3]), "r"(B0), "r"(B1))

#define LDSM4(R0,R1,R2,R3,ADDR)                                              \
  asm volatile("ldmatrix.sync.aligned.m8n8.x4.shared.b16 {%0,%1,%2,%3},[%4];"\
      : "=r"(R0),"=r"(R1),"=r"(R2),"=r"(R3) : "r"(ADDR))

#define LDSM4T(R0,R1,R2,R3,ADDR)                                             \
  asm volatile("ldmatrix.sync.aligned.m8n8.x4.trans.shared.b16 {%0,%1,%2,%3},[%4];"\
      : "=r"(R0),"=r"(R1),"=r"(R2),"=r"(R3) : "r"(ADDR))

__device__ __forceinline__ void cp16(uint32_t dst, const void* src){
  asm volatile("cp.async.cg.shared.global [%0], [%1], 16;" :: "r"(dst), "l"(src));
}
#define CPCOMMIT() asm volatile("cp.async.commit_group;")
#define CPWAIT0()  asm volatile("cp.async.wait_group 0;")

__device__ __forceinline__ void split1(float v, bf16& h, bf16& l){
  h = __float2bfloat16_rn(v);
  l = __float2bfloat16_rn(v - __bfloat162float(h));
}
__device__ __forceinline__ void split1h(float v, half_t& h, half_t& l){
  h = __float2half_rn(v);
  l = __float2half_rn(v - __half2float(h));
}

// ---------------- convert passes --------------------------------------------
__global__ void splitx(const float* __restrict__ src, half_t* __restrict__ h,
                       half_t* __restrict__ l, int n4)
{
  int i = blockIdx.x * blockDim.x + threadIdx.x;
  if (i >= n4) return;
  float4 v = ((const float4*)src)[i];
  half_t hh[4], ll[4];
  split1h(v.x, hh[0], ll[0]); split1h(v.y, hh[1], ll[1]);
  split1h(v.z, hh[2], ll[2]); split1h(v.w, hh[3], ll[3]);
  __half2 h0 = {hh[0], hh[1]}, h1 = {hh[2], hh[3]};
  __half2 l0 = {ll[0], ll[1]}, l1 = {ll[2], ll[3]};
  ((__half2*)h)[2*i] = h0; ((__half2*)h)[2*i+1] = h1;
  ((__half2*)l)[2*i] = l0; ((__half2*)l)[2*i+1] = l1;
}

// One launch for all four weight transposes -> single fp16 [N][K]
// z=0: Wq (64x64 tiles), z=1: Wk (16x64), z=2: Wv (16x64), z=3: Wo (64x64)
__global__ void wsplit_all(const float* __restrict__ Wq,
                           const float* __restrict__ Wk,
                           const float* __restrict__ Wv,
                           const float* __restrict__ Wo,
                           half_t* __restrict__ wqkv, half_t* __restrict__ wo)
{
  const int z = blockIdx.z;
  const float* W; half_t* T; int K, N;
  if (z == 0){ W = Wq; T = wqkv;                       K = Dc;     N = Hc*HDc; }
  else if (z == 1){ W = Wk; T = wqkv + (size_t)2048*Dc; K = Dc;    N = HKVc*HDc; }
  else if (z == 2){ W = Wv; T = wqkv + (size_t)2560*Dc; K = Dc;    N = HKVc*HDc; }
  else            { W = Wo; T = wo;                     K = Hc*HDc; N = Dc; }
  if (blockIdx.x * 32 >= N) return;

  __shared__ float tile[32][33];
  int k0 = blockIdx.y*32, n0 = blockIdx.x*32;
  int tx = threadIdx.x, ty = threadIdx.y;
#pragma unroll
  for (int i = 0; i < 4; i++)
    tile[ty + 8*i][tx] = W[(size_t)(k0 + ty + 8*i) * N + n0 + tx];
  __syncthreads();
#pragma unroll
  for (int i = 0; i < 4; i++){
    int n = n0 + ty + 8*i;
    T[(size_t)n*K + k0 + tx] = __float2half_rn(tile[tx][ty + 8*i]);
  }
}

// ---------------- fp16 2-term tensor-core GEMM ------------------------------
// C[M][N] fp32 = (Ah+Al)[M][K] @ B^T, B single fp16 stored [N][K]. BK=64.
// smem/stage: Ah 16K | Al 16K | B 16K. 256 thr, 8 warps, warp tile 32x64.
#define GSTG2 49152
__global__ __launch_bounds__(256) void gemm_fp16(
    const half_t* __restrict__ Ah, const half_t* __restrict__ Al,
    const half_t* __restrict__ B, float* __restrict__ C, int M, int N, int K)
{
  extern __shared__ char smraw[];
  const uint32_t smb = (uint32_t)__cvta_generic_to_shared(smraw);
  const int tid = threadIdx.x, lane = tid & 31, warp = tid >> 5;
  const int wm = (warp & 3) * 32, wn = (warp >> 2) * 64;
  const int g = lane >> 2, t = lane & 3;
  const int row0 = blockIdx.y * 128, col0 = blockIdx.x * 128;
  const int KI = K >> 6;

  const half_t* gsrc[3] = { Ah + (size_t)row0 * K, Al + (size_t)row0 * K,
                            B + (size_t)col0 * K };

  auto stage = [&](int ki, int s){
#pragma unroll
    for (int q = 0; q < 3; q++)
#pragma unroll
      for (int it = 0; it < 4; it++){
        int fid = tid + it * 256;
        int row = fid >> 3, ch = fid & 7;
        cp16(smb + s*GSTG2 + q*16384 + row*128 + ((ch ^ (row & 7)) * 16),
             gsrc[q] + (size_t)row * K + ki*64 + ch*8);
      }
  };

  float c[2][8][4];
#pragma unroll
  for (int i=0;i<2;i++)
#pragma unroll
    for (int j=0;j<8;j++)
#pragma unroll
      for (int e=0;e<4;e++) c[i][j][e] = 0.f;

  stage(0, 0); CPCOMMIT();

  for (int ki = 0; ki < KI; ki++){
    int s = ki & 1;
    CPWAIT0();
    __syncthreads();
    if (ki + 1 < KI){ stage(ki + 1, s ^ 1); CPCOMMIT(); }

    const uint32_t ab = smb + s*GSTG2, bb = ab + 32768;
    const int rA  = (lane & 7) + ((lane >> 3) & 1) * 8;
    const int chA = (lane >> 4);
    const int rB  = (lane & 7) + ((lane >> 4) << 3);
    const int chB = (lane >> 3) & 1;
#pragma unroll
    for (int kc = 0; kc < 4; kc++){
      uint32_t ah[2][4], al[2][4];
#pragma unroll
      for (int mt = 0; mt < 2; mt++){
        int r = wm + mt*16 + rA;
        int ch = kc*2 + chA;
        uint32_t ad = ab + r*128 + ((ch ^ (r & 7)) * 16);
        LDSM4(ah[mt][0], ah[mt][1], ah[mt][2], ah[mt][3], ad);
        LDSM4(al[mt][0], al[mt][1], al[mt][2], al[mt][3], ad + 16384);
      }
#pragma unroll
      for (int ntp = 0; ntp < 4; ntp++){
        int r = wn + ntp*16 + rB;
        int ch = kc*2 + chB;
        uint32_t ad = bb + r*128 + ((ch ^ (r & 7)) * 16);
        uint32_t b0,b1,b2,b3;
        LDSM4(b0,b1,b2,b3, ad);
#pragma unroll
        for (int mt = 0; mt < 2; mt++){
          MMAH(c[mt][2*ntp],   ah[mt], b0, b1);
          MMAH(c[mt][2*ntp+1], ah[mt], b2, b3);
          MMAH(c[mt][2*ntp],   al[mt], b0, b1);
          MMAH(c[mt][2*ntp+1], al[mt], b2, b3);
        }
      }
    }
    __syncthreads();
  }

#pragma unroll
  for (int mt = 0; mt < 2; mt++)
#pragma unroll
    for (int nt = 0; nt < 8; nt++){
      int r = row0 + wm + mt*16 + g;
      int cc = col0 + wn + nt*8 + 2*t;
      float2 v0 = { c[mt][nt][0], c[mt][nt][1] };
      float2 v1 = { c[mt][nt][2], c[mt][nt][3] };
      *(float2*)(C + (size_t)r * N + cc) = v0;
      *(float2*)(C + (size_t)(r + 8) * N + cc) = v1;
    }
}

// ---------------- fused post-QKV: RMSNorm+RoPE (Q,K) + V split --------------
// One warp per 64-wide head row across all three sections.
__global__ __launch_bounds__(256) void qkvpost(
    const float* __restrict__ qkv, const float* __restrict__ qnw,
    const float* __restrict__ knw,
    bf16* __restrict__ qh, bf16* __restrict__ ql,
    bf16* __restrict__ kh, bf16* __restrict__ kl,
    bf16* __restrict__ vh, bf16* __restrict__ vl)
{
  int wid = (blockIdx.x * blockDim.x + threadIdx.x) >> 5;
  int lane = threadIdx.x & 31;
  const int nQ = Mtok * Hc, nK = Mtok * HKVc;
  if (wid >= nQ + 2*nK) return;

  int nh, coloff, head, bl;
  const float* w;
  bf16 *oh, *ol;
  bool dorope = true;
  if (wid < nQ){
    nh = Hc; head = wid % nh; bl = wid / nh; coloff = 0;
    w = qnw; oh = qh; ol = ql;
  } else if (wid < nQ + nK){
    int wv = wid - nQ;
    nh = HKVc; head = wv % nh; bl = wv / nh; coloff = 2048;
    w = knw; oh = kh; ol = kl;
  } else {
    int wv = wid - nQ - nK;
    nh = HKVc; head = wv % nh; bl = wv / nh; coloff = 2560;
    w = (const float*)0; oh = vh; ol = vl; dorope = false;
  }
  int pos = bl % Lc;
  int b = bl / Lc;

  const float* row = qkv + (size_t)bl * QKVN + coloff + head * HDc;
  float x1 = row[lane], x2 = row[lane + 32];
  float y1, y2;

  if (dorope){
    float ss = x1*x1 + x2*x2;
#pragma unroll
    for (int o = 16; o > 0; o >>= 1) ss += __shfl_xor_sync(0xffffffffu, ss, o);
    float r = rsqrtf(ss * (1.0f/64.0f) + 1e-5f);
    float x1n = x1 * r * w[lane];
    float x2n = x2 * r * w[lane + 32];
    float expnt = -((float)(2*lane)) * (1.0f/64.0f);
    float invf = powf(1000000.0f, expnt);
    float ang = (float)pos * invf;
    float cth = cosf(ang), sth = sinf(ang);
    y1 = x1n*cth - x2n*sth;
    y2 = x2n*cth + x1n*sth;
  } else {
    y1 = x1; y2 = x2;
  }

  size_t ob = ((size_t)(b*nh + head)*Lc + pos) * HDc;
  bf16 h, l;
  split1(y1, h, l); oh[ob + lane] = h;      ol[ob + lane] = l;
  split1(y2, h, l); oh[ob + lane + 32] = h; ol[ob + lane + 32] = l;
}

// ---------------- tensor-core flash attention (bf16 3-term, 64-row) ---------
#define FSM_Q   0
#define FSM_KV  16384
#define KV_STG  32768
#define FLASH_SMEM (16384 + 2*32768)

__global__ __launch_bounds__(128) void flash_tc(
    const bf16* __restrict__ Qh, const bf16* __restrict__ Ql,
    const bf16* __restrict__ Kh, const bf16* __restrict__ Kl,
    const bf16* __restrict__ Vh, const bf16* __restrict__ Vl,
    half_t* __restrict__ Oh, half_t* __restrict__ Ol)
{
  extern __shared__ char smraw[];
  const uint32_t smb = (uint32_t)__cvta_generic_to_shared(smraw);
  const int tid = threadIdx.x, lane = tid & 31, warp = tid >> 5;
  const int qt = gridDim.x - 1 - blockIdx.x;   // big tiles first
  const int h = blockIdx.y, b = blockIdx.z, hkv = h >> 2;
  const int g = lane >> 2, t = lane & 3;

  const bf16* qhp = Qh + ((size_t)(b*Hc + h)*Lc + qt*64) * HDc;
  const bf16* qlp = Ql + ((size_t)(b*Hc + h)*Lc + qt*64) * HDc;
  const size_t kvoff = (size_t)(b*HKVc + hkv) * Lc * HDc;
  const bf16* kvsrc[4] = { Kh + kvoff, Kl + kvoff, Vh + kvoff, Vl + kvoff };

#pragma unroll
  for (int it = 0; it < 4; it++){
    int fid = tid + it * 128;
    int row = fid >> 3, ch = fid & 7;
    uint4 vh4 = *(const uint4*)(qhp + row*64 + ch*8);
    uint4 vl4 = *(const uint4*)(qlp + row*64 + ch*8);
    int off = row*128 + ((ch ^ (row & 7)) * 16);
    *(uint4*)(smraw + FSM_Q + off)        = vh4;
    *(uint4*)(smraw + FSM_Q + 8192 + off) = vl4;
  }

  auto stageKV = [&](int j, int s){
#pragma unroll
    for (int q = 0; q < 4; q++)
#pragma unroll
      for (int it = 0; it < 4; it++){
        int fid = tid + it * 128;
        int row = fid >> 3, ch = fid & 7;
        cp16(smb + FSM_KV + s*KV_STG + q*8192 + row*128 + ((ch ^ (row & 7))*16),
             kvsrc[q] + (size_t)(j*64 + row)*64 + ch*8);
      }
  };

  stageKV(0, 0); CPCOMMIT();
  __syncthreads();

  uint32_t qfh[4][4], qfl[4][4];
  {
    int r = warp*16 + (lane & 7) + ((lane >> 3) & 1) * 8;
#pragma unroll
    for (int kc = 0; kc < 4; kc++){
      int ch = kc*2 + (lane >> 4);
      uint32_t ad = smb + FSM_Q + r*128 + ((ch ^ (r & 7)) * 16);
      LDSM4(qfh[kc][0], qfh[kc][1], qfh[kc][2], qfh[kc][3], ad);
      LDSM4(qfl[kc][0], qfl[kc][1], qfl[kc][2], qfl[kc][3], ad + 8192);
    }
  }

  float o[8][4];
#pragma unroll
  for (int nt=0;nt<8;nt++)
#pragma unroll
    for (int e=0;e<4;e++) o[nt][e] = 0.f;
  float m0r = -1e30f, m1r = -1e30f, l0 = 0.f, l1 = 0.f;

  const int r0g = qt*64 + warp*16 + g;
  const int r1g = r0g + 8;
  const int rBv = (lane & 7) + ((lane >> 4) << 3);
  const int chBv = (lane >> 3) & 1;
  const int rVv = (lane & 7) + (((lane >> 3) & 1) << 3);
  const int chVv = lane >> 4;

  for (int j = 0; j <= qt; j++){
    int s = j & 1;
    CPWAIT0();
    __syncthreads();
    if (j < qt){ stageKV(j + 1, s ^ 1); CPCOMMIT(); }

    const uint32_t kb = smb + FSM_KV + s*KV_STG;

    float sf[8][4];
#pragma unroll
    for (int nt=0;nt<8;nt++)
#pragma unroll
      for (int e=0;e<4;e++) sf[nt][e] = 0.f;

#pragma unroll
    for (int kc = 0; kc < 4; kc++){
#pragma unroll
      for (int ntp = 0; ntp < 4; ntp++){
        int r = ntp*16 + rBv;
        int ch = kc*2 + chBv;
        uint32_t ad = kb + r*128 + ((ch ^ (r & 7)) * 16);
        uint32_t bh0,bh1,bh2,bh3, bl0,bl1,bl2,bl3;
        LDSM4(bh0,bh1,bh2,bh3, ad);
        LDSM4(bl0,bl1,bl2,bl3, ad + 8192);
        MMA4(sf[2*ntp],   qfh[kc], bh0, bh1);
        MMA4(sf[2*ntp+1], qfh[kc], bh2, bh3);
        MMA4(sf[2*ntp],   qfh[kc], bl0, bl1);
        MMA4(sf[2*ntp+1], qfh[kc], bl2, bl3);
        MMA4(sf[2*ntp],   qfl[kc], bh0, bh1);
        MMA4(sf[2*ntp+1], qfl[kc], bh2, bh3);
      }
    }

    float tm0 = -1e30f, tm1 = -1e30f;
    const bool mayMask = (j == qt);
#pragma unroll
    for (int nt = 0; nt < 8; nt++){
      int c0 = j*64 + nt*8 + 2*t;
      float v0 = sf[nt][0]*0.125f, v1 = sf[nt][1]*0.125f;
      float v2 = sf[nt][2]*0.125f, v3 = sf[nt][3]*0.125f;
      if (mayMask){
        if (c0     > r0g) v0 = -1e30f;
        if (c0 + 1 > r0g) v1 = -1e30f;
        if (c0     > r1g) v2 = -1e30f;
        if (c0 + 1 > r1g) v3 = -1e30f;
      }
      sf[nt][0]=v0; sf[nt][1]=v1; sf[nt][2]=v2; sf[nt][3]=v3;
      tm0 = fmaxf(tm0, fmaxf(v0, v1));
      tm1 = fmaxf(tm1, fmaxf(v2, v3));
    }
    tm0 = fmaxf(tm0, __shfl_xor_sync(0xffffffffu, tm0, 1));
    tm0 = fmaxf(tm0, __shfl_xor_sync(0xffffffffu, tm0, 2));
    tm1 = fmaxf(tm1, __shfl_xor_sync(0xffffffffu, tm1, 1));
    tm1 = fmaxf(tm1, __shfl_xor_sync(0xffffffffu, tm1, 2));

    float mn0 = fmaxf(m0r, tm0), mn1 = fmaxf(m1r, tm1);
    float corr0 = __expf(m0r - mn0), corr1 = __expf(m1r - mn1);
    float s0 = 0.f, s1 = 0.f;
#pragma unroll
    for (int nt = 0; nt < 8; nt++){
      sf[nt][0] = __expf(sf[nt][0] - mn0);
      sf[nt][1] = __expf(sf[nt][1] - mn0);
      sf[nt][2] = __expf(sf[nt][2] - mn1);
      sf[nt][3] = __expf(sf[nt][3] - mn1);
      s0 += sf[nt][0] + sf[nt][1];
      s1 += sf[nt][2] + sf[nt][3];
    }
    s0 += __shfl_xor_sync(0xffffffffu, s0, 1);
    s0 += __shfl_xor_sync(0xffffffffu, s0, 2);
    s1 += __shfl_xor_sync(0xffffffffu, s1, 1);
    s1 += __shfl_xor_sync(0xffffffffu, s1, 2);
    l0 = l0*corr0 + s0;  l1 = l1*corr1 + s1;
    m0r = mn0;  m1r = mn1;
#pragma unroll
    for (int nt = 0; nt < 8; nt++){
      o[nt][0] *= corr0; o[nt][1] *= corr0;
      o[nt][2] *= corr1; o[nt][3] *= corr1;
    }

    const uint32_t vb = kb + 16384;
#pragma unroll
    for (int kc = 0; kc < 4; kc++){
      uint32_t ph[4], pl[4];
#pragma unroll
      for (int q2 = 0; q2 < 2; q2++){
        float c0 = sf[2*kc+q2][0], c1 = sf[2*kc+q2][1];
        float c2 = sf[2*kc+q2][2], c3 = sf[2*kc+q2][3];
        bf16 h0,h1,h2,h3, e0,e1,e2,e3;
        split1(c0,h0,e0); split1(c1,h1,e1); split1(c2,h2,e2); split1(c3,h3,e3);
        bf162 p01; p01.x=h0; p01.y=h1;  bf162 p23; p23.x=h2; p23.y=h3;
        bf162 q01; q01.x=e0; q01.y=e1;  bf162 q23; q23.x=e2; q23.y=e3;
        ph[2*q2 + 0] = *(uint32_t*)&p01;  ph[2*q2 + 1] = *(uint32_t*)&p23;
        pl[2*q2 + 0] = *(uint32_t*)&q01;  pl[2*q2 + 1] = *(uint32_t*)&q23;
      }
#pragma unroll
      for (int ntp = 0; ntp < 4; ntp++){
        int r = kc*16 + rVv;
        int ch = ntp*2 + chVv;
        uint32_t ad = vb + r*128 + ((ch ^ (r & 7)) * 16);
        uint32_t wh0,wh1,wh2,wh3, wl0,wl1,wl2,wl3;
        LDSM4T(wh0,wh1,wh2,wh3, ad);
        LDSM4T(wl0,wl1,wl2,wl3, ad + 8192);
        MMA4(o[2*ntp],   ph, wh0, wh1);
        MMA4(o[2*ntp+1], ph, wh2, wh3);
        MMA4(o[2*ntp],   ph, wl0, wl1);
        MMA4(o[2*ntp+1], ph, wl2, wl3);
        MMA4(o[2*ntp],   pl, wh0, wh1);
        MMA4(o[2*ntp+1], pl, wh2, wh3);
      }
    }
  }

  // epilogue: normalize, write split fp16 attn [b][l][h][d]
  float inv0 = 1.f / l0, inv1 = 1.f / l1;
  size_t ob0 = ((size_t)(b*Lc + qt*64 + warp*16 + g) * Hc + h) * HDc;
  size_t ob1 = ob0 + (size_t)8 * Hc * HDc;
#pragma unroll
  for (int nt = 0; nt < 8; nt++){
    int d = nt*8 + 2*t;
    float v0 = o[nt][0]*inv0, v1 = o[nt][1]*inv0;
    float v2 = o[nt][2]*inv1, v3 = o[nt][3]*inv1;
    half_t h0,h1,h2,h3, e0,e1,e2,e3;
    split1h(v0,h0,e0); split1h(v1,h1,e1); split1h(v2,h2,e2); split1h(v3,h3,e3);
    __half2 a = {h0, h1}, c = {e0, e1}, d2 = {h2, h3}, f = {e2, e3};
    *(__half2*)(Oh + ob0 + d) = a;  *(__half2*)(Ol + ob0 + d) = c;
    *(__half2*)(Oh + ob1 + d) = d2; *(__half2*)(Ol + ob1 + d) = f;
  }
}

// ---------------------------------------------------------------------------
extern "C" void kernel_launch(void* const* d_in, const int* in_sizes, int n_in,
                              void* d_out, int out_size)
{
  const float* x   = (const float*)d_in[0];
  const float* Wq  = (const float*)d_in[1];
  const float* Wk  = (const float*)d_in[2];
  const float* Wv  = (const float*)d_in[3];
  const float* Wo  = (const float*)d_in[4];
  const float* qnw = (const float*)d_in[5];
  const float* knw = (const float*)d_in[6];
  float* out = (float*)d_out;

  float *qkv;
  half_t *xh,*xl,*wqkv,*wo,*ath,*atl;
  bf16 *qh,*ql,*kh,*kl,*vh,*vl;
  cudaGetSymbolAddress((void**)&qkv, g_qkv);
  cudaGetSymbolAddress((void**)&xh, g_xh);   cudaGetSymbolAddress((void**)&xl, g_xl);
  cudaGetSymbolAddress((void**)&wqkv, g_wqkvT);
  cudaGetSymbolAddress((void**)&wo, g_woT);
  cudaGetSymbolAddress((void**)&qh, g_qh); cudaGetSymbolAddress((void**)&ql, g_ql);
  cudaGetSymbolAddress((void**)&kh, g_kh); cudaGetSymbolAddress((void**)&kl, g_kl);
  cudaGetSymbolAddress((void**)&vh, g_vh); cudaGetSymbolAddress((void**)&vl, g_vl);
  cudaGetSymbolAddress((void**)&ath, g_ath); cudaGetSymbolAddress((void**)&atl, g_atl);

  const int M = Mtok;

  // (1) activation split
  splitx<<<(M*Dc/4 + 255)/256, 256>>>(x, xh, xl, M*Dc/4);
  // (2) all weight transposes in one launch
  wsplit_all<<<dim3(64, 64, 4), dim3(32,8)>>>(Wq, Wk, Wv, Wo, wqkv, wo);

  // (3) fused QKV projection: C [M][3072]
  cudaFuncSetAttribute(gemm_fp16, cudaFuncAttributeMaxDynamicSharedMemorySize, 2*GSTG2);
  gemm_fp16<<<dim3(QKVN/128, M/128), 256, 2*GSTG2>>>(xh, xl, wqkv, qkv, M, QKVN, Dc);

  // (4) fused norm + rope + split (head-major)
  {
    int nw = M*Hc + 2*M*HKVc;
    qkvpost<<<(nw*32 + 255)/256, 256>>>(qkv, qnw, knw, qh, ql, kh, kl, vh, vl);
  }

  // (5) flash attention  (5th launch -> ncu capture target)
  cudaFuncSetAttribute(flash_tc, cudaFuncAttributeMaxDynamicSharedMemorySize, FLASH_SMEM);
  flash_tc<<<dim3(Lc/64, Hc, Bc), 128, FLASH_SMEM>>>(qh, ql, kh, kl, vh, vl, ath, atl);

  // (6) output projection
  gemm_fp16<<<dim3(Dc/128, M/128), 256, 2*GSTG2>>>(ath, atl, wo, out, M, Dc, Dc);
}

// round 7
// speedup vs baseline: 1.5011x; 1.1839x over previous
#include <cuda_runtime.h>
#include <cuda_bf16.h>
#include <cuda_fp16.h>
#include <math.h>
#include <stdint.h>
#include <stddef.h>

#define Bc 2
#define Lc 2048
#define Dc 2048
#define Hc 32
#define HKVc 8
#define HDc 64
#define Mtok (Bc*Lc)
#define QKVN 3072          // fused projection width: 2048 Q | 512 K | 512 V

typedef __half half_t;

// ---------------- scratch (__device__ globals; no allocs allowed) -----------
__device__ float g_qkv[(size_t)Mtok*QKVN];              // 50 MB fused QKV out

__device__ __align__(16) half_t g_xh[(size_t)Mtok*Dc];
__device__ __align__(16) half_t g_xl[(size_t)Mtok*Dc];
__device__ __align__(16) half_t g_wqkvT[(size_t)QKVN*Dc];   // single fp16
__device__ __align__(16) half_t g_woT[(size_t)Dc*Hc*HDc];   // single fp16
__device__ __align__(16) half_t g_qh[(size_t)Bc*Hc*Lc*HDc]; // Q hi (fp16)
__device__ __align__(16) half_t g_ql[(size_t)Bc*Hc*Lc*HDc]; // Q lo (fp16)
__device__ __align__(16) half_t g_k[(size_t)Bc*HKVc*Lc*HDc];// K single fp16
__device__ __align__(16) half_t g_v[(size_t)Bc*HKVc*Lc*HDc];// V single fp16
__device__ __align__(16) half_t g_ath[(size_t)Mtok*Hc*HDc];
__device__ __align__(16) half_t g_atl[(size_t)Mtok*Hc*HDc];

// ---------------- PTX helpers ----------------------------------------------
#define MMAH(CR, A, B0, B1)                                                  \
  asm volatile(                                                              \
      "mma.sync.aligned.m16n8k16.row.col.f32.f16.f16.f32 "                   \
      "{%0,%1,%2,%3},{%4,%5,%6,%7},{%8,%9},{%0,%1,%2,%3};"                   \
      : "+f"((CR)[0]), "+f"((CR)[1]), "+f"((CR)[2]), "+f"((CR)[3])           \
      : "r"((A)[0]), "r"((A)[1]), "r"((A)[2]), "r"((A)[3]), "r"(B0), "r"(B1))

#define LDSM4(R0,R1,R2,R3,ADDR)                                              \
  asm volatile("ldmatrix.sync.aligned.m8n8.x4.shared.b16 {%0,%1,%2,%3},[%4];"\
      : "=r"(R0),"=r"(R1),"=r"(R2),"=r"(R3) : "r"(ADDR))

#define LDSM4T(R0,R1,R2,R3,ADDR)                                             \
  asm volatile("ldmatrix.sync.aligned.m8n8.x4.trans.shared.b16 {%0,%1,%2,%3},[%4];"\
      : "=r"(R0),"=r"(R1),"=r"(R2),"=r"(R3) : "r"(ADDR))

__device__ __forceinline__ void cp16(uint32_t dst, const void* src){
  asm volatile("cp.async.cg.shared.global [%0], [%1], 16;" :: "r"(dst), "l"(src));
}
#define CPCOMMIT() asm volatile("cp.async.commit_group;")
#define CPWAIT0()  asm volatile("cp.async.wait_group 0;")

__device__ __forceinline__ void split1h(float v, half_t& h, half_t& l){
  h = __float2half_rn(v);
  l = __float2half_rn(v - __half2float(h));
}

// ---------------- convert passes --------------------------------------------
__global__ void splitx(const float* __restrict__ src, half_t* __restrict__ h,
                       half_t* __restrict__ l, int n4)
{
  int i = blockIdx.x * blockDim.x + threadIdx.x;
  if (i >= n4) return;
  float4 v = ((const float4*)src)[i];
  half_t hh[4], ll[4];
  split1h(v.x, hh[0], ll[0]); split1h(v.y, hh[1], ll[1]);
  split1h(v.z, hh[2], ll[2]); split1h(v.w, hh[3], ll[3]);
  __half2 h0 = {hh[0], hh[1]}, h1 = {hh[2], hh[3]};
  __half2 l0 = {ll[0], ll[1]}, l1 = {ll[2], ll[3]};
  ((__half2*)h)[2*i] = h0; ((__half2*)h)[2*i+1] = h1;
  ((__half2*)l)[2*i] = l0; ((__half2*)l)[2*i+1] = l1;
}

// One launch for all four weight transposes -> single fp16 [N][K]
__global__ void wsplit_all(const float* __restrict__ Wq,
                           const float* __restrict__ Wk,
                           const float* __restrict__ Wv,
                           const float* __restrict__ Wo,
                           half_t* __restrict__ wqkv, half_t* __restrict__ wo)
{
  const int z = blockIdx.z;
  const float* W; half_t* T; int K, N;
  if (z == 0){ W = Wq; T = wqkv;                       K = Dc;     N = Hc*HDc; }
  else if (z == 1){ W = Wk; T = wqkv + (size_t)2048*Dc; K = Dc;    N = HKVc*HDc; }
  else if (z == 2){ W = Wv; T = wqkv + (size_t)2560*Dc; K = Dc;    N = HKVc*HDc; }
  else            { W = Wo; T = wo;                     K = Hc*HDc; N = Dc; }
  if (blockIdx.x * 32 >= N) return;

  __shared__ float tile[32][33];
  int k0 = blockIdx.y*32, n0 = blockIdx.x*32;
  int tx = threadIdx.x, ty = threadIdx.y;
#pragma unroll
  for (int i = 0; i < 4; i++)
    tile[ty + 8*i][tx] = W[(size_t)(k0 + ty + 8*i) * N + n0 + tx];
  __syncthreads();
#pragma unroll
  for (int i = 0; i < 4; i++){
    int n = n0 + ty + 8*i;
    T[(size_t)n*K + k0 + tx] = __float2half_rn(tile[tx][ty + 8*i]);
  }
}

// ---------------- fp16 2-term tensor-core GEMM ------------------------------
// C[M][N] fp32 = (Ah+Al)[M][K] @ B^T, B single fp16 stored [N][K]. BK=64.
#define GSTG2 49152
__global__ __launch_bounds__(256) void gemm_fp16(
    const half_t* __restrict__ Ah, const half_t* __restrict__ Al,
    const half_t* __restrict__ B, float* __restrict__ C, int M, int N, int K)
{
  extern __shared__ char smraw[];
  const uint32_t smb = (uint32_t)__cvta_generic_to_shared(smraw);
  const int tid = threadIdx.x, lane = tid & 31, warp = tid >> 5;
  const int wm = (warp & 3) * 32, wn = (warp >> 2) * 64;
  const int g = lane >> 2, t = lane & 3;
  const int row0 = blockIdx.y * 128, col0 = blockIdx.x * 128;
  const int KI = K >> 6;

  const half_t* gsrc[3] = { Ah + (size_t)row0 * K, Al + (size_t)row0 * K,
                            B + (size_t)col0 * K };

  auto stage = [&](int ki, int s){
#pragma unroll
    for (int q = 0; q < 3; q++)
#pragma unroll
      for (int it = 0; it < 4; it++){
        int fid = tid + it * 256;
        int row = fid >> 3, ch = fid & 7;
        cp16(smb + s*GSTG2 + q*16384 + row*128 + ((ch ^ (row & 7)) * 16),
             gsrc[q] + (size_t)row * K + ki*64 + ch*8);
      }
  };

  float c[2][8][4];
#pragma unroll
  for (int i=0;i<2;i++)
#pragma unroll
    for (int j=0;j<8;j++)
#pragma unroll
      for (int e=0;e<4;e++) c[i][j][e] = 0.f;

  stage(0, 0); CPCOMMIT();

  for (int ki = 0; ki < KI; ki++){
    int s = ki & 1;
    CPWAIT0();
    __syncthreads();
    if (ki + 1 < KI){ stage(ki + 1, s ^ 1); CPCOMMIT(); }

    const uint32_t ab = smb + s*GSTG2, bb = ab + 32768;
    const int rA  = (lane & 7) + ((lane >> 3) & 1) * 8;
    const int chA = (lane >> 4);
    const int rB  = (lane & 7) + ((lane >> 4) << 3);
    const int chB = (lane >> 3) & 1;
#pragma unroll
    for (int kc = 0; kc < 4; kc++){
      uint32_t ah[2][4], al[2][4];
#pragma unroll
      for (int mt = 0; mt < 2; mt++){
        int r = wm + mt*16 + rA;
        int ch = kc*2 + chA;
        uint32_t ad = ab + r*128 + ((ch ^ (r & 7)) * 16);
        LDSM4(ah[mt][0], ah[mt][1], ah[mt][2], ah[mt][3], ad);
        LDSM4(al[mt][0], al[mt][1], al[mt][2], al[mt][3], ad + 16384);
      }
#pragma unroll
      for (int ntp = 0; ntp < 4; ntp++){
        int r = wn + ntp*16 + rB;
        int ch = kc*2 + chB;
        uint32_t ad = bb + r*128 + ((ch ^ (r & 7)) * 16);
        uint32_t b0,b1,b2,b3;
        LDSM4(b0,b1,b2,b3, ad);
#pragma unroll
        for (int mt = 0; mt < 2; mt++){
          MMAH(c[mt][2*ntp],   ah[mt], b0, b1);
          MMAH(c[mt][2*ntp+1], ah[mt], b2, b3);
          MMAH(c[mt][2*ntp],   al[mt], b0, b1);
          MMAH(c[mt][2*ntp+1], al[mt], b2, b3);
        }
      }
    }
    __syncthreads();
  }

#pragma unroll
  for (int mt = 0; mt < 2; mt++)
#pragma unroll
    for (int nt = 0; nt < 8; nt++){
      int r = row0 + wm + mt*16 + g;
      int cc = col0 + wn + nt*8 + 2*t;
      float2 v0 = { c[mt][nt][0], c[mt][nt][1] };
      float2 v1 = { c[mt][nt][2], c[mt][nt][3] };
      *(float2*)(C + (size_t)r * N + cc) = v0;
      *(float2*)(C + (size_t)(r + 8) * N + cc) = v1;
    }
}

// ---------------- fused post-QKV: RMSNorm+RoPE (Q,K) + V --------------------
// Q -> fp16 hi/lo head-major; K,V -> single fp16 head-major.
__global__ __launch_bounds__(256) void qkvpost(
    const float* __restrict__ qkv, const float* __restrict__ qnw,
    const float* __restrict__ knw,
    half_t* __restrict__ qh, half_t* __restrict__ ql,
    half_t* __restrict__ kk, half_t* __restrict__ vv)
{
  int wid = (blockIdx.x * blockDim.x + threadIdx.x) >> 5;
  int lane = threadIdx.x & 31;
  const int nQ = Mtok * Hc, nK = Mtok * HKVc;
  if (wid >= nQ + 2*nK) return;

  int nh, coloff, head, bl;
  const float* w = (const float*)0;
  int mode;                       // 0=Q, 1=K, 2=V
  if (wid < nQ){
    nh = Hc; head = wid % nh; bl = wid / nh; coloff = 0; w = qnw; mode = 0;
  } else if (wid < nQ + nK){
    int wv2 = wid - nQ;
    nh = HKVc; head = wv2 % nh; bl = wv2 / nh; coloff = 2048; w = knw; mode = 1;
  } else {
    int wv2 = wid - nQ - nK;
    nh = HKVc; head = wv2 % nh; bl = wv2 / nh; coloff = 2560; mode = 2;
  }
  int pos = bl % Lc;
  int b = bl / Lc;

  const float* row = qkv + (size_t)bl * QKVN + coloff + head * HDc;
  float x1 = row[lane], x2 = row[lane + 32];
  float y1, y2;

  if (mode != 2){
    float ss = x1*x1 + x2*x2;
#pragma unroll
    for (int o = 16; o > 0; o >>= 1) ss += __shfl_xor_sync(0xffffffffu, ss, o);
    float r = rsqrtf(ss * (1.0f/64.0f) + 1e-5f);
    float x1n = x1 * r * w[lane];
    float x2n = x2 * r * w[lane + 32];
    float expnt = -((float)(2*lane)) * (1.0f/64.0f);
    float invf = powf(1000000.0f, expnt);
    float ang = (float)pos * invf;
    float cth = cosf(ang), sth = sinf(ang);
    y1 = x1n*cth - x2n*sth;
    y2 = x2n*cth + x1n*sth;
  } else {
    y1 = x1; y2 = x2;
  }

  size_t ob = ((size_t)(b*nh + head)*Lc + pos) * HDc;
  if (mode == 0){
    half_t h, l;
    split1h(y1, h, l); qh[ob + lane] = h;      ql[ob + lane] = l;
    split1h(y2, h, l); qh[ob + lane + 32] = h; ql[ob + lane + 32] = l;
  } else {
    half_t* dst = (mode == 1) ? kk : vv;
    dst[ob + lane]      = __float2half_rn(y1);
    dst[ob + lane + 32] = __float2half_rn(y2);
  }
}

// ---------------- tensor-core flash attention (fp16, 64-row q tiles) --------
// smem: Qh 8K | Ql 8K | 2 stages x (K 8K | V 8K) = 48K total.
#define FSM_KV  16384
#define KV_STG  16384
#define FLASH_SMEM (16384 + 2*KV_STG)

__global__ __launch_bounds__(128) void flash_tc(
    const half_t* __restrict__ Qh, const half_t* __restrict__ Ql,
    const half_t* __restrict__ Kp, const half_t* __restrict__ Vp,
    half_t* __restrict__ Oh, half_t* __restrict__ Ol)
{
  extern __shared__ char smraw[];
  const uint32_t smb = (uint32_t)__cvta_generic_to_shared(smraw);
  const int tid = threadIdx.x, lane = tid & 31, warp = tid >> 5;
  const int qt = gridDim.x - 1 - blockIdx.x;   // big tiles first
  const int h = blockIdx.y, b = blockIdx.z, hkv = h >> 2;
  const int g = lane >> 2, t = lane & 3;

  const half_t* qhp = Qh + ((size_t)(b*Hc + h)*Lc + qt*64) * HDc;
  const half_t* qlp = Ql + ((size_t)(b*Hc + h)*Lc + qt*64) * HDc;
  const size_t kvoff = (size_t)(b*HKVc + hkv) * Lc * HDc;
  const half_t* kvsrc[2] = { Kp + kvoff, Vp + kvoff };

  // stage Q (once): 64 rows x 64 cols fp16, hi+lo
#pragma unroll
  for (int it = 0; it < 4; it++){
    int fid = tid + it * 128;
    int row = fid >> 3, ch = fid & 7;
    uint4 vh4 = *(const uint4*)(qhp + row*64 + ch*8);
    uint4 vl4 = *(const uint4*)(qlp + row*64 + ch*8);
    int off = row*128 + ((ch ^ (row & 7)) * 16);
    *(uint4*)(smraw + off)        = vh4;
    *(uint4*)(smraw + 8192 + off) = vl4;
  }

  auto stageKV = [&](int j, int s){
#pragma unroll
    for (int q = 0; q < 2; q++)
#pragma unroll
      for (int it = 0; it < 4; it++){
        int fid = tid + it * 128;
        int row = fid >> 3, ch = fid & 7;
        cp16(smb + FSM_KV + s*KV_STG + q*8192 + row*128 + ((ch ^ (row & 7))*16),
             kvsrc[q] + (size_t)(j*64 + row)*64 + ch*8);
      }
  };

  stageKV(0, 0); CPCOMMIT();
  __syncthreads();

  // Q fragments (persistent)
  uint32_t qfh[4][4], qfl[4][4];
  {
    int r = warp*16 + (lane & 7) + ((lane >> 3) & 1) * 8;
#pragma unroll
    for (int kc = 0; kc < 4; kc++){
      int ch = kc*2 + (lane >> 4);
      uint32_t ad = smb + r*128 + ((ch ^ (r & 7)) * 16);
      LDSM4(qfh[kc][0], qfh[kc][1], qfh[kc][2], qfh[kc][3], ad);
      LDSM4(qfl[kc][0], qfl[kc][1], qfl[kc][2], qfl[kc][3], ad + 8192);
    }
  }

  float o[8][4];
#pragma unroll
  for (int nt=0;nt<8;nt++)
#pragma unroll
    for (int e=0;e<4;e++) o[nt][e] = 0.f;
  float m0r = -1e30f, m1r = -1e30f, l0 = 0.f, l1 = 0.f;

  const int r0g = qt*64 + warp*16 + g;
  const int r1g = r0g + 8;
  const int rBv = (lane & 7) + ((lane >> 4) << 3);
  const int chBv = (lane >> 3) & 1;
  const int rVv = (lane & 7) + (((lane >> 3) & 1) << 3);
  const int chVv = lane >> 4;

  for (int j = 0; j <= qt; j++){
    int s = j & 1;
    CPWAIT0();
    __syncthreads();
    if (j < qt){ stageKV(j + 1, s ^ 1); CPCOMMIT(); }

    const uint32_t kb = smb + FSM_KV + s*KV_STG;

    float sf[8][4];
#pragma unroll
    for (int nt=0;nt<8;nt++)
#pragma unroll
      for (int e=0;e<4;e++) sf[nt][e] = 0.f;

    // S = Q K^T : Q hi/lo fp16 (2 terms), K single fp16
#pragma unroll
    for (int kc = 0; kc < 4; kc++){
#pragma unroll
      for (int ntp = 0; ntp < 4; ntp++){
        int r = ntp*16 + rBv;
        int ch = kc*2 + chBv;
        uint32_t ad = kb + r*128 + ((ch ^ (r & 7)) * 16);
        uint32_t b0,b1,b2,b3;
        LDSM4(b0,b1,b2,b3, ad);
        MMAH(sf[2*ntp],   qfh[kc], b0, b1);
        MMAH(sf[2*ntp+1], qfh[kc], b2, b3);
        MMAH(sf[2*ntp],   qfl[kc], b0, b1);
        MMAH(sf[2*ntp+1], qfl[kc], b2, b3);
      }
    }

    float tm0 = -1e30f, tm1 = -1e30f;
    const bool mayMask = (j == qt);
#pragma unroll
    for (int nt = 0; nt < 8; nt++){
      int c0 = j*64 + nt*8 + 2*t;
      float v0 = sf[nt][0]*0.125f, v1 = sf[nt][1]*0.125f;
      float v2 = sf[nt][2]*0.125f, v3 = sf[nt][3]*0.125f;
      if (mayMask){
        if (c0     > r0g) v0 = -1e30f;
        if (c0 + 1 > r0g) v1 = -1e30f;
        if (c0     > r1g) v2 = -1e30f;
        if (c0 + 1 > r1g) v3 = -1e30f;
      }
      sf[nt][0]=v0; sf[nt][1]=v1; sf[nt][2]=v2; sf[nt][3]=v3;
      tm0 = fmaxf(tm0, fmaxf(v0, v1));
      tm1 = fmaxf(tm1, fmaxf(v2, v3));
    }
    tm0 = fmaxf(tm0, __shfl_xor_sync(0xffffffffu, tm0, 1));
    tm0 = fmaxf(tm0, __shfl_xor_sync(0xffffffffu, tm0, 2));
    tm1 = fmaxf(tm1, __shfl_xor_sync(0xffffffffu, tm1, 1));
    tm1 = fmaxf(tm1, __shfl_xor_sync(0xffffffffu, tm1, 2));

    float mn0 = fmaxf(m0r, tm0), mn1 = fmaxf(m1r, tm1);
    float corr0 = __expf(m0r - mn0), corr1 = __expf(m1r - mn1);
    float s0 = 0.f, s1 = 0.f;
#pragma unroll
    for (int nt = 0; nt < 8; nt++){
      sf[nt][0] = __expf(sf[nt][0] - mn0);
      sf[nt][1] = __expf(sf[nt][1] - mn0);
      sf[nt][2] = __expf(sf[nt][2] - mn1);
      sf[nt][3] = __expf(sf[nt][3] - mn1);
      s0 += sf[nt][0] + sf[nt][1];
      s1 += sf[nt][2] + sf[nt][3];
    }
    s0 += __shfl_xor_sync(0xffffffffu, s0, 1);
    s0 += __shfl_xor_sync(0xffffffffu, s0, 2);
    s1 += __shfl_xor_sync(0xffffffffu, s1, 1);
    s1 += __shfl_xor_sync(0xffffffffu, s1, 2);
    l0 = l0*corr0 + s0;  l1 = l1*corr1 + s1;
    m0r = mn0;  m1r = mn1;
#pragma unroll
    for (int nt = 0; nt < 8; nt++){
      o[nt][0] *= corr0; o[nt][1] *= corr0;
      o[nt][2] *= corr1; o[nt][3] *= corr1;
    }

    // O += P V : P single fp16, V single fp16 (1 term)
    const uint32_t vb = kb + 8192;
#pragma unroll
    for (int kc = 0; kc < 4; kc++){
      uint32_t ph[4];
#pragma unroll
      for (int q2 = 0; q2 < 2; q2++){
        __half2 p01 = { __float2half_rn(sf[2*kc+q2][0]), __float2half_rn(sf[2*kc+q2][1]) };
        __half2 p23 = { __float2half_rn(sf[2*kc+q2][2]), __float2half_rn(sf[2*kc+q2][3]) };
        ph[2*q2 + 0] = *(uint32_t*)&p01;
        ph[2*q2 + 1] = *(uint32_t*)&p23;
      }
#pragma unroll
      for (int ntp = 0; ntp < 4; ntp++){
        int r = kc*16 + rVv;
        int ch = ntp*2 + chVv;
        uint32_t ad = vb + r*128 + ((ch ^ (r & 7)) * 16);
        uint32_t w0,w1,w2,w3;
        LDSM4T(w0,w1,w2,w3, ad);
        MMAH(o[2*ntp],   ph, w0, w1);
        MMAH(o[2*ntp+1], ph, w2, w3);
      }
    }
  }

  // epilogue: normalize, write split fp16 attn [b][l][h][d]
  float inv0 = 1.f / l0, inv1 = 1.f / l1;
  size_t ob0 = ((size_t)(b*Lc + qt*64 + warp*16 + g) * Hc + h) * HDc;
  size_t ob1 = ob0 + (size_t)8 * Hc * HDc;
#pragma unroll
  for (int nt = 0; nt < 8; nt++){
    int d = nt*8 + 2*t;
    float v0 = o[nt][0]*inv0, v1 = o[nt][1]*inv0;
    float v2 = o[nt][2]*inv1, v3 = o[nt][3]*inv1;
    half_t h0,h1,h2,h3, e0,e1,e2,e3;
    split1h(v0,h0,e0); split1h(v1,h1,e1); split1h(v2,h2,e2); split1h(v3,h3,e3);
    __half2 a = {h0, h1}, c = {e0, e1}, d2 = {h2, h3}, f = {e2, e3};
    *(__half2*)(Oh + ob0 + d) = a;  *(__half2*)(Ol + ob0 + d) = c;
    *(__half2*)(Oh + ob1 + d) = d2; *(__half2*)(Ol + ob1 + d) = f;
  }
}

// ---------------------------------------------------------------------------
extern "C" void kernel_launch(void* const* d_in, const int* in_sizes, int n_in,
                              void* d_out, int out_size)
{
  const float* x   = (const float*)d_in[0];
  const float* Wq  = (const float*)d_in[1];
  const float* Wk  = (const float*)d_in[2];
  const float* Wv  = (const float*)d_in[3];
  const float* Wo  = (const float*)d_in[4];
  const float* qnw = (const float*)d_in[5];
  const float* knw = (const float*)d_in[6];
  float* out = (float*)d_out;

  float *qkv;
  half_t *xh,*xl,*wqkv,*wo,*ath,*atl,*qh,*ql,*kk,*vv;
  cudaGetSymbolAddress((void**)&qkv, g_qkv);
  cudaGetSymbolAddress((void**)&xh, g_xh);   cudaGetSymbolAddress((void**)&xl, g_xl);
  cudaGetSymbolAddress((void**)&wqkv, g_wqkvT);
  cudaGetSymbolAddress((void**)&wo, g_woT);
  cudaGetSymbolAddress((void**)&qh, g_qh); cudaGetSymbolAddress((void**)&ql, g_ql);
  cudaGetSymbolAddress((void**)&kk, g_k);  cudaGetSymbolAddress((void**)&vv, g_v);
  cudaGetSymbolAddress((void**)&ath, g_ath); cudaGetSymbolAddress((void**)&atl, g_atl);

  const int M = Mtok;

  // (1) activation split
  splitx<<<(M*Dc/4 + 255)/256, 256>>>(x, xh, xl, M*Dc/4);
  // (2) all weight transposes in one launch
  wsplit_all<<<dim3(64, 64, 4), dim3(32,8)>>>(Wq, Wk, Wv, Wo, wqkv, wo);

  // (3) fused QKV projection: C [M][3072]
  cudaFuncSetAttribute(gemm_fp16, cudaFuncAttributeMaxDynamicSharedMemorySize, 2*GSTG2);
  gemm_fp16<<<dim3(QKVN/128, M/128), 256, 2*GSTG2>>>(xh, xl, wqkv, qkv, M, QKVN, Dc);

  // (4) fused norm + rope + convert (head-major)
  {
    int nw = M*Hc + 2*M*HKVc;
    qkvpost<<<(nw*32 + 255)/256, 256>>>(qkv, qnw, knw, qh, ql, kk, vv);
  }

  // (5) flash attention (ncu capture target)
  cudaFuncSetAttribute(flash_tc, cudaFuncAttributeMaxDynamicSharedMemorySize, FLASH_SMEM);
  flash_tc<<<dim3(Lc/64, Hc, Bc), 128, FLASH_SMEM>>>(qh, ql, kk, vv, ath, atl);

  // (6) output projection
  gemm_fp16<<<dim3(Dc/128, M/128), 256, 2*GSTG2>>>(ath, atl, wo, out, M, Dc, Dc);
}

// round 8
// speedup vs baseline: 2.2855x; 1.5226x over previous
#include <cuda_runtime.h>
#include <cuda_fp16.h>
#include <math.h>
#include <stdint.h>
#include <stddef.h>

#define Bc 2
#define Lc 2048
#define Dc 2048
#define Hc 32
#define HKVc 8
#define HDc 64
#define Mtok (Bc*Lc)
#define QKVN 3072          // fused projection width: 2048 Q | 512 K | 512 V

typedef __half half_t;

// ---------------- scratch (__device__ globals; no allocs allowed) -----------
__device__ float g_qkv[(size_t)Mtok*QKVN];              // 50 MB fused QKV out

__device__ __align__(16) half_t g_x16[(size_t)Mtok*Dc];     // x single fp16
__device__ __align__(16) half_t g_wqkvT[(size_t)QKVN*Dc];   // single fp16
__device__ __align__(16) half_t g_woT[(size_t)Dc*Hc*HDc];   // single fp16
__device__ __align__(16) half_t g_qh[(size_t)Bc*Hc*Lc*HDc]; // Q hi (fp16)
__device__ __align__(16) half_t g_ql[(size_t)Bc*Hc*Lc*HDc]; // Q lo (fp16)
__device__ __align__(16) half_t g_k[(size_t)Bc*HKVc*Lc*HDc];// K single fp16
__device__ __align__(16) half_t g_v[(size_t)Bc*HKVc*Lc*HDc];// V single fp16
__device__ __align__(16) half_t g_at[(size_t)Mtok*Hc*HDc];  // attn single fp16

// ---------------- PTX helpers ----------------------------------------------
#define MMAH(CR, A, B0, B1)                                                  \
  asm volatile(                                                              \
      "mma.sync.aligned.m16n8k16.row.col.f32.f16.f16.f32 "                   \
      "{%0,%1,%2,%3},{%4,%5,%6,%7},{%8,%9},{%0,%1,%2,%3};"                   \
      : "+f"((CR)[0]), "+f"((CR)[1]), "+f"((CR)[2]), "+f"((CR)[3])           \
      : "r"((A)[0]), "r"((A)[1]), "r"((A)[2]), "r"((A)[3]), "r"(B0), "r"(B1))

#define LDSM4(R0,R1,R2,R3,ADDR)                                              \
  asm volatile("ldmatrix.sync.aligned.m8n8.x4.shared.b16 {%0,%1,%2,%3},[%4];"\
      : "=r"(R0),"=r"(R1),"=r"(R2),"=r"(R3) : "r"(ADDR))

#define LDSM4T(R0,R1,R2,R3,ADDR)                                             \
  asm volatile("ldmatrix.sync.aligned.m8n8.x4.trans.shared.b16 {%0,%1,%2,%3},[%4];"\
      : "=r"(R0),"=r"(R1),"=r"(R2),"=r"(R3) : "r"(ADDR))

__device__ __forceinline__ void cp16(uint32_t dst, const void* src){
  asm volatile("cp.async.cg.shared.global [%0], [%1], 16;" :: "r"(dst), "l"(src));
}
#define CPCOMMIT() asm volatile("cp.async.commit_group;")
#define CPWAIT0()  asm volatile("cp.async.wait_group 0;")

__device__ __forceinline__ void split1h(float v, half_t& h, half_t& l){
  h = __float2half_rn(v);
  l = __float2half_rn(v - __half2float(h));
}

// ---------------- convert passes --------------------------------------------
__global__ void xcvt(const float* __restrict__ src, half_t* __restrict__ d, int n4)
{
  int i = blockIdx.x * blockDim.x + threadIdx.x;
  if (i >= n4) return;
  float4 v = ((const float4*)src)[i];
  __half2 h0 = { __float2half_rn(v.x), __float2half_rn(v.y) };
  __half2 h1 = { __float2half_rn(v.z), __float2half_rn(v.w) };
  ((__half2*)d)[2*i] = h0; ((__half2*)d)[2*i+1] = h1;
}

// One launch for all four weight transposes -> single fp16 [N][K]
__global__ void wsplit_all(const float* __restrict__ Wq,
                           const float* __restrict__ Wk,
                           const float* __restrict__ Wv,
                           const float* __restrict__ Wo,
                           half_t* __restrict__ wqkv, half_t* __restrict__ wo)
{
  const int z = blockIdx.z;
  const float* W; half_t* T; int K, N;
  if (z == 0){ W = Wq; T = wqkv;                       K = Dc;     N = Hc*HDc; }
  else if (z == 1){ W = Wk; T = wqkv + (size_t)2048*Dc; K = Dc;    N = HKVc*HDc; }
  else if (z == 2){ W = Wv; T = wqkv + (size_t)2560*Dc; K = Dc;    N = HKVc*HDc; }
  else            { W = Wo; T = wo;                     K = Hc*HDc; N = Dc; }
  if (blockIdx.x * 32 >= N) return;

  __shared__ float tile[32][33];
  int k0 = blockIdx.y*32, n0 = blockIdx.x*32;
  int tx = threadIdx.x, ty = threadIdx.y;
#pragma unroll
  for (int i = 0; i < 4; i++)
    tile[ty + 8*i][tx] = W[(size_t)(k0 + ty + 8*i) * N + n0 + tx];
  __syncthreads();
#pragma unroll
  for (int i = 0; i < 4; i++){
    int n = n0 + ty + 8*i;
    T[(size_t)n*K + k0 + tx] = __float2half_rn(tile[tx][ty + 8*i]);
  }
}

// ---------------- single fp16 tensor-core GEMM ------------------------------
// C[M][N] fp32 = A[M][K] @ B^T, A and B single fp16, B stored [N][K]. BK=64.
// smem/stage: A 16K | B 16K. 256 thr, 8 warps, warp tile 32x64.
#define GSTG1 32768
__global__ __launch_bounds__(256) void gemm_fp16(
    const half_t* __restrict__ A, const half_t* __restrict__ B,
    float* __restrict__ C, int M, int N, int K)
{
  extern __shared__ char smraw[];
  const uint32_t smb = (uint32_t)__cvta_generic_to_shared(smraw);
  const int tid = threadIdx.x, lane = tid & 31, warp = tid >> 5;
  const int wm = (warp & 3) * 32, wn = (warp >> 2) * 64;
  const int g = lane >> 2, t = lane & 3;
  const int row0 = blockIdx.y * 128, col0 = blockIdx.x * 128;
  const int KI = K >> 6;

  const half_t* gsrc[2] = { A + (size_t)row0 * K, B + (size_t)col0 * K };

  auto stage = [&](int ki, int s){
#pragma unroll
    for (int q = 0; q < 2; q++)
#pragma unroll
      for (int it = 0; it < 4; it++){
        int fid = tid + it * 256;
        int row = fid >> 3, ch = fid & 7;
        cp16(smb + s*GSTG1 + q*16384 + row*128 + ((ch ^ (row & 7)) * 16),
             gsrc[q] + (size_t)row * K + ki*64 + ch*8);
      }
  };

  float c[2][8][4];
#pragma unroll
  for (int i=0;i<2;i++)
#pragma unroll
    for (int j=0;j<8;j++)
#pragma unroll
      for (int e=0;e<4;e++) c[i][j][e] = 0.f;

  stage(0, 0); CPCOMMIT();

  for (int ki = 0; ki < KI; ki++){
    int s = ki & 1;
    CPWAIT0();
    __syncthreads();
    if (ki + 1 < KI){ stage(ki + 1, s ^ 1); CPCOMMIT(); }

    const uint32_t ab = smb + s*GSTG1, bb = ab + 16384;
    const int rA  = (lane & 7) + ((lane >> 3) & 1) * 8;
    const int chA = (lane >> 4);
    const int rB  = (lane & 7) + ((lane >> 4) << 3);
    const int chB = (lane >> 3) & 1;
#pragma unroll
    for (int kc = 0; kc < 4; kc++){
      uint32_t ah[2][4];
#pragma unroll
      for (int mt = 0; mt < 2; mt++){
        int r = wm + mt*16 + rA;
        int ch = kc*2 + chA;
        uint32_t ad = ab + r*128 + ((ch ^ (r & 7)) * 16);
        LDSM4(ah[mt][0], ah[mt][1], ah[mt][2], ah[mt][3], ad);
      }
#pragma unroll
      for (int ntp = 0; ntp < 4; ntp++){
        int r = wn + ntp*16 + rB;
        int ch = kc*2 + chB;
        uint32_t ad = bb + r*128 + ((ch ^ (r & 7)) * 16);
        uint32_t b0,b1,b2,b3;
        LDSM4(b0,b1,b2,b3, ad);
#pragma unroll
        for (int mt = 0; mt < 2; mt++){
          MMAH(c[mt][2*ntp],   ah[mt], b0, b1);
          MMAH(c[mt][2*ntp+1], ah[mt], b2, b3);
        }
      }
    }
    __syncthreads();
  }

#pragma unroll
  for (int mt = 0; mt < 2; mt++)
#pragma unroll
    for (int nt = 0; nt < 8; nt++){
      int r = row0 + wm + mt*16 + g;
      int cc = col0 + wn + nt*8 + 2*t;
      float2 v0 = { c[mt][nt][0], c[mt][nt][1] };
      float2 v1 = { c[mt][nt][2], c[mt][nt][3] };
      *(float2*)(C + (size_t)r * N + cc) = v0;
      *(float2*)(C + (size_t)(r + 8) * N + cc) = v1;
    }
}

// ---------------- fused post-QKV: RMSNorm+RoPE (Q,K) + V --------------------
// Q -> fp16 hi/lo head-major; K,V -> single fp16 head-major.
__global__ __launch_bounds__(256) void qkvpost(
    const float* __restrict__ qkv, const float* __restrict__ qnw,
    const float* __restrict__ knw,
    half_t* __restrict__ qh, half_t* __restrict__ ql,
    half_t* __restrict__ kk, half_t* __restrict__ vv)
{
  int wid = (blockIdx.x * blockDim.x + threadIdx.x) >> 5;
  int lane = threadIdx.x & 31;
  const int nQ = Mtok * Hc, nK = Mtok * HKVc;
  if (wid >= nQ + 2*nK) return;

  int nh, coloff, head, bl;
  const float* w = (const float*)0;
  int mode;                       // 0=Q, 1=K, 2=V
  if (wid < nQ){
    nh = Hc; head = wid % nh; bl = wid / nh; coloff = 0; w = qnw; mode = 0;
  } else if (wid < nQ + nK){
    int wv2 = wid - nQ;
    nh = HKVc; head = wv2 % nh; bl = wv2 / nh; coloff = 2048; w = knw; mode = 1;
  } else {
    int wv2 = wid - nQ - nK;
    nh = HKVc; head = wv2 % nh; bl = wv2 / nh; coloff = 2560; mode = 2;
  }
  int pos = bl % Lc;
  int b = bl / Lc;

  const float* row = qkv + (size_t)bl * QKVN + coloff + head * HDc;
  float x1 = row[lane], x2 = row[lane + 32];
  float y1, y2;

  if (mode != 2){
    float ss = x1*x1 + x2*x2;
#pragma unroll
    for (int o = 16; o > 0; o >>= 1) ss += __shfl_xor_sync(0xffffffffu, ss, o);
    float r = rsqrtf(ss * (1.0f/64.0f) + 1e-5f);
    float x1n = x1 * r * w[lane];
    float x2n = x2 * r * w[lane + 32];
    float expnt = -((float)(2*lane)) * (1.0f/64.0f);
    float invf = powf(1000000.0f, expnt);
    float ang = (float)pos * invf;
    float cth = cosf(ang), sth = sinf(ang);
    y1 = x1n*cth - x2n*sth;
    y2 = x2n*cth + x1n*sth;
  } else {
    y1 = x1; y2 = x2;
  }

  size_t ob = ((size_t)(b*nh + head)*Lc + pos) * HDc;
  if (mode == 0){
    half_t h, l;
    split1h(y1, h, l); qh[ob + lane] = h;      ql[ob + lane] = l;
    split1h(y2, h, l); qh[ob + lane + 32] = h; ql[ob + lane + 32] = l;
  } else {
    half_t* dst = (mode == 1) ? kk : vv;
    dst[ob + lane]      = __float2half_rn(y1);
    dst[ob + lane + 32] = __float2half_rn(y2);
  }
}

// ---------------- tensor-core flash attention (fp16, 64-row q tiles) --------
// smem: Qh 8K | Ql 8K | 2 stages x (K 8K | V 8K) = 48K total.
#define FSM_KV  16384
#define KV_STG  16384
#define FLASH_SMEM (16384 + 2*KV_STG)

__global__ __launch_bounds__(128) void flash_tc(
    const half_t* __restrict__ Qh, const half_t* __restrict__ Ql,
    const half_t* __restrict__ Kp, const half_t* __restrict__ Vp,
    half_t* __restrict__ O)
{
  extern __shared__ char smraw[];
  const uint32_t smb = (uint32_t)__cvta_generic_to_shared(smraw);
  const int tid = threadIdx.x, lane = tid & 31, warp = tid >> 5;
  const int qt = gridDim.x - 1 - blockIdx.x;   // big tiles first
  const int h = blockIdx.y, b = blockIdx.z, hkv = h >> 2;
  const int g = lane >> 2, t = lane & 3;

  const half_t* qhp = Qh + ((size_t)(b*Hc + h)*Lc + qt*64) * HDc;
  const half_t* qlp = Ql + ((size_t)(b*Hc + h)*Lc + qt*64) * HDc;
  const size_t kvoff = (size_t)(b*HKVc + hkv) * Lc * HDc;
  const half_t* kvsrc[2] = { Kp + kvoff, Vp + kvoff };

  // stage Q (once): 64 rows x 64 cols fp16, hi+lo
#pragma unroll
  for (int it = 0; it < 4; it++){
    int fid = tid + it * 128;
    int row = fid >> 3, ch = fid & 7;
    uint4 vh4 = *(const uint4*)(qhp + row*64 + ch*8);
    uint4 vl4 = *(const uint4*)(qlp + row*64 + ch*8);
    int off = row*128 + ((ch ^ (row & 7)) * 16);
    *(uint4*)(smraw + off)        = vh4;
    *(uint4*)(smraw + 8192 + off) = vl4;
  }

  auto stageKV = [&](int j, int s){
#pragma unroll
    for (int q = 0; q < 2; q++)
#pragma unroll
      for (int it = 0; it < 4; it++){
        int fid = tid + it * 128;
        int row = fid >> 3, ch = fid & 7;
        cp16(smb + FSM_KV + s*KV_STG + q*8192 + row*128 + ((ch ^ (row & 7))*16),
             kvsrc[q] + (size_t)(j*64 + row)*64 + ch*8);
      }
  };

  stageKV(0, 0); CPCOMMIT();
  __syncthreads();

  // Q fragments (persistent)
  uint32_t qfh[4][4], qfl[4][4];
  {
    int r = warp*16 + (lane & 7) + ((lane >> 3) & 1) * 8;
#pragma unroll
    for (int kc = 0; kc < 4; kc++){
      int ch = kc*2 + (lane >> 4);
      uint32_t ad = smb + r*128 + ((ch ^ (r & 7)) * 16);
      LDSM4(qfh[kc][0], qfh[kc][1], qfh[kc][2], qfh[kc][3], ad);
      LDSM4(qfl[kc][0], qfl[kc][1], qfl[kc][2], qfl[kc][3], ad + 8192);
    }
  }

  float o[8][4];
#pragma unroll
  for (int nt=0;nt<8;nt++)
#pragma unroll
    for (int e=0;e<4;e++) o[nt][e] = 0.f;
  float m0r = -1e30f, m1r = -1e30f, l0 = 0.f, l1 = 0.f;

  const int r0g = qt*64 + warp*16 + g;
  const int r1g = r0g + 8;
  const int rBv = (lane & 7) + ((lane >> 4) << 3);
  const int chBv = (lane >> 3) & 1;
  const int rVv = (lane & 7) + (((lane >> 3) & 1) << 3);
  const int chVv = lane >> 4;

  for (int j = 0; j <= qt; j++){
    int s = j & 1;
    CPWAIT0();
    __syncthreads();
    if (j < qt){ stageKV(j + 1, s ^ 1); CPCOMMIT(); }

    const uint32_t kb = smb + FSM_KV + s*KV_STG;

    float sf[8][4];
#pragma unroll
    for (int nt=0;nt<8;nt++)
#pragma unroll
      for (int e=0;e<4;e++) sf[nt][e] = 0.f;

    // S = Q K^T : Q hi/lo fp16 (2 terms), K single fp16
#pragma unroll
    for (int kc = 0; kc < 4; kc++){
#pragma unroll
      for (int ntp = 0; ntp < 4; ntp++){
        int r = ntp*16 + rBv;
        int ch = kc*2 + chBv;
        uint32_t ad = kb + r*128 + ((ch ^ (r & 7)) * 16);
        uint32_t b0,b1,b2,b3;
        LDSM4(b0,b1,b2,b3, ad);
        MMAH(sf[2*ntp],   qfh[kc], b0, b1);
        MMAH(sf[2*ntp+1], qfh[kc], b2, b3);
        MMAH(sf[2*ntp],   qfl[kc], b0, b1);
        MMAH(sf[2*ntp+1], qfl[kc], b2, b3);
      }
    }

    float tm0 = -1e30f, tm1 = -1e30f;
    const bool mayMask = (j == qt);
#pragma unroll
    for (int nt = 0; nt < 8; nt++){
      int c0 = j*64 + nt*8 + 2*t;
      float v0 = sf[nt][0]*0.125f, v1 = sf[nt][1]*0.125f;
      float v2 = sf[nt][2]*0.125f, v3 = sf[nt][3]*0.125f;
      if (mayMask){
        if (c0     > r0g) v0 = -1e30f;
        if (c0 + 1 > r0g) v1 = -1e30f;
        if (c0     > r1g) v2 = -1e30f;
        if (c0 + 1 > r1g) v3 = -1e30f;
      }
      sf[nt][0]=v0; sf[nt][1]=v1; sf[nt][2]=v2; sf[nt][3]=v3;
      tm0 = fmaxf(tm0, fmaxf(v0, v1));
      tm1 = fmaxf(tm1, fmaxf(v2, v3));
    }
    tm0 = fmaxf(tm0, __shfl_xor_sync(0xffffffffu, tm0, 1));
    tm0 = fmaxf(tm0, __shfl_xor_sync(0xffffffffu, tm0, 2));
    tm1 = fmaxf(tm1, __shfl_xor_sync(0xffffffffu, tm1, 1));
    tm1 = fmaxf(tm1, __shfl_xor_sync(0xffffffffu, tm1, 2));

    float mn0 = fmaxf(m0r, tm0), mn1 = fmaxf(m1r, tm1);
    float corr0 = __expf(m0r - mn0), corr1 = __expf(m1r - mn1);
    float s0 = 0.f, s1 = 0.f;
#pragma unroll
    for (int nt = 0; nt < 8; nt++){
      sf[nt][0] = __expf(sf[nt][0] - mn0);
      sf[nt][1] = __expf(sf[nt][1] - mn0);
      sf[nt][2] = __expf(sf[nt][2] - mn1);
      sf[nt][3] = __expf(sf[nt][3] - mn1);
      s0 += sf[nt][0] + sf[nt][1];
      s1 += sf[nt][2] + sf[nt][3];
    }
    s0 += __shfl_xor_sync(0xffffffffu, s0, 1);
    s0 += __shfl_xor_sync(0xffffffffu, s0, 2);
    s1 += __shfl_xor_sync(0xffffffffu, s1, 1);
    s1 += __shfl_xor_sync(0xffffffffu, s1, 2);
    l0 = l0*corr0 + s0;  l1 = l1*corr1 + s1;
    m0r = mn0;  m1r = mn1;
#pragma unroll
    for (int nt = 0; nt < 8; nt++){
      o[nt][0] *= corr0; o[nt][1] *= corr0;
      o[nt][2] *= corr1; o[nt][3] *= corr1;
    }

    // O += P V : P single fp16, V single fp16 (1 term)
    const uint32_t vb = kb + 8192;
#pragma unroll
    for (int kc = 0; kc < 4; kc++){
      uint32_t ph[4];
#pragma unroll
      for (int q2 = 0; q2 < 2; q2++){
        __half2 p01 = { __float2half_rn(sf[2*kc+q2][0]), __float2half_rn(sf[2*kc+q2][1]) };
        __half2 p23 = { __float2half_rn(sf[2*kc+q2][2]), __float2half_rn(sf[2*kc+q2][3]) };
        ph[2*q2 + 0] = *(uint32_t*)&p01;
        ph[2*q2 + 1] = *(uint32_t*)&p23;
      }
#pragma unroll
      for (int ntp = 0; ntp < 4; ntp++){
        int r = kc*16 + rVv;
        int ch = ntp*2 + chVv;
        uint32_t ad = vb + r*128 + ((ch ^ (r & 7)) * 16);
        uint32_t w0,w1,w2,w3;
        LDSM4T(w0,w1,w2,w3, ad);
        MMAH(o[2*ntp],   ph, w0, w1);
        MMAH(o[2*ntp+1], ph, w2, w3);
      }
    }
  }

  // epilogue: normalize, write single fp16 attn [b][l][h][d]
  float inv0 = 1.f / l0, inv1 = 1.f / l1;
  size_t ob0 = ((size_t)(b*Lc + qt*64 + warp*16 + g) * Hc + h) * HDc;
  size_t ob1 = ob0 + (size_t)8 * Hc * HDc;
#pragma unroll
  for (int nt = 0; nt < 8; nt++){
    int d = nt*8 + 2*t;
    __half2 a = { __float2half_rn(o[nt][0]*inv0), __float2half_rn(o[nt][1]*inv0) };
    __half2 c = { __float2half_rn(o[nt][2]*inv1), __float2half_rn(o[nt][3]*inv1) };
    *(__half2*)(O + ob0 + d) = a;
    *(__half2*)(O + ob1 + d) = c;
  }
}

// ---------------------------------------------------------------------------
extern "C" void kernel_launch(void* const* d_in, const int* in_sizes, int n_in,
                              void* d_out, int out_size)
{
  const float* x   = (const float*)d_in[0];
  const float* Wq  = (const float*)d_in[1];
  const float* Wk  = (const float*)d_in[2];
  const float* Wv  = (const float*)d_in[3];
  const float* Wo  = (const float*)d_in[4];
  const float* qnw = (const float*)d_in[5];
  const float* knw = (const float*)d_in[6];
  float* out = (float*)d_out;

  float *qkv;
  half_t *x16,*wqkv,*wo,*at,*qh,*ql,*kk,*vv;
  cudaGetSymbolAddress((void**)&qkv, g_qkv);
  cudaGetSymbolAddress((void**)&x16, g_x16);
  cudaGetSymbolAddress((void**)&wqkv, g_wqkvT);
  cudaGetSymbolAddress((void**)&wo, g_woT);
  cudaGetSymbolAddress((void**)&qh, g_qh); cudaGetSymbolAddress((void**)&ql, g_ql);
  cudaGetSymbolAddress((void**)&kk, g_k);  cudaGetSymbolAddress((void**)&vv, g_v);
  cudaGetSymbolAddress((void**)&at, g_at);

  const int M = Mtok;

  // (1) activation convert
  xcvt<<<(M*Dc/4 + 255)/256, 256>>>(x, x16, M*Dc/4);
  // (2) all weight transposes in one launch
  wsplit_all<<<dim3(64, 64, 4), dim3(32,8)>>>(Wq, Wk, Wv, Wo, wqkv, wo);

  // (3) fused QKV projection: C [M][3072]
  cudaFuncSetAttribute(gemm_fp16, cudaFuncAttributeMaxDynamicSharedMemorySize, 2*GSTG1);
  gemm_fp16<<<dim3(QKVN/128, M/128), 256, 2*GSTG1>>>(x16, wqkv, qkv, M, QKVN, Dc);

  // (4) fused norm + rope + convert (head-major)
  {
    int nw = M*Hc + 2*M*HKVc;
    qkvpost<<<(nw*32 + 255)/256, 256>>>(qkv, qnw, knw, qh, ql, kk, vv);
  }

  // (5) flash attention (ncu capture target)
  cudaFuncSetAttribute(flash_tc, cudaFuncAttributeMaxDynamicSharedMemorySize, FLASH_SMEM);
  flash_tc<<<dim3(Lc/64, Hc, Bc), 128, FLASH_SMEM>>>(qh, ql, kk, vv, at);

  // (6) output projection
  gemm_fp16<<<dim3(Dc/128, M/128), 256, 2*GSTG1>>>(at, wo, out, M, Dc, Dc);
}

// round 9
// speedup vs baseline: 2.4073x; 1.0533x over previous
#include <cuda_runtime.h>
#include <cuda_fp16.h>
#include <math.h>
#include <stdint.h>
#include <stddef.h>

#define Bc 2
#define Lc 2048
#define Dc 2048
#define Hc 32
#define HKVc 8
#define HDc 64
#define Mtok (Bc*Lc)
#define QKVN 3072          // fused projection width: 2048 Q | 512 K | 512 V

typedef __half half_t;

// ---------------- scratch (__device__ globals; no allocs allowed) -----------
__device__ __align__(16) half_t g_x16[(size_t)Mtok*Dc];     // x single fp16
__device__ __align__(16) half_t g_wqkvT[(size_t)QKVN*Dc];   // single fp16
__device__ __align__(16) half_t g_woT[(size_t)Dc*Hc*HDc];   // single fp16
__device__ __align__(16) half_t g_qh[(size_t)Bc*Hc*Lc*HDc]; // Q hi (fp16)
__device__ __align__(16) half_t g_ql[(size_t)Bc*Hc*Lc*HDc]; // Q lo (fp16)
__device__ __align__(16) half_t g_k[(size_t)Bc*HKVc*Lc*HDc];// K single fp16
__device__ __align__(16) half_t g_v[(size_t)Bc*HKVc*Lc*HDc];// V single fp16
__device__ __align__(16) half_t g_at[(size_t)Mtok*Hc*HDc];  // attn single fp16

// ---------------- PTX helpers ----------------------------------------------
#define MMAH(CR, A, B0, B1)                                                  \
  asm volatile(                                                              \
      "mma.sync.aligned.m16n8k16.row.col.f32.f16.f16.f32 "                   \
      "{%0,%1,%2,%3},{%4,%5,%6,%7},{%8,%9},{%0,%1,%2,%3};"                   \
      : "+f"((CR)[0]), "+f"((CR)[1]), "+f"((CR)[2]), "+f"((CR)[3])           \
      : "r"((A)[0]), "r"((A)[1]), "r"((A)[2]), "r"((A)[3]), "r"(B0), "r"(B1))

#define LDSM4(R0,R1,R2,R3,ADDR)                                              \
  asm volatile("ldmatrix.sync.aligned.m8n8.x4.shared.b16 {%0,%1,%2,%3},[%4];"\
      : "=r"(R0),"=r"(R1),"=r"(R2),"=r"(R3) : "r"(ADDR))

#define LDSM4T(R0,R1,R2,R3,ADDR)                                             \
  asm volatile("ldmatrix.sync.aligned.m8n8.x4.trans.shared.b16 {%0,%1,%2,%3},[%4];"\
      : "=r"(R0),"=r"(R1),"=r"(R2),"=r"(R3) : "r"(ADDR))

__device__ __forceinline__ void cp16(uint32_t dst, const void* src){
  asm volatile("cp.async.cg.shared.global [%0], [%1], 16;" :: "r"(dst), "l"(src));
}
#define CPCOMMIT() asm volatile("cp.async.commit_group;")
#define CPWAIT0()  asm volatile("cp.async.wait_group 0;")

__device__ __forceinline__ void split1h(float v, half_t& h, half_t& l){
  h = __float2half_rn(v);
  l = __float2half_rn(v - __half2float(h));
}

// ---------------- convert passes --------------------------------------------
__global__ void xcvt(const float* __restrict__ src, half_t* __restrict__ d, int n4)
{
  int i = blockIdx.x * blockDim.x + threadIdx.x;
  if (i >= n4) return;
  float4 v = ((const float4*)src)[i];
  __half2 h0 = { __float2half_rn(v.x), __float2half_rn(v.y) };
  __half2 h1 = { __float2half_rn(v.z), __float2half_rn(v.w) };
  ((__half2*)d)[2*i] = h0; ((__half2*)d)[2*i+1] = h1;
}

// One launch for all four weight transposes -> single fp16 [N][K]
__global__ void wsplit_all(const float* __restrict__ Wq,
                           const float* __restrict__ Wk,
                           const float* __restrict__ Wv,
                           const float* __restrict__ Wo,
                           half_t* __restrict__ wqkv, half_t* __restrict__ wo)
{
  const int z = blockIdx.z;
  const float* W; half_t* T; int K, N;
  if (z == 0){ W = Wq; T = wqkv;                       K = Dc;     N = Hc*HDc; }
  else if (z == 1){ W = Wk; T = wqkv + (size_t)2048*Dc; K = Dc;    N = HKVc*HDc; }
  else if (z == 2){ W = Wv; T = wqkv + (size_t)2560*Dc; K = Dc;    N = HKVc*HDc; }
  else            { W = Wo; T = wo;                     K = Hc*HDc; N = Dc; }
  if (blockIdx.x * 32 >= N) return;

  __shared__ float tile[32][33];
  int k0 = blockIdx.y*32, n0 = blockIdx.x*32;
  int tx = threadIdx.x, ty = threadIdx.y;
#pragma unroll
  for (int i = 0; i < 4; i++)
    tile[ty + 8*i][tx] = W[(size_t)(k0 + ty + 8*i) * N + n0 + tx];
  __syncthreads();
#pragma unroll
  for (int i = 0; i < 4; i++){
    int n = n0 + ty + 8*i;
    T[(size_t)n*K + k0 + tx] = __float2half_rn(tile[tx][ty + 8*i]);
  }
}

// ---------------- fused QKV GEMM + RMSNorm + RoPE + head-major fp16 ---------
// C = x16 @ wqkvT^T (M=4096, N=3072, K=2048). Each warp's 64-wide N-half is
// exactly one head: RMS sum = quad reduce; RoPE pair (d,d+32) = (nt,nt+4)
// within one thread. Outputs head-major fp16 (Q hi/lo, K, V) directly.
#define GSTG1 32768
__global__ __launch_bounds__(256) void gemm_qkv(
    const half_t* __restrict__ A, const half_t* __restrict__ B,
    const float* __restrict__ qnw, const float* __restrict__ knw,
    half_t* __restrict__ qh, half_t* __restrict__ ql,
    half_t* __restrict__ kk, half_t* __restrict__ vv)
{
  const int M = Mtok, N = QKVN, K = Dc;
  extern __shared__ char smraw[];
  const uint32_t smb = (uint32_t)__cvta_generic_to_shared(smraw);
  const int tid = threadIdx.x, lane = tid & 31, warp = tid >> 5;
  const int wm = (warp & 3) * 32, wn = (warp >> 2) * 64;
  const int g = lane >> 2, t = lane & 3;
  const int row0 = blockIdx.y * 128, col0 = blockIdx.x * 128;
  const int KI = K >> 6;

  const half_t* gsrc[2] = { A + (size_t)row0 * K, B + (size_t)col0 * K };

  auto stage = [&](int ki, int s){
#pragma unroll
    for (int q = 0; q < 2; q++)
#pragma unroll
      for (int it = 0; it < 4; it++){
        int fid = tid + it * 256;
        int row = fid >> 3, ch = fid & 7;
        cp16(smb + s*GSTG1 + q*16384 + row*128 + ((ch ^ (row & 7)) * 16),
             gsrc[q] + (size_t)row * K + ki*64 + ch*8);
      }
  };

  float c[2][8][4];
#pragma unroll
  for (int i=0;i<2;i++)
#pragma unroll
    for (int j=0;j<8;j++)
#pragma unroll
      for (int e=0;e<4;e++) c[i][j][e] = 0.f;

  stage(0, 0); CPCOMMIT();

  for (int ki = 0; ki < KI; ki++){
    int s = ki & 1;
    CPWAIT0();
    __syncthreads();
    if (ki + 1 < KI){ stage(ki + 1, s ^ 1); CPCOMMIT(); }

    const uint32_t ab = smb + s*GSTG1, bb = ab + 16384;
    const int rA  = (lane & 7) + ((lane >> 3) & 1) * 8;
    const int chA = (lane >> 4);
    const int rB  = (lane & 7) + ((lane >> 4) << 3);
    const int chB = (lane >> 3) & 1;
#pragma unroll
    for (int kc = 0; kc < 4; kc++){
      uint32_t ah[2][4];
#pragma unroll
      for (int mt = 0; mt < 2; mt++){
        int r = wm + mt*16 + rA;
        int ch = kc*2 + chA;
        uint32_t ad = ab + r*128 + ((ch ^ (r & 7)) * 16);
        LDSM4(ah[mt][0], ah[mt][1], ah[mt][2], ah[mt][3], ad);
      }
#pragma unroll
      for (int ntp = 0; ntp < 4; ntp++){
        int r = wn + ntp*16 + rB;
        int ch = kc*2 + chB;
        uint32_t ad = bb + r*128 + ((ch ^ (r & 7)) * 16);
        uint32_t b0,b1,b2,b3;
        LDSM4(b0,b1,b2,b3, ad);
#pragma unroll
        for (int mt = 0; mt < 2; mt++){
          MMAH(c[mt][2*ntp],   ah[mt], b0, b1);
          MMAH(c[mt][2*ntp+1], ah[mt], b2, b3);
        }
      }
    }
    __syncthreads();
  }

  // ---- fused epilogue ----
  const int gcol = col0 + wn;            // this warp's head starts here
  int mode, nh, head;
  const float* w = qnw;
  if (gcol < 2048)      { mode = 0; nh = Hc;   head = gcol >> 6; w = qnw; }
  else if (gcol < 2560) { mode = 1; nh = HKVc; head = (gcol - 2048) >> 6; w = knw; }
  else                  { mode = 2; nh = HKVc; head = (gcol - 2560) >> 6; }

  // per-thread rope freqs for pair-index d0 = nt*8+2t, d0+1 (d0 < 32)
  float invf[8];
  if (mode < 2){
#pragma unroll
    for (int nt = 0; nt < 4; nt++){
      int d0 = nt*8 + 2*t;
      invf[2*nt]   = powf(1000000.0f, -((float)(2*d0))     * (1.0f/64.0f));
      invf[2*nt+1] = powf(1000000.0f, -((float)(2*(d0+1))) * (1.0f/64.0f));
    }
  }

#pragma unroll
  for (int mt = 0; mt < 2; mt++){
    int r0 = row0 + wm + mt*16 + g;      // rows r0 (e=0,1) and r0+8 (e=2,3)
    float rn0 = 0.f, rn1 = 0.f;
    if (mode < 2){
      float ss0 = 0.f, ss1 = 0.f;
#pragma unroll
      for (int nt = 0; nt < 8; nt++){
        ss0 += c[mt][nt][0]*c[mt][nt][0] + c[mt][nt][1]*c[mt][nt][1];
        ss1 += c[mt][nt][2]*c[mt][nt][2] + c[mt][nt][3]*c[mt][nt][3];
      }
      ss0 += __shfl_xor_sync(0xffffffffu, ss0, 1);
      ss0 += __shfl_xor_sync(0xffffffffu, ss0, 2);
      ss1 += __shfl_xor_sync(0xffffffffu, ss1, 1);
      ss1 += __shfl_xor_sync(0xffffffffu, ss1, 2);
      rn0 = rsqrtf(ss0 * (1.0f/64.0f) + 1e-5f);
      rn1 = rsqrtf(ss1 * (1.0f/64.0f) + 1e-5f);
    }

#pragma unroll
    for (int half2row = 0; half2row < 2; half2row++){
      int r = r0 + half2row*8;
      int e = half2row*2;                // e, e+1 are this row's two cols
      float rn = half2row ? rn1 : rn0;
      int pos = r & (Lc-1);
      int b = r >> 11;
      size_t base = ((size_t)(b*nh + head)*Lc + pos) * HDc;

      if (mode == 2){
#pragma unroll
        for (int nt = 0; nt < 8; nt++){
          int d0 = nt*8 + 2*t;
          __half2 v2 = { __float2half_rn(c[mt][nt][e]), __float2half_rn(c[mt][nt][e+1]) };
          *(__half2*)(vv + base + d0) = v2;
        }
      } else {
        float fpos = (float)pos;
#pragma unroll
        for (int nt = 0; nt < 4; nt++){
          int d0 = nt*8 + 2*t;
          float x1a = c[mt][nt][e]   * rn * w[d0];
          float x1b = c[mt][nt][e+1] * rn * w[d0+1];
          float x2a = c[mt][nt+4][e]   * rn * w[d0+32];
          float x2b = c[mt][nt+4][e+1] * rn * w[d0+33];
          float anga = fpos * invf[2*nt],  angb = fpos * invf[2*nt+1];
          float ca = cosf(anga), sa = sinf(anga);
          float cb = cosf(angb), sb = sinf(angb);
          float y1a = x1a*ca - x2a*sa,  y1b = x1b*cb - x2b*sb;
          float y2a = x2a*ca + x1a*sa,  y2b = x2b*cb + x1b*sb;
          if (mode == 0){
            half_t h0,l0,h1,l1,h2,l2,h3,l3;
            split1h(y1a,h0,l0); split1h(y1b,h1,l1);
            split1h(y2a,h2,l2); split1h(y2b,h3,l3);
            __half2 hh1 = {h0,h1}, ll1 = {l0,l1}, hh2 = {h2,h3}, ll2 = {l2,l3};
            *(__half2*)(qh + base + d0)      = hh1;
            *(__half2*)(ql + base + d0)      = ll1;
            *(__half2*)(qh + base + d0 + 32) = hh2;
            *(__half2*)(ql + base + d0 + 32) = ll2;
          } else {
            __half2 v1 = { __float2half_rn(y1a), __float2half_rn(y1b) };
            __half2 v2 = { __float2half_rn(y2a), __float2half_rn(y2b) };
            *(__half2*)(kk + base + d0)      = v1;
            *(__half2*)(kk + base + d0 + 32) = v2;
          }
        }
      }
    }
  }
}

// ---------------- single fp16 tensor-core GEMM (Wo) -------------------------
__global__ __launch_bounds__(256) void gemm_fp16(
    const half_t* __restrict__ A, const half_t* __restrict__ B,
    float* __restrict__ C, int M, int N, int K)
{
  extern __shared__ char smraw[];
  const uint32_t smb = (uint32_t)__cvta_generic_to_shared(smraw);
  const int tid = threadIdx.x, lane = tid & 31, warp = tid >> 5;
  const int wm = (warp & 3) * 32, wn = (warp >> 2) * 64;
  const int g = lane >> 2, t = lane & 3;
  const int row0 = blockIdx.y * 128, col0 = blockIdx.x * 128;
  const int KI = K >> 6;

  const half_t* gsrc[2] = { A + (size_t)row0 * K, B + (size_t)col0 * K };

  auto stage = [&](int ki, int s){
#pragma unroll
    for (int q = 0; q < 2; q++)
#pragma unroll
      for (int it = 0; it < 4; it++){
        int fid = tid + it * 256;
        int row = fid >> 3, ch = fid & 7;
        cp16(smb + s*GSTG1 + q*16384 + row*128 + ((ch ^ (row & 7)) * 16),
             gsrc[q] + (size_t)row * K + ki*64 + ch*8);
      }
  };

  float c[2][8][4];
#pragma unroll
  for (int i=0;i<2;i++)
#pragma unroll
    for (int j=0;j<8;j++)
#pragma unroll
      for (int e=0;e<4;e++) c[i][j][e] = 0.f;

  stage(0, 0); CPCOMMIT();

  for (int ki = 0; ki < KI; ki++){
    int s = ki & 1;
    CPWAIT0();
    __syncthreads();
    if (ki + 1 < KI){ stage(ki + 1, s ^ 1); CPCOMMIT(); }

    const uint32_t ab = smb + s*GSTG1, bb = ab + 16384;
    const int rA  = (lane & 7) + ((lane >> 3) & 1) * 8;
    const int chA = (lane >> 4);
    const int rB  = (lane & 7) + ((lane >> 4) << 3);
    const int chB = (lane >> 3) & 1;
#pragma unroll
    for (int kc = 0; kc < 4; kc++){
      uint32_t ah[2][4];
#pragma unroll
      for (int mt = 0; mt < 2; mt++){
        int r = wm + mt*16 + rA;
        int ch = kc*2 + chA;
        uint32_t ad = ab + r*128 + ((ch ^ (r & 7)) * 16);
        LDSM4(ah[mt][0], ah[mt][1], ah[mt][2], ah[mt][3], ad);
      }
#pragma unroll
      for (int ntp = 0; ntp < 4; ntp++){
        int r = wn + ntp*16 + rB;
        int ch = kc*2 + chB;
        uint32_t ad = bb + r*128 + ((ch ^ (r & 7)) * 16);
        uint32_t b0,b1,b2,b3;
        LDSM4(b0,b1,b2,b3, ad);
#pragma unroll
        for (int mt = 0; mt < 2; mt++){
          MMAH(c[mt][2*ntp],   ah[mt], b0, b1);
          MMAH(c[mt][2*ntp+1], ah[mt], b2, b3);
        }
      }
    }
    __syncthreads();
  }

#pragma unroll
  for (int mt = 0; mt < 2; mt++)
#pragma unroll
    for (int nt = 0; nt < 8; nt++){
      int r = row0 + wm + mt*16 + g;
      int cc = col0 + wn + nt*8 + 2*t;
      float2 v0 = { c[mt][nt][0], c[mt][nt][1] };
      float2 v1 = { c[mt][nt][2], c[mt][nt][3] };
      *(float2*)(C + (size_t)r * N + cc) = v0;
      *(float2*)(C + (size_t)(r + 8) * N + cc) = v1;
    }
}

// ---------------- tensor-core flash attention (fp16, 64-row q tiles) --------
// smem: Qh 8K | Ql 8K | 2 stages x (K 8K | V 8K) = 48K total.
#define FSM_KV  16384
#define KV_STG  16384
#define FLASH_SMEM (16384 + 2*KV_STG)

__global__ __launch_bounds__(128) void flash_tc(
    const half_t* __restrict__ Qh, const half_t* __restrict__ Ql,
    const half_t* __restrict__ Kp, const half_t* __restrict__ Vp,
    half_t* __restrict__ O)
{
  extern __shared__ char smraw[];
  const uint32_t smb = (uint32_t)__cvta_generic_to_shared(smraw);
  const int tid = threadIdx.x, lane = tid & 31, warp = tid >> 5;
  const int qt = gridDim.x - 1 - blockIdx.x;   // big tiles first
  const int h = blockIdx.y, b = blockIdx.z, hkv = h >> 2;
  const int g = lane >> 2, t = lane & 3;

  const half_t* qhp = Qh + ((size_t)(b*Hc + h)*Lc + qt*64) * HDc;
  const half_t* qlp = Ql + ((size_t)(b*Hc + h)*Lc + qt*64) * HDc;
  const size_t kvoff = (size_t)(b*HKVc + hkv) * Lc * HDc;
  const half_t* kvsrc[2] = { Kp + kvoff, Vp + kvoff };

  // stage Q (once): 64 rows x 64 cols fp16, hi+lo
#pragma unroll
  for (int it = 0; it < 4; it++){
    int fid = tid + it * 128;
    int row = fid >> 3, ch = fid & 7;
    uint4 vh4 = *(const uint4*)(qhp + row*64 + ch*8);
    uint4 vl4 = *(const uint4*)(qlp + row*64 + ch*8);
    int off = row*128 + ((ch ^ (row & 7)) * 16);
    *(uint4*)(smraw + off)        = vh4;
    *(uint4*)(smraw + 8192 + off) = vl4;
  }

  auto stageKV = [&](int j, int s){
#pragma unroll
    for (int q = 0; q < 2; q++)
#pragma unroll
      for (int it = 0; it < 4; it++){
        int fid = tid + it * 128;
        int row = fid >> 3, ch = fid & 7;
        cp16(smb + FSM_KV + s*KV_STG + q*8192 + row*128 + ((ch ^ (row & 7))*16),
             kvsrc[q] + (size_t)(j*64 + row)*64 + ch*8);
      }
  };

  stageKV(0, 0); CPCOMMIT();
  __syncthreads();

  // Q fragments (persistent)
  uint32_t qfh[4][4], qfl[4][4];
  {
    int r = warp*16 + (lane & 7) + ((lane >> 3) & 1) * 8;
#pragma unroll
    for (int kc = 0; kc < 4; kc++){
      int ch = kc*2 + (lane >> 4);
      uint32_t ad = smb + r*128 + ((ch ^ (r & 7)) * 16);
      LDSM4(qfh[kc][0], qfh[kc][1], qfh[kc][2], qfh[kc][3], ad);
      LDSM4(qfl[kc][0], qfl[kc][1], qfl[kc][2], qfl[kc][3], ad + 8192);
    }
  }

  float o[8][4];
#pragma unroll
  for (int nt=0;nt<8;nt++)
#pragma unroll
    for (int e=0;e<4;e++) o[nt][e] = 0.f;
  float m0r = -1e30f, m1r = -1e30f, l0 = 0.f, l1 = 0.f;

  const int r0g = qt*64 + warp*16 + g;
  const int r1g = r0g + 8;
  const int rBv = (lane & 7) + ((lane >> 4) << 3);
  const int chBv = (lane >> 3) & 1;
  const int rVv = (lane & 7) + (((lane >> 3) & 1) << 3);
  const int chVv = lane >> 4;

  for (int j = 0; j <= qt; j++){
    int s = j & 1;
    CPWAIT0();
    __syncthreads();
    if (j < qt){ stageKV(j + 1, s ^ 1); CPCOMMIT(); }

    const uint32_t kb = smb + FSM_KV + s*KV_STG;

    float sf[8][4];
#pragma unroll
    for (int nt=0;nt<8;nt++)
#pragma unroll
      for (int e=0;e<4;e++) sf[nt][e] = 0.f;

    // S = Q K^T : Q hi/lo fp16 (2 terms), K single fp16
#pragma unroll
    for (int kc = 0; kc < 4; kc++){
#pragma unroll
      for (int ntp = 0; ntp < 4; ntp++){
        int r = ntp*16 + rBv;
        int ch = kc*2 + chBv;
        uint32_t ad = kb + r*128 + ((ch ^ (r & 7)) * 16);
        uint32_t b0,b1,b2,b3;
        LDSM4(b0,b1,b2,b3, ad);
        MMAH(sf[2*ntp],   qfh[kc], b0, b1);
        MMAH(sf[2*ntp+1], qfh[kc], b2, b3);
        MMAH(sf[2*ntp],   qfl[kc], b0, b1);
        MMAH(sf[2*ntp+1], qfl[kc], b2, b3);
      }
    }

    float tm0 = -1e30f, tm1 = -1e30f;
    const bool mayMask = (j == qt);
#pragma unroll
    for (int nt = 0; nt < 8; nt++){
      int c0 = j*64 + nt*8 + 2*t;
      float v0 = sf[nt][0]*0.125f, v1 = sf[nt][1]*0.125f;
      float v2 = sf[nt][2]*0.125f, v3 = sf[nt][3]*0.125f;
      if (mayMask){
        if (c0     > r0g) v0 = -1e30f;
        if (c0 + 1 > r0g) v1 = -1e30f;
        if (c0     > r1g) v2 = -1e30f;
        if (c0 + 1 > r1g) v3 = -1e30f;
      }
      sf[nt][0]=v0; sf[nt][1]=v1; sf[nt][2]=v2; sf[nt][3]=v3;
      tm0 = fmaxf(tm0, fmaxf(v0, v1));
      tm1 = fmaxf(tm1, fmaxf(v2, v3));
    }
    tm0 = fmaxf(tm0, __shfl_xor_sync(0xffffffffu, tm0, 1));
    tm0 = fmaxf(tm0, __shfl_xor_sync(0xffffffffu, tm0, 2));
    tm1 = fmaxf(tm1, __shfl_xor_sync(0xffffffffu, tm1, 1));
    tm1 = fmaxf(tm1, __shfl_xor_sync(0xffffffffu, tm1, 2));

    float mn0 = fmaxf(m0r, tm0), mn1 = fmaxf(m1r, tm1);
    float corr0 = __expf(m0r - mn0), corr1 = __expf(m1r - mn1);
    float s0 = 0.f, s1 = 0.f;
#pragma unroll
    for (int nt = 0; nt < 8; nt++){
      sf[nt][0] = __expf(sf[nt][0] - mn0);
      sf[nt][1] = __expf(sf[nt][1] - mn0);
      sf[nt][2] = __expf(sf[nt][2] - mn1);
      sf[nt][3] = __expf(sf[nt][3] - mn1);
      s0 += sf[nt][0] + sf[nt][1];
      s1 += sf[nt][2] + sf[nt][3];
    }
    s0 += __shfl_xor_sync(0xffffffffu, s0, 1);
    s0 += __shfl_xor_sync(0xffffffffu, s0, 2);
    s1 += __shfl_xor_sync(0xffffffffu, s1, 1);
    s1 += __shfl_xor_sync(0xffffffffu, s1, 2);
    l0 = l0*corr0 + s0;  l1 = l1*corr1 + s1;
    m0r = mn0;  m1r = mn1;
#pragma unroll
    for (int nt = 0; nt < 8; nt++){
      o[nt][0] *= corr0; o[nt][1] *= corr0;
      o[nt][2] *= corr1; o[nt][3] *= corr1;
    }

    // O += P V : P single fp16, V single fp16 (1 term)
    const uint32_t vb = kb + 8192;
#pragma unroll
    for (int kc = 0; kc < 4; kc++){
      uint32_t ph[4];
#pragma unroll
      for (int q2 = 0; q2 < 2; q2++){
        __half2 p01 = { __float2half_rn(sf[2*kc+q2][0]), __float2half_rn(sf[2*kc+q2][1]) };
        __half2 p23 = { __float2half_rn(sf[2*kc+q2][2]), __float2half_rn(sf[2*kc+q2][3]) };
        ph[2*q2 + 0] = *(uint32_t*)&p01;
        ph[2*q2 + 1] = *(uint32_t*)&p23;
      }
#pragma unroll
      for (int ntp = 0; ntp < 4; ntp++){
        int r = kc*16 + rVv;
        int ch = ntp*2 + chVv;
        uint32_t ad = vb + r*128 + ((ch ^ (r & 7)) * 16);
        uint32_t w0,w1,w2,w3;
        LDSM4T(w0,w1,w2,w3, ad);
        MMAH(o[2*ntp],   ph, w0, w1);
        MMAH(o[2*ntp+1], ph, w2, w3);
      }
    }
  }

  // epilogue: normalize, write single fp16 attn [b][l][h][d]
  float inv0 = 1.f / l0, inv1 = 1.f / l1;
  size_t ob0 = ((size_t)(b*Lc + qt*64 + warp*16 + g) * Hc + h) * HDc;
  size_t ob1 = ob0 + (size_t)8 * Hc * HDc;
#pragma unroll
  for (int nt = 0; nt < 8; nt++){
    int d = nt*8 + 2*t;
    __half2 a = { __float2half_rn(o[nt][0]*inv0), __float2half_rn(o[nt][1]*inv0) };
    __half2 c = { __float2half_rn(o[nt][2]*inv1), __float2half_rn(o[nt][3]*inv1) };
    *(__half2*)(O + ob0 + d) = a;
    *(__half2*)(O + ob1 + d) = c;
  }
}

// ---------------------------------------------------------------------------
extern "C" void kernel_launch(void* const* d_in, const int* in_sizes, int n_in,
                              void* d_out, int out_size)
{
  const float* x   = (const float*)d_in[0];
  const float* Wq  = (const float*)d_in[1];
  const float* Wk  = (const float*)d_in[2];
  const float* Wv  = (const float*)d_in[3];
  const float* Wo  = (const float*)d_in[4];
  const float* qnw = (const float*)d_in[5];
  const float* knw = (const float*)d_in[6];
  float* out = (float*)d_out;

  half_t *x16,*wqkv,*wo,*at,*qh,*ql,*kk,*vv;
  cudaGetSymbolAddress((void**)&x16, g_x16);
  cudaGetSymbolAddress((void**)&wqkv, g_wqkvT);
  cudaGetSymbolAddress((void**)&wo, g_woT);
  cudaGetSymbolAddress((void**)&qh, g_qh); cudaGetSymbolAddress((void**)&ql, g_ql);
  cudaGetSymbolAddress((void**)&kk, g_k);  cudaGetSymbolAddress((void**)&vv, g_v);
  cudaGetSymbolAddress((void**)&at, g_at);

  const int M = Mtok;

  // (1) activation convert
  xcvt<<<(M*Dc/4 + 255)/256, 256>>>(x, x16, M*Dc/4);
  // (2) all weight transposes in one launch
  wsplit_all<<<dim3(64, 64, 4), dim3(32,8)>>>(Wq, Wk, Wv, Wo, wqkv, wo);

  // (3) fused QKV projection + RMSNorm + RoPE -> head-major fp16
  cudaFuncSetAttribute(gemm_qkv, cudaFuncAttributeMaxDynamicSharedMemorySize, 2*GSTG1);
  gemm_qkv<<<dim3(QKVN/128, M/128), 256, 2*GSTG1>>>(x16, wqkv, qnw, knw, qh, ql, kk, vv);

  // (4) flash attention
  cudaFuncSetAttribute(flash_tc, cudaFuncAttributeMaxDynamicSharedMemorySize, FLASH_SMEM);
  flash_tc<<<dim3(Lc/64, Hc, Bc), 128, FLASH_SMEM>>>(qh, ql, kk, vv, at);

  // (5) output projection
  cudaFuncSetAttribute(gemm_fp16, cudaFuncAttributeMaxDynamicSharedMemorySize, 2*GSTG1);
  gemm_fp16<<<dim3(Dc/128, M/128), 256, 2*GSTG1>>>(at, wo, out, M, Dc, Dc);
}

// round 10
// speedup vs baseline: 2.5883x; 1.0752x over previous
#include <cuda_runtime.h>
#include <cuda_fp16.h>
#include <math.h>
#include <stdint.h>
#include <stddef.h>

#define Bc 2
#define Lc 2048
#define Dc 2048
#define Hc 32
#define HKVc 8
#define HDc 64
#define Mtok (Bc*Lc)
#define QKVN 3072          // fused projection width: 2048 Q | 512 K | 512 V

typedef __half half_t;

// ---------------- scratch (__device__ globals; no allocs allowed) -----------
__device__ __align__(16) half_t g_x16[(size_t)Mtok*Dc];     // x single fp16
__device__ __align__(16) half_t g_wqkvT[(size_t)QKVN*Dc];   // single fp16
__device__ __align__(16) half_t g_woT[(size_t)Dc*Hc*HDc];   // single fp16
__device__ __align__(16) half_t g_q[(size_t)Bc*Hc*Lc*HDc];  // Q single fp16
__device__ __align__(16) half_t g_k[(size_t)Bc*HKVc*Lc*HDc];// K single fp16
__device__ __align__(16) half_t g_v[(size_t)Bc*HKVc*Lc*HDc];// V single fp16
__device__ __align__(16) half_t g_at[(size_t)Mtok*Hc*HDc];  // attn single fp16

// ---------------- PTX helpers ----------------------------------------------
#define MMAH(CR, A, B0, B1)                                                  \
  asm volatile(                                                              \
      "mma.sync.aligned.m16n8k16.row.col.f32.f16.f16.f32 "                   \
      "{%0,%1,%2,%3},{%4,%5,%6,%7},{%8,%9},{%0,%1,%2,%3};"                   \
      : "+f"((CR)[0]), "+f"((CR)[1]), "+f"((CR)[2]), "+f"((CR)[3])           \
      : "r"((A)[0]), "r"((A)[1]), "r"((A)[2]), "r"((A)[3]), "r"(B0), "r"(B1))

#define LDSM4(R0,R1,R2,R3,ADDR)                                              \
  asm volatile("ldmatrix.sync.aligned.m8n8.x4.shared.b16 {%0,%1,%2,%3},[%4];"\
      : "=r"(R0),"=r"(R1),"=r"(R2),"=r"(R3) : "r"(ADDR))

#define LDSM4T(R0,R1,R2,R3,ADDR)                                             \
  asm volatile("ldmatrix.sync.aligned.m8n8.x4.trans.shared.b16 {%0,%1,%2,%3},[%4];"\
      : "=r"(R0),"=r"(R1),"=r"(R2),"=r"(R3) : "r"(ADDR))

__device__ __forceinline__ void cp16(uint32_t dst, const void* src){
  asm volatile("cp.async.cg.shared.global [%0], [%1], 16;" :: "r"(dst), "l"(src));
}
#define CPCOMMIT() asm volatile("cp.async.commit_group;")
#define CPWAIT0()  asm volatile("cp.async.wait_group 0;")

// ---------------- convert passes --------------------------------------------
__global__ void xcvt(const float* __restrict__ src, half_t* __restrict__ d, int n4)
{
  int i = blockIdx.x * blockDim.x + threadIdx.x;
  if (i >= n4) return;
  float4 v = ((const float4*)src)[i];
  __half2 h0 = { __float2half_rn(v.x), __float2half_rn(v.y) };
  __half2 h1 = { __float2half_rn(v.z), __float2half_rn(v.w) };
  ((__half2*)d)[2*i] = h0; ((__half2*)d)[2*i+1] = h1;
}

// One launch for all four weight transposes -> single fp16 [N][K]
__global__ void wsplit_all(const float* __restrict__ Wq,
                           const float* __restrict__ Wk,
                           const float* __restrict__ Wv,
                           const float* __restrict__ Wo,
                           half_t* __restrict__ wqkv, half_t* __restrict__ wo)
{
  const int z = blockIdx.z;
  const float* W; half_t* T; int K, N;
  if (z == 0){ W = Wq; T = wqkv;                       K = Dc;     N = Hc*HDc; }
  else if (z == 1){ W = Wk; T = wqkv + (size_t)2048*Dc; K = Dc;    N = HKVc*HDc; }
  else if (z == 2){ W = Wv; T = wqkv + (size_t)2560*Dc; K = Dc;    N = HKVc*HDc; }
  else            { W = Wo; T = wo;                     K = Hc*HDc; N = Dc; }
  if (blockIdx.x * 32 >= N) return;

  __shared__ float tile[32][33];
  int k0 = blockIdx.y*32, n0 = blockIdx.x*32;
  int tx = threadIdx.x, ty = threadIdx.y;
#pragma unroll
  for (int i = 0; i < 4; i++)
    tile[ty + 8*i][tx] = W[(size_t)(k0 + ty + 8*i) * N + n0 + tx];
  __syncthreads();
#pragma unroll
  for (int i = 0; i < 4; i++){
    int n = n0 + ty + 8*i;
    T[(size_t)n*K + k0 + tx] = __float2half_rn(tile[tx][ty + 8*i]);
  }
}

// ---------------- fused QKV GEMM + RMSNorm + RoPE + head-major fp16 ---------
#define GSTG1 32768
__global__ __launch_bounds__(256) void gemm_qkv(
    const half_t* __restrict__ A, const half_t* __restrict__ B,
    const float* __restrict__ qnw, const float* __restrict__ knw,
    half_t* __restrict__ qq, half_t* __restrict__ kk, half_t* __restrict__ vv)
{
  const int K = Dc;
  extern __shared__ char smraw[];
  const uint32_t smb = (uint32_t)__cvta_generic_to_shared(smraw);
  const int tid = threadIdx.x, lane = tid & 31, warp = tid >> 5;
  const int wm = (warp & 3) * 32, wn = (warp >> 2) * 64;
  const int g = lane >> 2, t = lane & 3;
  const int row0 = blockIdx.y * 128, col0 = blockIdx.x * 128;
  const int KI = K >> 6;

  const half_t* gsrc[2] = { A + (size_t)row0 * K, B + (size_t)col0 * K };

  auto stage = [&](int ki, int s){
#pragma unroll
    for (int q = 0; q < 2; q++)
#pragma unroll
      for (int it = 0; it < 4; it++){
        int fid = tid + it * 256;
        int row = fid >> 3, ch = fid & 7;
        cp16(smb + s*GSTG1 + q*16384 + row*128 + ((ch ^ (row & 7)) * 16),
             gsrc[q] + (size_t)row * K + ki*64 + ch*8);
      }
  };

  float c[2][8][4];
#pragma unroll
  for (int i=0;i<2;i++)
#pragma unroll
    for (int j=0;j<8;j++)
#pragma unroll
      for (int e=0;e<4;e++) c[i][j][e] = 0.f;

  stage(0, 0); CPCOMMIT();

  for (int ki = 0; ki < KI; ki++){
    int s = ki & 1;
    CPWAIT0();
    __syncthreads();
    if (ki + 1 < KI){ stage(ki + 1, s ^ 1); CPCOMMIT(); }

    const uint32_t ab = smb + s*GSTG1, bb = ab + 16384;
    const int rA  = (lane & 7) + ((lane >> 3) & 1) * 8;
    const int chA = (lane >> 4);
    const int rB  = (lane & 7) + ((lane >> 4) << 3);
    const int chB = (lane >> 3) & 1;
#pragma unroll
    for (int kc = 0; kc < 4; kc++){
      uint32_t ah[2][4];
#pragma unroll
      for (int mt = 0; mt < 2; mt++){
        int r = wm + mt*16 + rA;
        int ch = kc*2 + chA;
        uint32_t ad = ab + r*128 + ((ch ^ (r & 7)) * 16);
        LDSM4(ah[mt][0], ah[mt][1], ah[mt][2], ah[mt][3], ad);
      }
#pragma unroll
      for (int ntp = 0; ntp < 4; ntp++){
        int r = wn + ntp*16 + rB;
        int ch = kc*2 + chB;
        uint32_t ad = bb + r*128 + ((ch ^ (r & 7)) * 16);
        uint32_t b0,b1,b2,b3;
        LDSM4(b0,b1,b2,b3, ad);
#pragma unroll
        for (int mt = 0; mt < 2; mt++){
          MMAH(c[mt][2*ntp],   ah[mt], b0, b1);
          MMAH(c[mt][2*ntp+1], ah[mt], b2, b3);
        }
      }
    }
    __syncthreads();
  }

  // ---- fused epilogue: RMSNorm + RoPE + head-major fp16 ----
  const int gcol = col0 + wn;
  int mode, nh, head;
  const float* w = qnw;
  if (gcol < 2048)      { mode = 0; nh = Hc;   head = gcol >> 6; w = qnw; }
  else if (gcol < 2560) { mode = 1; nh = HKVc; head = (gcol - 2048) >> 6; w = knw; }
  else                  { mode = 2; nh = HKVc; head = (gcol - 2560) >> 6; }

  float invf[8];
  if (mode < 2){
#pragma unroll
    for (int nt = 0; nt < 4; nt++){
      int d0 = nt*8 + 2*t;
      invf[2*nt]   = powf(1000000.0f, -((float)(2*d0))     * (1.0f/64.0f));
      invf[2*nt+1] = powf(1000000.0f, -((float)(2*(d0+1))) * (1.0f/64.0f));
    }
  }

#pragma unroll
  for (int mt = 0; mt < 2; mt++){
    int r0 = row0 + wm + mt*16 + g;
    float rn0 = 0.f, rn1 = 0.f;
    if (mode < 2){
      float ss0 = 0.f, ss1 = 0.f;
#pragma unroll
      for (int nt = 0; nt < 8; nt++){
        ss0 += c[mt][nt][0]*c[mt][nt][0] + c[mt][nt][1]*c[mt][nt][1];
        ss1 += c[mt][nt][2]*c[mt][nt][2] + c[mt][nt][3]*c[mt][nt][3];
      }
      ss0 += __shfl_xor_sync(0xffffffffu, ss0, 1);
      ss0 += __shfl_xor_sync(0xffffffffu, ss0, 2);
      ss1 += __shfl_xor_sync(0xffffffffu, ss1, 1);
      ss1 += __shfl_xor_sync(0xffffffffu, ss1, 2);
      rn0 = rsqrtf(ss0 * (1.0f/64.0f) + 1e-5f);
      rn1 = rsqrtf(ss1 * (1.0f/64.0f) + 1e-5f);
    }

#pragma unroll
    for (int half2row = 0; half2row < 2; half2row++){
      int r = r0 + half2row*8;
      int e = half2row*2;
      float rn = half2row ? rn1 : rn0;
      int pos = r & (Lc-1);
      int b = r >> 11;
      size_t base = ((size_t)(b*nh + head)*Lc + pos) * HDc;

      if (mode == 2){
#pragma unroll
        for (int nt = 0; nt < 8; nt++){
          int d0 = nt*8 + 2*t;
          __half2 v2 = { __float2half_rn(c[mt][nt][e]), __float2half_rn(c[mt][nt][e+1]) };
          *(__half2*)(vv + base + d0) = v2;
        }
      } else {
        float fpos = (float)pos;
        half_t* dst = (mode == 0) ? qq : kk;
#pragma unroll
        for (int nt = 0; nt < 4; nt++){
          int d0 = nt*8 + 2*t;
          float x1a = c[mt][nt][e]   * rn * w[d0];
          float x1b = c[mt][nt][e+1] * rn * w[d0+1];
          float x2a = c[mt][nt+4][e]   * rn * w[d0+32];
          float x2b = c[mt][nt+4][e+1] * rn * w[d0+33];
          float anga = fpos * invf[2*nt],  angb = fpos * invf[2*nt+1];
          float ca = cosf(anga), sa = sinf(anga);
          float cb = cosf(angb), sb = sinf(angb);
          float y1a = x1a*ca - x2a*sa,  y1b = x1b*cb - x2b*sb;
          float y2a = x2a*ca + x1a*sa,  y2b = x2b*cb + x1b*sb;
          __half2 v1 = { __float2half_rn(y1a), __float2half_rn(y1b) };
          __half2 v2 = { __float2half_rn(y2a), __float2half_rn(y2b) };
          *(__half2*)(dst + base + d0)      = v1;
          *(__half2*)(dst + base + d0 + 32) = v2;
        }
      }
    }
  }
}

// ---------------- single fp16 tensor-core GEMM (Wo) -------------------------
__global__ __launch_bounds__(256) void gemm_fp16(
    const half_t* __restrict__ A, const half_t* __restrict__ B,
    float* __restrict__ C, int M, int N, int K)
{
  extern __shared__ char smraw[];
  const uint32_t smb = (uint32_t)__cvta_generic_to_shared(smraw);
  const int tid = threadIdx.x, lane = tid & 31, warp = tid >> 5;
  const int wm = (warp & 3) * 32, wn = (warp >> 2) * 64;
  const int g = lane >> 2, t = lane & 3;
  const int row0 = blockIdx.y * 128, col0 = blockIdx.x * 128;
  const int KI = K >> 6;

  const half_t* gsrc[2] = { A + (size_t)row0 * K, B + (size_t)col0 * K };

  auto stage = [&](int ki, int s){
#pragma unroll
    for (int q = 0; q < 2; q++)
#pragma unroll
      for (int it = 0; it < 4; it++){
        int fid = tid + it * 256;
        int row = fid >> 3, ch = fid & 7;
        cp16(smb + s*GSTG1 + q*16384 + row*128 + ((ch ^ (row & 7)) * 16),
             gsrc[q] + (size_t)row * K + ki*64 + ch*8);
      }
  };

  float c[2][8][4];
#pragma unroll
  for (int i=0;i<2;i++)
#pragma unroll
    for (int j=0;j<8;j++)
#pragma unroll
      for (int e=0;e<4;e++) c[i][j][e] = 0.f;

  stage(0, 0); CPCOMMIT();

  for (int ki = 0; ki < KI; ki++){
    int s = ki & 1;
    CPWAIT0();
    __syncthreads();
    if (ki + 1 < KI){ stage(ki + 1, s ^ 1); CPCOMMIT(); }

    const uint32_t ab = smb + s*GSTG1, bb = ab + 16384;
    const int rA  = (lane & 7) + ((lane >> 3) & 1) * 8;
    const int chA = (lane >> 4);
    const int rB  = (lane & 7) + ((lane >> 4) << 3);
    const int chB = (lane >> 3) & 1;
#pragma unroll
    for (int kc = 0; kc < 4; kc++){
      uint32_t ah[2][4];
#pragma unroll
      for (int mt = 0; mt < 2; mt++){
        int r = wm + mt*16 + rA;
        int ch = kc*2 + chA;
        uint32_t ad = ab + r*128 + ((ch ^ (r & 7)) * 16);
        LDSM4(ah[mt][0], ah[mt][1], ah[mt][2], ah[mt][3], ad);
      }
#pragma unroll
      for (int ntp = 0; ntp < 4; ntp++){
        int r = wn + ntp*16 + rB;
        int ch = kc*2 + chB;
        uint32_t ad = bb + r*128 + ((ch ^ (r & 7)) * 16);
        uint32_t b0,b1,b2,b3;
        LDSM4(b0,b1,b2,b3, ad);
#pragma unroll
        for (int mt = 0; mt < 2; mt++){
          MMAH(c[mt][2*ntp],   ah[mt], b0, b1);
          MMAH(c[mt][2*ntp+1], ah[mt], b2, b3);
        }
      }
    }
    __syncthreads();
  }

#pragma unroll
  for (int mt = 0; mt < 2; mt++)
#pragma unroll
    for (int nt = 0; nt < 8; nt++){
      int r = row0 + wm + mt*16 + g;
      int cc = col0 + wn + nt*8 + 2*t;
      float2 v0 = { c[mt][nt][0], c[mt][nt][1] };
      float2 v1 = { c[mt][nt][2], c[mt][nt][3] };
      *(float2*)(C + (size_t)r * N + cc) = v0;
      *(float2*)(C + (size_t)(r + 8) * N + cc) = v1;
    }
}

// ---------------- tensor-core flash attention (all single fp16) -------------
// smem: Q 8K | 2 stages x (K 8K | V 8K) = 40K total. 4 CTAs/SM target.
#define FSM_KV  8192
#define KV_STG  16384
#define FLASH_SMEM (8192 + 2*KV_STG)

__global__ __launch_bounds__(128, 4) void flash_tc(
    const half_t* __restrict__ Qp, const half_t* __restrict__ Kp,
    const half_t* __restrict__ Vp, half_t* __restrict__ O)
{
  extern __shared__ char smraw[];
  const uint32_t smb = (uint32_t)__cvta_generic_to_shared(smraw);
  const int tid = threadIdx.x, lane = tid & 31, warp = tid >> 5;
  const int qt = gridDim.x - 1 - blockIdx.x;   // big tiles first
  const int h = blockIdx.y, b = blockIdx.z, hkv = h >> 2;
  const int g = lane >> 2, t = lane & 3;

  const half_t* qp = Qp + ((size_t)(b*Hc + h)*Lc + qt*64) * HDc;
  const size_t kvoff = (size_t)(b*HKVc + hkv) * Lc * HDc;
  const half_t* kvsrc[2] = { Kp + kvoff, Vp + kvoff };

  // stage Q (once): 64 rows x 64 cols fp16
#pragma unroll
  for (int it = 0; it < 4; it++){
    int fid = tid + it * 128;
    int row = fid >> 3, ch = fid & 7;
    uint4 v4 = *(const uint4*)(qp + row*64 + ch*8);
    *(uint4*)(smraw + row*128 + ((ch ^ (row & 7)) * 16)) = v4;
  }

  auto stageKV = [&](int j, int s){
#pragma unroll
    for (int q = 0; q < 2; q++)
#pragma unroll
      for (int it = 0; it < 4; it++){
        int fid = tid + it * 128;
        int row = fid >> 3, ch = fid & 7;
        cp16(smb + FSM_KV + s*KV_STG + q*8192 + row*128 + ((ch ^ (row & 7))*16),
             kvsrc[q] + (size_t)(j*64 + row)*64 + ch*8);
      }
  };

  stageKV(0, 0); CPCOMMIT();
  __syncthreads();

  // Q fragments (persistent, single fp16)
  uint32_t qf[4][4];
  {
    int r = warp*16 + (lane & 7) + ((lane >> 3) & 1) * 8;
#pragma unroll
    for (int kc = 0; kc < 4; kc++){
      int ch = kc*2 + (lane >> 4);
      uint32_t ad = smb + r*128 + ((ch ^ (r & 7)) * 16);
      LDSM4(qf[kc][0], qf[kc][1], qf[kc][2], qf[kc][3], ad);
    }
  }

  float o[8][4];
#pragma unroll
  for (int nt=0;nt<8;nt++)
#pragma unroll
    for (int e=0;e<4;e++) o[nt][e] = 0.f;
  float m0r = -1e30f, m1r = -1e30f, l0 = 0.f, l1 = 0.f;

  const int r0g = qt*64 + warp*16 + g;
  const int r1g = r0g + 8;
  const int rBv = (lane & 7) + ((lane >> 4) << 3);
  const int chBv = (lane >> 3) & 1;
  const int rVv = (lane & 7) + (((lane >> 3) & 1) << 3);
  const int chVv = lane >> 4;

  for (int j = 0; j <= qt; j++){
    int s = j & 1;
    CPWAIT0();
    __syncthreads();
    if (j < qt){ stageKV(j + 1, s ^ 1); CPCOMMIT(); }

    const uint32_t kb = smb + FSM_KV + s*KV_STG;

    float sf[8][4];
#pragma unroll
    for (int nt=0;nt<8;nt++)
#pragma unroll
      for (int e=0;e<4;e++) sf[nt][e] = 0.f;

    // S = Q K^T : single fp16 both sides
#pragma unroll
    for (int kc = 0; kc < 4; kc++){
#pragma unroll
      for (int ntp = 0; ntp < 4; ntp++){
        int r = ntp*16 + rBv;
        int ch = kc*2 + chBv;
        uint32_t ad = kb + r*128 + ((ch ^ (r & 7)) * 16);
        uint32_t b0,b1,b2,b3;
        LDSM4(b0,b1,b2,b3, ad);
        MMAH(sf[2*ntp],   qf[kc], b0, b1);
        MMAH(sf[2*ntp+1], qf[kc], b2, b3);
      }
    }

    float tm0 = -1e30f, tm1 = -1e30f;
    const bool mayMask = (j == qt);
#pragma unroll
    for (int nt = 0; nt < 8; nt++){
      int c0 = j*64 + nt*8 + 2*t;
      float v0 = sf[nt][0]*0.125f, v1 = sf[nt][1]*0.125f;
      float v2 = sf[nt][2]*0.125f, v3 = sf[nt][3]*0.125f;
      if (mayMask){
        if (c0     > r0g) v0 = -1e30f;
        if (c0 + 1 > r0g) v1 = -1e30f;
        if (c0     > r1g) v2 = -1e30f;
        if (c0 + 1 > r1g) v3 = -1e30f;
      }
      sf[nt][0]=v0; sf[nt][1]=v1; sf[nt][2]=v2; sf[nt][3]=v3;
      tm0 = fmaxf(tm0, fmaxf(v0, v1));
      tm1 = fmaxf(tm1, fmaxf(v2, v3));
    }
    tm0 = fmaxf(tm0, __shfl_xor_sync(0xffffffffu, tm0, 1));
    tm0 = fmaxf(tm0, __shfl_xor_sync(0xffffffffu, tm0, 2));
    tm1 = fmaxf(tm1, __shfl_xor_sync(0xffffffffu, tm1, 1));
    tm1 = fmaxf(tm1, __shfl_xor_sync(0xffffffffu, tm1, 2));

    float mn0 = fmaxf(m0r, tm0), mn1 = fmaxf(m1r, tm1);
    float corr0 = __expf(m0r - mn0), corr1 = __expf(m1r - mn1);
    float s0 = 0.f, s1 = 0.f;
#pragma unroll
    for (int nt = 0; nt < 8; nt++){
      sf[nt][0] = __expf(sf[nt][0] - mn0);
      sf[nt][1] = __expf(sf[nt][1] - mn0);
      sf[nt][2] = __expf(sf[nt][2] - mn1);
      sf[nt][3] = __expf(sf[nt][3] - mn1);
      s0 += sf[nt][0] + sf[nt][1];
      s1 += sf[nt][2] + sf[nt][3];
    }
    s0 += __shfl_xor_sync(0xffffffffu, s0, 1);
    s0 += __shfl_xor_sync(0xffffffffu, s0, 2);
    s1 += __shfl_xor_sync(0xffffffffu, s1, 1);
    s1 += __shfl_xor_sync(0xffffffffu, s1, 2);
    l0 = l0*corr0 + s0;  l1 = l1*corr1 + s1;
    m0r = mn0;  m1r = mn1;
#pragma unroll
    for (int nt = 0; nt < 8; nt++){
      o[nt][0] *= corr0; o[nt][1] *= corr0;
      o[nt][2] *= corr1; o[nt][3] *= corr1;
    }

    // O += P V : P single fp16, V single fp16
    const uint32_t vb = kb + 8192;
#pragma unroll
    for (int kc = 0; kc < 4; kc++){
      uint32_t ph[4];
#pragma unroll
      for (int q2 = 0; q2 < 2; q2++){
        __half2 p01 = { __float2half_rn(sf[2*kc+q2][0]), __float2half_rn(sf[2*kc+q2][1]) };
        __half2 p23 = { __float2half_rn(sf[2*kc+q2][2]), __float2half_rn(sf[2*kc+q2][3]) };
        ph[2*q2 + 0] = *(uint32_t*)&p01;
        ph[2*q2 + 1] = *(uint32_t*)&p23;
      }
#pragma unroll
      for (int ntp = 0; ntp < 4; ntp++){
        int r = kc*16 + rVv;
        int ch = ntp*2 + chVv;
        uint32_t ad = vb + r*128 + ((ch ^ (r & 7)) * 16);
        uint32_t w0,w1,w2,w3;
        LDSM4T(w0,w1,w2,w3, ad);
        MMAH(o[2*ntp],   ph, w0, w1);
        MMAH(o[2*ntp+1], ph, w2, w3);
      }
    }
  }

  // epilogue: normalize, write single fp16 attn [b][l][h][d]
  float inv0 = 1.f / l0, inv1 = 1.f / l1;
  size_t ob0 = ((size_t)(b*Lc + qt*64 + warp*16 + g) * Hc + h) * HDc;
  size_t ob1 = ob0 + (size_t)8 * Hc * HDc;
#pragma unroll
  for (int nt = 0; nt < 8; nt++){
    int d = nt*8 + 2*t;
    __half2 a = { __float2half_rn(o[nt][0]*inv0), __float2half_rn(o[nt][1]*inv0) };
    __half2 c = { __float2half_rn(o[nt][2]*inv1), __float2half_rn(o[nt][3]*inv1) };
    *(__half2*)(O + ob0 + d) = a;
    *(__half2*)(O + ob1 + d) = c;
  }
}

// ---------------------------------------------------------------------------
extern "C" void kernel_launch(void* const* d_in, const int* in_sizes, int n_in,
                              void* d_out, int out_size)
{
  const float* x   = (const float*)d_in[0];
  const float* Wq  = (const float*)d_in[1];
  const float* Wk  = (const float*)d_in[2];
  const float* Wv  = (const float*)d_in[3];
  const float* Wo  = (const float*)d_in[4];
  const float* qnw = (const float*)d_in[5];
  const float* knw = (const float*)d_in[6];
  float* out = (float*)d_out;

  half_t *x16,*wqkv,*wo,*at,*qq,*kk,*vv;
  cudaGetSymbolAddress((void**)&x16, g_x16);
  cudaGetSymbolAddress((void**)&wqkv, g_wqkvT);
  cudaGetSymbolAddress((void**)&wo, g_woT);
  cudaGetSymbolAddress((void**)&qq, g_q);
  cudaGetSymbolAddress((void**)&kk, g_k);  cudaGetSymbolAddress((void**)&vv, g_v);
  cudaGetSymbolAddress((void**)&at, g_at);

  const int M = Mtok;

  // (1) activation convert
  xcvt<<<(M*Dc/4 + 255)/256, 256>>>(x, x16, M*Dc/4);
  // (2) all weight transposes in one launch
  wsplit_all<<<dim3(64, 64, 4), dim3(32,8)>>>(Wq, Wk, Wv, Wo, wqkv, wo);

  // (3) fused QKV projection + RMSNorm + RoPE -> head-major fp16
  cudaFuncSetAttribute(gemm_qkv, cudaFuncAttributeMaxDynamicSharedMemorySize, 2*GSTG1);
  gemm_qkv<<<dim3(QKVN/128, M/128), 256, 2*GSTG1>>>(x16, wqkv, qnw, knw, qq, kk, vv);

  // (4) flash attention
  cudaFuncSetAttribute(flash_tc, cudaFuncAttributeMaxDynamicSharedMemorySize, FLASH_SMEM);
  flash_tc<<<dim3(Lc/64, Hc, Bc), 128, FLASH_SMEM>>>(qq, kk, vv, at);

  // (5) output projection
  cudaFuncSetAttribute(gemm_fp16, cudaFuncAttributeMaxDynamicSharedMemorySize, 2*GSTG1);
  gemm_fp16<<<dim3(Dc/128, M/128), 256, 2*GSTG1>>>(at, wo, out, M, Dc, Dc);
}

// round 11
// speedup vs baseline: 2.6174x; 1.0112x over previous
#include <cuda_runtime.h>
#include <cuda_fp16.h>
#include <math.h>
#include <stdint.h>
#include <stddef.h>

#define Bc 2
#define Lc 2048
#define Dc 2048
#define Hc 32
#define HKVc 8
#define HDc 64
#define Mtok (Bc*Lc)
#define QKVN 3072          // fused projection width: 2048 Q | 512 K | 512 V
#define QSCALE 0.18033688011112042f   // 0.125 * log2(e): S in log2 domain

typedef __half half_t;

// ---------------- scratch (__device__ globals; no allocs allowed) -----------
__device__ __align__(16) half_t g_x16[(size_t)Mtok*Dc];     // x single fp16
__device__ __align__(16) half_t g_wqkvT[(size_t)QKVN*Dc];   // single fp16
__device__ __align__(16) half_t g_woT[(size_t)Dc*Hc*HDc];   // single fp16
__device__ __align__(16) half_t g_q[(size_t)Bc*Hc*Lc*HDc];  // Q*QSCALE fp16
__device__ __align__(16) half_t g_k[(size_t)Bc*HKVc*Lc*HDc];// K single fp16
__device__ __align__(16) half_t g_v[(size_t)Bc*HKVc*Lc*HDc];// V single fp16
__device__ __align__(16) half_t g_at[(size_t)Mtok*Hc*HDc];  // attn single fp16

// ---------------- PTX helpers ----------------------------------------------
#define MMAH(CR, A, B0, B1)                                                  \
  asm volatile(                                                              \
      "mma.sync.aligned.m16n8k16.row.col.f32.f16.f16.f32 "                   \
      "{%0,%1,%2,%3},{%4,%5,%6,%7},{%8,%9},{%0,%1,%2,%3};"                   \
      : "+f"((CR)[0]), "+f"((CR)[1]), "+f"((CR)[2]), "+f"((CR)[3])           \
      : "r"((A)[0]), "r"((A)[1]), "r"((A)[2]), "r"((A)[3]), "r"(B0), "r"(B1))

#define LDSM4(R0,R1,R2,R3,ADDR)                                              \
  asm volatile("ldmatrix.sync.aligned.m8n8.x4.shared.b16 {%0,%1,%2,%3},[%4];"\
      : "=r"(R0),"=r"(R1),"=r"(R2),"=r"(R3) : "r"(ADDR))

#define LDSM4T(R0,R1,R2,R3,ADDR)                                             \
  asm volatile("ldmatrix.sync.aligned.m8n8.x4.trans.shared.b16 {%0,%1,%2,%3},[%4];"\
      : "=r"(R0),"=r"(R1),"=r"(R2),"=r"(R3) : "r"(ADDR))

__device__ __forceinline__ void cp16(uint32_t dst, const void* src){
  asm volatile("cp.async.cg.shared.global [%0], [%1], 16;" :: "r"(dst), "l"(src));
}
#define CPCOMMIT() asm volatile("cp.async.commit_group;")
#define CPWAIT0()  asm volatile("cp.async.wait_group 0;")

// ---------------- convert passes --------------------------------------------
__global__ void xcvt(const float* __restrict__ src, half_t* __restrict__ d, int n4)
{
  int i = blockIdx.x * blockDim.x + threadIdx.x;
  if (i >= n4) return;
  float4 v = ((const float4*)src)[i];
  __half2 h0 = { __float2half_rn(v.x), __float2half_rn(v.y) };
  __half2 h1 = { __float2half_rn(v.z), __float2half_rn(v.w) };
  ((__half2*)d)[2*i] = h0; ((__half2*)d)[2*i+1] = h1;
}

// One launch for all four weight transposes -> single fp16 [N][K]
__global__ void wsplit_all(const float* __restrict__ Wq,
                           const float* __restrict__ Wk,
                           const float* __restrict__ Wv,
                           const float* __restrict__ Wo,
                           half_t* __restrict__ wqkv, half_t* __restrict__ wo)
{
  const int z = blockIdx.z;
  const float* W; half_t* T; int K, N;
  if (z == 0){ W = Wq; T = wqkv;                       K = Dc;     N = Hc*HDc; }
  else if (z == 1){ W = Wk; T = wqkv + (size_t)2048*Dc; K = Dc;    N = HKVc*HDc; }
  else if (z == 2){ W = Wv; T = wqkv + (size_t)2560*Dc; K = Dc;    N = HKVc*HDc; }
  else            { W = Wo; T = wo;                     K = Hc*HDc; N = Dc; }
  if (blockIdx.x * 32 >= N) return;

  __shared__ float tile[32][33];
  int k0 = blockIdx.y*32, n0 = blockIdx.x*32;
  int tx = threadIdx.x, ty = threadIdx.y;
#pragma unroll
  for (int i = 0; i < 4; i++)
    tile[ty + 8*i][tx] = W[(size_t)(k0 + ty + 8*i) * N + n0 + tx];
  __syncthreads();
#pragma unroll
  for (int i = 0; i < 4; i++){
    int n = n0 + ty + 8*i;
    T[(size_t)n*K + k0 + tx] = __float2half_rn(tile[tx][ty + 8*i]);
  }
}

// ---------------- fused QKV GEMM + RMSNorm + RoPE + head-major fp16 ---------
#define GSTG1 32768
__global__ __launch_bounds__(256) void gemm_qkv(
    const half_t* __restrict__ A, const half_t* __restrict__ B,
    const float* __restrict__ qnw, const float* __restrict__ knw,
    half_t* __restrict__ qq, half_t* __restrict__ kk, half_t* __restrict__ vv)
{
  const int K = Dc;
  extern __shared__ char smraw[];
  const uint32_t smb = (uint32_t)__cvta_generic_to_shared(smraw);
  const int tid = threadIdx.x, lane = tid & 31, warp = tid >> 5;
  const int wm = (warp & 3) * 32, wn = (warp >> 2) * 64;
  const int g = lane >> 2, t = lane & 3;
  const int row0 = blockIdx.y * 128, col0 = blockIdx.x * 128;
  const int KI = K >> 6;

  const half_t* gsrc[2] = { A + (size_t)row0 * K, B + (size_t)col0 * K };

  auto stage = [&](int ki, int s){
#pragma unroll
    for (int q = 0; q < 2; q++)
#pragma unroll
      for (int it = 0; it < 4; it++){
        int fid = tid + it * 256;
        int row = fid >> 3, ch = fid & 7;
        cp16(smb + s*GSTG1 + q*16384 + row*128 + ((ch ^ (row & 7)) * 16),
             gsrc[q] + (size_t)row * K + ki*64 + ch*8);
      }
  };

  float c[2][8][4];
#pragma unroll
  for (int i=0;i<2;i++)
#pragma unroll
    for (int j=0;j<8;j++)
#pragma unroll
      for (int e=0;e<4;e++) c[i][j][e] = 0.f;

  stage(0, 0); CPCOMMIT();

  for (int ki = 0; ki < KI; ki++){
    int s = ki & 1;
    CPWAIT0();
    __syncthreads();
    if (ki + 1 < KI){ stage(ki + 1, s ^ 1); CPCOMMIT(); }

    const uint32_t ab = smb + s*GSTG1, bb = ab + 16384;
    const int rA  = (lane & 7) + ((lane >> 3) & 1) * 8;
    const int chA = (lane >> 4);
    const int rB  = (lane & 7) + ((lane >> 4) << 3);
    const int chB = (lane >> 3) & 1;
#pragma unroll
    for (int kc = 0; kc < 4; kc++){
      uint32_t ah[2][4];
#pragma unroll
      for (int mt = 0; mt < 2; mt++){
        int r = wm + mt*16 + rA;
        int ch = kc*2 + chA;
        uint32_t ad = ab + r*128 + ((ch ^ (r & 7)) * 16);
        LDSM4(ah[mt][0], ah[mt][1], ah[mt][2], ah[mt][3], ad);
      }
#pragma unroll
      for (int ntp = 0; ntp < 4; ntp++){
        int r = wn + ntp*16 + rB;
        int ch = kc*2 + chB;
        uint32_t ad = bb + r*128 + ((ch ^ (r & 7)) * 16);
        uint32_t b0,b1,b2,b3;
        LDSM4(b0,b1,b2,b3, ad);
#pragma unroll
        for (int mt = 0; mt < 2; mt++){
          MMAH(c[mt][2*ntp],   ah[mt], b0, b1);
          MMAH(c[mt][2*ntp+1], ah[mt], b2, b3);
        }
      }
    }
    __syncthreads();
  }

  // ---- fused epilogue: RMSNorm + RoPE + head-major fp16 ----
  const int gcol = col0 + wn;
  int mode, nh, head;
  const float* w = qnw;
  if (gcol < 2048)      { mode = 0; nh = Hc;   head = gcol >> 6; w = qnw; }
  else if (gcol < 2560) { mode = 1; nh = HKVc; head = (gcol - 2048) >> 6; w = knw; }
  else                  { mode = 2; nh = HKVc; head = (gcol - 2560) >> 6; }

  float invf[8];
  if (mode < 2){
#pragma unroll
    for (int nt = 0; nt < 4; nt++){
      int d0 = nt*8 + 2*t;
      invf[2*nt]   = powf(1000000.0f, -((float)(2*d0))     * (1.0f/64.0f));
      invf[2*nt+1] = powf(1000000.0f, -((float)(2*(d0+1))) * (1.0f/64.0f));
    }
  }
  const float oscale = (mode == 0) ? QSCALE : 1.0f;

#pragma unroll
  for (int mt = 0; mt < 2; mt++){
    int r0 = row0 + wm + mt*16 + g;
    float rn0 = 0.f, rn1 = 0.f;
    if (mode < 2){
      float ss0 = 0.f, ss1 = 0.f;
#pragma unroll
      for (int nt = 0; nt < 8; nt++){
        ss0 += c[mt][nt][0]*c[mt][nt][0] + c[mt][nt][1]*c[mt][nt][1];
        ss1 += c[mt][nt][2]*c[mt][nt][2] + c[mt][nt][3]*c[mt][nt][3];
      }
      ss0 += __shfl_xor_sync(0xffffffffu, ss0, 1);
      ss0 += __shfl_xor_sync(0xffffffffu, ss0, 2);
      ss1 += __shfl_xor_sync(0xffffffffu, ss1, 1);
      ss1 += __shfl_xor_sync(0xffffffffu, ss1, 2);
      rn0 = rsqrtf(ss0 * (1.0f/64.0f) + 1e-5f);
      rn1 = rsqrtf(ss1 * (1.0f/64.0f) + 1e-5f);
    }

#pragma unroll
    for (int half2row = 0; half2row < 2; half2row++){
      int r = r0 + half2row*8;
      int e = half2row*2;
      float rn = half2row ? rn1 : rn0;
      int pos = r & (Lc-1);
      int b = r >> 11;
      size_t base = ((size_t)(b*nh + head)*Lc + pos) * HDc;

      if (mode == 2){
#pragma unroll
        for (int nt = 0; nt < 8; nt++){
          int d0 = nt*8 + 2*t;
          __half2 v2 = { __float2half_rn(c[mt][nt][e]), __float2half_rn(c[mt][nt][e+1]) };
          *(__half2*)(vv + base + d0) = v2;
        }
      } else {
        float fpos = (float)pos;
        half_t* dst = (mode == 0) ? qq : kk;
#pragma unroll
        for (int nt = 0; nt < 4; nt++){
          int d0 = nt*8 + 2*t;
          float x1a = c[mt][nt][e]   * rn * w[d0];
          float x1b = c[mt][nt][e+1] * rn * w[d0+1];
          float x2a = c[mt][nt+4][e]   * rn * w[d0+32];
          float x2b = c[mt][nt+4][e+1] * rn * w[d0+33];
          float anga = fpos * invf[2*nt],  angb = fpos * invf[2*nt+1];
          float ca = cosf(anga), sa = sinf(anga);
          float cb = cosf(angb), sb = sinf(angb);
          float y1a = (x1a*ca - x2a*sa) * oscale,  y1b = (x1b*cb - x2b*sb) * oscale;
          float y2a = (x2a*ca + x1a*sa) * oscale,  y2b = (x2b*cb + x1b*sb) * oscale;
          __half2 v1 = { __float2half_rn(y1a), __float2half_rn(y1b) };
          __half2 v2 = { __float2half_rn(y2a), __float2half_rn(y2b) };
          *(__half2*)(dst + base + d0)      = v1;
          *(__half2*)(dst + base + d0 + 32) = v2;
        }
      }
    }
  }
}

// ---------------- single fp16 tensor-core GEMM (Wo) -------------------------
__global__ __launch_bounds__(256) void gemm_fp16(
    const half_t* __restrict__ A, const half_t* __restrict__ B,
    float* __restrict__ C, int M, int N, int K)
{
  extern __shared__ char smraw[];
  const uint32_t smb = (uint32_t)__cvta_generic_to_shared(smraw);
  const int tid = threadIdx.x, lane = tid & 31, warp = tid >> 5;
  const int wm = (warp & 3) * 32, wn = (warp >> 2) * 64;
  const int g = lane >> 2, t = lane & 3;
  const int row0 = blockIdx.y * 128, col0 = blockIdx.x * 128;
  const int KI = K >> 6;

  const half_t* gsrc[2] = { A + (size_t)row0 * K, B + (size_t)col0 * K };

  auto stage = [&](int ki, int s){
#pragma unroll
    for (int q = 0; q < 2; q++)
#pragma unroll
      for (int it = 0; it < 4; it++){
        int fid = tid + it * 256;
        int row = fid >> 3, ch = fid & 7;
        cp16(smb + s*GSTG1 + q*16384 + row*128 + ((ch ^ (row & 7)) * 16),
             gsrc[q] + (size_t)row * K + ki*64 + ch*8);
      }
  };

  float c[2][8][4];
#pragma unroll
  for (int i=0;i<2;i++)
#pragma unroll
    for (int j=0;j<8;j++)
#pragma unroll
      for (int e=0;e<4;e++) c[i][j][e] = 0.f;

  stage(0, 0); CPCOMMIT();

  for (int ki = 0; ki < KI; ki++){
    int s = ki & 1;
    CPWAIT0();
    __syncthreads();
    if (ki + 1 < KI){ stage(ki + 1, s ^ 1); CPCOMMIT(); }

    const uint32_t ab = smb + s*GSTG1, bb = ab + 16384;
    const int rA  = (lane & 7) + ((lane >> 3) & 1) * 8;
    const int chA = (lane >> 4);
    const int rB  = (lane & 7) + ((lane >> 4) << 3);
    const int chB = (lane >> 3) & 1;
#pragma unroll
    for (int kc = 0; kc < 4; kc++){
      uint32_t ah[2][4];
#pragma unroll
      for (int mt = 0; mt < 2; mt++){
        int r = wm + mt*16 + rA;
        int ch = kc*2 + chA;
        uint32_t ad = ab + r*128 + ((ch ^ (r & 7)) * 16);
        LDSM4(ah[mt][0], ah[mt][1], ah[mt][2], ah[mt][3], ad);
      }
#pragma unroll
      for (int ntp = 0; ntp < 4; ntp++){
        int r = wn + ntp*16 + rB;
        int ch = kc*2 + chB;
        uint32_t ad = bb + r*128 + ((ch ^ (r & 7)) * 16);
        uint32_t b0,b1,b2,b3;
        LDSM4(b0,b1,b2,b3, ad);
#pragma unroll
        for (int mt = 0; mt < 2; mt++){
          MMAH(c[mt][2*ntp],   ah[mt], b0, b1);
          MMAH(c[mt][2*ntp+1], ah[mt], b2, b3);
        }
      }
    }
    __syncthreads();
  }

#pragma unroll
  for (int mt = 0; mt < 2; mt++)
#pragma unroll
    for (int nt = 0; nt < 8; nt++){
      int r = row0 + wm + mt*16 + g;
      int cc = col0 + wn + nt*8 + 2*t;
      float2 v0 = { c[mt][nt][0], c[mt][nt][1] };
      float2 v1 = { c[mt][nt][2], c[mt][nt][3] };
      *(float2*)(C + (size_t)r * N + cc) = v0;
      *(float2*)(C + (size_t)(r + 8) * N + cc) = v1;
    }
}

// ---------------- tensor-core flash attention (fp16, log2-domain softmax) ---
// smem: Q 8K | 2 stages x (K 8K | V 8K) = 40K total. 4 CTAs/SM target.
#define FSM_KV  8192
#define KV_STG  16384
#define FLASH_SMEM (8192 + 2*KV_STG)

__global__ __launch_bounds__(128, 4) void flash_tc(
    const half_t* __restrict__ Qp, const half_t* __restrict__ Kp,
    const half_t* __restrict__ Vp, half_t* __restrict__ O)
{
  extern __shared__ char smraw[];
  const uint32_t smb = (uint32_t)__cvta_generic_to_shared(smraw);
  const int tid = threadIdx.x, lane = tid & 31, warp = tid >> 5;
  const int qt = gridDim.x - 1 - blockIdx.x;   // big tiles first
  const int h = blockIdx.y, b = blockIdx.z, hkv = h >> 2;
  const int g = lane >> 2, t = lane & 3;

  const half_t* qp = Qp + ((size_t)(b*Hc + h)*Lc + qt*64) * HDc;
  const size_t kvoff = (size_t)(b*HKVc + hkv) * Lc * HDc;
  const half_t* kvsrc[2] = { Kp + kvoff, Vp + kvoff };

  // stage Q (once): 64 rows x 64 cols fp16 (already * 0.125*log2e)
#pragma unroll
  for (int it = 0; it < 4; it++){
    int fid = tid + it * 128;
    int row = fid >> 3, ch = fid & 7;
    uint4 v4 = *(const uint4*)(qp + row*64 + ch*8);
    *(uint4*)(smraw + row*128 + ((ch ^ (row & 7)) * 16)) = v4;
  }

  auto stageKV = [&](int j, int s){
#pragma unroll
    for (int q = 0; q < 2; q++)
#pragma unroll
      for (int it = 0; it < 4; it++){
        int fid = tid + it * 128;
        int row = fid >> 3, ch = fid & 7;
        cp16(smb + FSM_KV + s*KV_STG + q*8192 + row*128 + ((ch ^ (row & 7))*16),
             kvsrc[q] + (size_t)(j*64 + row)*64 + ch*8);
      }
  };

  stageKV(0, 0); CPCOMMIT();
  __syncthreads();

  // Q fragments (persistent)
  uint32_t qf[4][4];
  {
    int r = warp*16 + (lane & 7) + ((lane >> 3) & 1) * 8;
#pragma unroll
    for (int kc = 0; kc < 4; kc++){
      int ch = kc*2 + (lane >> 4);
      uint32_t ad = smb + r*128 + ((ch ^ (r & 7)) * 16);
      LDSM4(qf[kc][0], qf[kc][1], qf[kc][2], qf[kc][3], ad);
    }
  }

  float o[8][4];
#pragma unroll
  for (int nt=0;nt<8;nt++)
#pragma unroll
    for (int e=0;e<4;e++) o[nt][e] = 0.f;
  float m0r = -1e30f, m1r = -1e30f, l0 = 0.f, l1 = 0.f;

  const int r0g = qt*64 + warp*16 + g;
  const int r1g = r0g + 8;
  const int rBv = (lane & 7) + ((lane >> 4) << 3);
  const int chBv = (lane >> 3) & 1;
  const int rVv = (lane & 7) + (((lane >> 3) & 1) << 3);
  const int chVv = lane >> 4;

  for (int j = 0; j <= qt; j++){
    int s = j & 1;
    CPWAIT0();
    __syncthreads();
    if (j < qt){ stageKV(j + 1, s ^ 1); CPCOMMIT(); }

    const uint32_t kb = smb + FSM_KV + s*KV_STG;

    float sf[8][4];
#pragma unroll
    for (int nt=0;nt<8;nt++)
#pragma unroll
      for (int e=0;e<4;e++) sf[nt][e] = 0.f;

    // S = Q K^T (log2 domain — Q pre-scaled by 0.125*log2e)
#pragma unroll
    for (int kc = 0; kc < 4; kc++){
#pragma unroll
      for (int ntp = 0; ntp < 4; ntp++){
        int r = ntp*16 + rBv;
        int ch = kc*2 + chBv;
        uint32_t ad = kb + r*128 + ((ch ^ (r & 7)) * 16);
        uint32_t b0,b1,b2,b3;
        LDSM4(b0,b1,b2,b3, ad);
        MMAH(sf[2*ntp],   qf[kc], b0, b1);
        MMAH(sf[2*ntp+1], qf[kc], b2, b3);
      }
    }

    // causal mask + row max (no scaling needed)
    float tm0 = -1e30f, tm1 = -1e30f;
    if (j == qt){
#pragma unroll
      for (int nt = 0; nt < 8; nt++){
        int c0 = j*64 + nt*8 + 2*t;
        if (c0     > r0g) sf[nt][0] = -1e30f;
        if (c0 + 1 > r0g) sf[nt][1] = -1e30f;
        if (c0     > r1g) sf[nt][2] = -1e30f;
        if (c0 + 1 > r1g) sf[nt][3] = -1e30f;
      }
    }
#pragma unroll
    for (int nt = 0; nt < 8; nt++){
      tm0 = fmaxf(tm0, fmaxf(sf[nt][0], sf[nt][1]));
      tm1 = fmaxf(tm1, fmaxf(sf[nt][2], sf[nt][3]));
    }
    tm0 = fmaxf(tm0, __shfl_xor_sync(0xffffffffu, tm0, 1));
    tm0 = fmaxf(tm0, __shfl_xor_sync(0xffffffffu, tm0, 2));
    tm1 = fmaxf(tm1, __shfl_xor_sync(0xffffffffu, tm1, 1));
    tm1 = fmaxf(tm1, __shfl_xor_sync(0xffffffffu, tm1, 2));

    float mn0 = fmaxf(m0r, tm0), mn1 = fmaxf(m1r, tm1);
    float corr0 = exp2f(m0r - mn0), corr1 = exp2f(m1r - mn1);

    // P = 2^(s - mn) computed in fp16x2 — output IS the packed A-fragment
    uint32_t pf[16];
    float s0 = 0.f, s1 = 0.f;
#pragma unroll
    for (int nt = 0; nt < 8; nt++){
      __half2 e0 = h2exp2(__floats2half2_rn(sf[nt][0]-mn0, sf[nt][1]-mn0));
      __half2 e1 = h2exp2(__floats2half2_rn(sf[nt][2]-mn1, sf[nt][3]-mn1));
      pf[2*nt]   = *(uint32_t*)&e0;
      pf[2*nt+1] = *(uint32_t*)&e1;
      float2 f0 = __half22float2(e0), f1 = __half22float2(e1);
      s0 += f0.x + f0.y;  s1 += f1.x + f1.y;
    }
    s0 += __shfl_xor_sync(0xffffffffu, s0, 1);
    s0 += __shfl_xor_sync(0xffffffffu, s0, 2);
    s1 += __shfl_xor_sync(0xffffffffu, s1, 1);
    s1 += __shfl_xor_sync(0xffffffffu, s1, 2);
    l0 = l0*corr0 + s0;  l1 = l1*corr1 + s1;
    m0r = mn0;  m1r = mn1;
#pragma unroll
    for (int nt = 0; nt < 8; nt++){
      o[nt][0] *= corr0; o[nt][1] *= corr0;
      o[nt][2] *= corr1; o[nt][3] *= corr1;
    }

    // O += P V
    const uint32_t vb = kb + 8192;
#pragma unroll
    for (int kc = 0; kc < 4; kc++){
      uint32_t ph[4] = { pf[4*kc], pf[4*kc+1], pf[4*kc+2], pf[4*kc+3] };
#pragma unroll
      for (int ntp = 0; ntp < 4; ntp++){
        int r = kc*16 + rVv;
        int ch = ntp*2 + chVv;
        uint32_t ad = vb + r*128 + ((ch ^ (r & 7)) * 16);
        uint32_t w0,w1,w2,w3;
        LDSM4T(w0,w1,w2,w3, ad);
        MMAH(o[2*ntp],   ph, w0, w1);
        MMAH(o[2*ntp+1], ph, w2, w3);
      }
    }
  }

  // epilogue: normalize, write single fp16 attn [b][l][h][d]
  float inv0 = 1.f / l0, inv1 = 1.f / l1;
  size_t ob0 = ((size_t)(b*Lc + qt*64 + warp*16 + g) * Hc + h) * HDc;
  size_t ob1 = ob0 + (size_t)8 * Hc * HDc;
#pragma unroll
  for (int nt = 0; nt < 8; nt++){
    int d = nt*8 + 2*t;
    __half2 a = { __float2half_rn(o[nt][0]*inv0), __float2half_rn(o[nt][1]*inv0) };
    __half2 c = { __float2half_rn(o[nt][2]*inv1), __float2half_rn(o[nt][3]*inv1) };
    *(__half2*)(O + ob0 + d) = a;
    *(__half2*)(O + ob1 + d) = c;
  }
}

// ---------------------------------------------------------------------------
extern "C" void kernel_launch(void* const* d_in, const int* in_sizes, int n_in,
                              void* d_out, int out_size)
{
  const float* x   = (const float*)d_in[0];
  const float* Wq  = (const float*)d_in[1];
  const float* Wk  = (const float*)d_in[2];
  const float* Wv  = (const float*)d_in[3];
  const float* Wo  = (const float*)d_in[4];
  const float* qnw = (const float*)d_in[5];
  const float* knw = (const float*)d_in[6];
  float* out = (float*)d_out;

  half_t *x16,*wqkv,*wo,*at,*qq,*kk,*vv;
  cudaGetSymbolAddress((void**)&x16, g_x16);
  cudaGetSymbolAddress((void**)&wqkv, g_wqkvT);
  cudaGetSymbolAddress((void**)&wo, g_woT);
  cudaGetSymbolAddress((void**)&qq, g_q);
  cudaGetSymbolAddress((void**)&kk, g_k);  cudaGetSymbolAddress((void**)&vv, g_v);
  cudaGetSymbolAddress((void**)&at, g_at);

  const int M = Mtok;

  // (1) activation convert
  xcvt<<<(M*Dc/4 + 255)/256, 256>>>(x, x16, M*Dc/4);
  // (2) all weight transposes in one launch
  wsplit_all<<<dim3(64, 64, 4), dim3(32,8)>>>(Wq, Wk, Wv, Wo, wqkv, wo);

  // (3) fused QKV projection + RMSNorm + RoPE -> head-major fp16
  cudaFuncSetAttribute(gemm_qkv, cudaFuncAttributeMaxDynamicSharedMemorySize, 2*GSTG1);
  gemm_qkv<<<dim3(QKVN/128, M/128), 256, 2*GSTG1>>>(x16, wqkv, qnw, knw, qq, kk, vv);

  // (4) flash attention
  cudaFuncSetAttribute(flash_tc, cudaFuncAttributeMaxDynamicSharedMemorySize, FLASH_SMEM);
  flash_tc<<<dim3(Lc/64, Hc, Bc), 128, FLASH_SMEM>>>(qq, kk, vv, at);

  // (5) output projection
  cudaFuncSetAttribute(gemm_fp16, cudaFuncAttributeMaxDynamicSharedMemorySize, 2*GSTG1);
  gemm_fp16<<<dim3(Dc/128, M/128), 256, 2*GSTG1>>>(at, wo, out, M, Dc, Dc);
}

// round 12
// speedup vs baseline: 2.6316x; 1.0054x over previous
#include <cuda_runtime.h>
#include <cuda_fp16.h>
#include <math.h>
#include <stdint.h>
#include <stddef.h>

#define Bc 2
#define Lc 2048
#define Dc 2048
#define Hc 32
#define HKVc 8
#define HDc 64
#define Mtok (Bc*Lc)
#define QKVN 3072          // fused projection width: 2048 Q | 512 K | 512 V
#define QSCALE 0.18033688011112042f   // 0.125 * log2(e): S in log2 domain

typedef __half half_t;

// ---------------- scratch (__device__ globals; no allocs allowed) -----------
__device__ __align__(16) half_t g_x16[(size_t)Mtok*Dc];     // x single fp16
__device__ __align__(16) half_t g_wqkvT[(size_t)QKVN*Dc];   // single fp16
__device__ __align__(16) half_t g_woT[(size_t)Dc*Hc*HDc];   // single fp16
__device__ __align__(16) half_t g_q[(size_t)Bc*Hc*Lc*HDc];  // Q*QSCALE fp16
__device__ __align__(16) half_t g_k[(size_t)Bc*HKVc*Lc*HDc];// K single fp16
__device__ __align__(16) half_t g_v[(size_t)Bc*HKVc*Lc*HDc];// V single fp16
__device__ __align__(16) half_t g_at[(size_t)Mtok*Hc*HDc];  // attn single fp16

// ---------------- PTX helpers ----------------------------------------------
#define MMAH(CR, A, B0, B1)                                                  \
  asm volatile(                                                              \
      "mma.sync.aligned.m16n8k16.row.col.f32.f16.f16.f32 "                   \
      "{%0,%1,%2,%3},{%4,%5,%6,%7},{%8,%9},{%0,%1,%2,%3};"                   \
      : "+f"((CR)[0]), "+f"((CR)[1]), "+f"((CR)[2]), "+f"((CR)[3])           \
      : "r"((A)[0]), "r"((A)[1]), "r"((A)[2]), "r"((A)[3]), "r"(B0), "r"(B1))

#define LDSM4(R0,R1,R2,R3,ADDR)                                              \
  asm volatile("ldmatrix.sync.aligned.m8n8.x4.shared.b16 {%0,%1,%2,%3},[%4];"\
      : "=r"(R0),"=r"(R1),"=r"(R2),"=r"(R3) : "r"(ADDR))

#define LDSM4T(R0,R1,R2,R3,ADDR)                                             \
  asm volatile("ldmatrix.sync.aligned.m8n8.x4.trans.shared.b16 {%0,%1,%2,%3},[%4];"\
      : "=r"(R0),"=r"(R1),"=r"(R2),"=r"(R3) : "r"(ADDR))

__device__ __forceinline__ void cp16(uint32_t dst, const void* src){
  asm volatile("cp.async.cg.shared.global [%0], [%1], 16;" :: "r"(dst), "l"(src));
}
#define CPCOMMIT() asm volatile("cp.async.commit_group;")
#define CPWAIT0()  asm volatile("cp.async.wait_group 0;")

// ---------------- convert passes --------------------------------------------
__global__ void xcvt(const float* __restrict__ src, half_t* __restrict__ d, int n4)
{
  int i = blockIdx.x * blockDim.x + threadIdx.x;
  if (i >= n4) return;
  float4 v = ((const float4*)src)[i];
  __half2 h0 = { __float2half_rn(v.x), __float2half_rn(v.y) };
  __half2 h1 = { __float2half_rn(v.z), __float2half_rn(v.w) };
  ((__half2*)d)[2*i] = h0; ((__half2*)d)[2*i+1] = h1;
}

// One launch for all four weight transposes -> single fp16 [N][K]
__global__ void wsplit_all(const float* __restrict__ Wq,
                           const float* __restrict__ Wk,
                           const float* __restrict__ Wv,
                           const float* __restrict__ Wo,
                           half_t* __restrict__ wqkv, half_t* __restrict__ wo)
{
  const int z = blockIdx.z;
  const float* W; half_t* T; int K, N;
  if (z == 0){ W = Wq; T = wqkv;                       K = Dc;     N = Hc*HDc; }
  else if (z == 1){ W = Wk; T = wqkv + (size_t)2048*Dc; K = Dc;    N = HKVc*HDc; }
  else if (z == 2){ W = Wv; T = wqkv + (size_t)2560*Dc; K = Dc;    N = HKVc*HDc; }
  else            { W = Wo; T = wo;                     K = Hc*HDc; N = Dc; }
  if (blockIdx.x * 32 >= N) return;

  __shared__ float tile[32][33];
  int k0 = blockIdx.y*32, n0 = blockIdx.x*32;
  int tx = threadIdx.x, ty = threadIdx.y;
#pragma unroll
  for (int i = 0; i < 4; i++)
    tile[ty + 8*i][tx] = W[(size_t)(k0 + ty + 8*i) * N + n0 + tx];
  __syncthreads();
#pragma unroll
  for (int i = 0; i < 4; i++){
    int n = n0 + ty + 8*i;
    T[(size_t)n*K + k0 + tx] = __float2half_rn(tile[tx][ty + 8*i]);
  }
}

// ---------------- fused QKV GEMM + RMSNorm + RoPE + head-major fp16 ---------
#define GSTG1 32768
__global__ __launch_bounds__(256) void gemm_qkv(
    const half_t* __restrict__ A, const half_t* __restrict__ B,
    const float* __restrict__ qnw, const float* __restrict__ knw,
    half_t* __restrict__ qq, half_t* __restrict__ kk, half_t* __restrict__ vv)
{
  const int K = Dc;
  extern __shared__ char smraw[];
  const uint32_t smb = (uint32_t)__cvta_generic_to_shared(smraw);
  const int tid = threadIdx.x, lane = tid & 31, warp = tid >> 5;
  const int wm = (warp & 3) * 32, wn = (warp >> 2) * 64;
  const int g = lane >> 2, t = lane & 3;
  const int row0 = blockIdx.y * 128, col0 = blockIdx.x * 128;
  const int KI = K >> 6;

  const half_t* gsrc[2] = { A + (size_t)row0 * K, B + (size_t)col0 * K };

  auto stage = [&](int ki, int s){
#pragma unroll
    for (int q = 0; q < 2; q++)
#pragma unroll
      for (int it = 0; it < 4; it++){
        int fid = tid + it * 256;
        int row = fid >> 3, ch = fid & 7;
        cp16(smb + s*GSTG1 + q*16384 + row*128 + ((ch ^ (row & 7)) * 16),
             gsrc[q] + (size_t)row * K + ki*64 + ch*8);
      }
  };

  float c[2][8][4];
#pragma unroll
  for (int i=0;i<2;i++)
#pragma unroll
    for (int j=0;j<8;j++)
#pragma unroll
      for (int e=0;e<4;e++) c[i][j][e] = 0.f;

  stage(0, 0); CPCOMMIT();

  for (int ki = 0; ki < KI; ki++){
    int s = ki & 1;
    CPWAIT0();
    __syncthreads();
    if (ki + 1 < KI){ stage(ki + 1, s ^ 1); CPCOMMIT(); }

    const uint32_t ab = smb + s*GSTG1, bb = ab + 16384;
    const int rA  = (lane & 7) + ((lane >> 3) & 1) * 8;
    const int chA = (lane >> 4);
    const int rB  = (lane & 7) + ((lane >> 4) << 3);
    const int chB = (lane >> 3) & 1;
#pragma unroll
    for (int kc = 0; kc < 4; kc++){
      uint32_t ah[2][4];
#pragma unroll
      for (int mt = 0; mt < 2; mt++){
        int r = wm + mt*16 + rA;
        int ch = kc*2 + chA;
        uint32_t ad = ab + r*128 + ((ch ^ (r & 7)) * 16);
        LDSM4(ah[mt][0], ah[mt][1], ah[mt][2], ah[mt][3], ad);
      }
#pragma unroll
      for (int ntp = 0; ntp < 4; ntp++){
        int r = wn + ntp*16 + rB;
        int ch = kc*2 + chB;
        uint32_t ad = bb + r*128 + ((ch ^ (r & 7)) * 16);
        uint32_t b0,b1,b2,b3;
        LDSM4(b0,b1,b2,b3, ad);
#pragma unroll
        for (int mt = 0; mt < 2; mt++){
          MMAH(c[mt][2*ntp],   ah[mt], b0, b1);
          MMAH(c[mt][2*ntp+1], ah[mt], b2, b3);
        }
      }
    }
    __syncthreads();
  }

  // ---- fused epilogue: RMSNorm + RoPE + head-major fp16 ----
  const int gcol = col0 + wn;
  int mode, nh, head;
  const float* w = qnw;
  if (gcol < 2048)      { mode = 0; nh = Hc;   head = gcol >> 6; w = qnw; }
  else if (gcol < 2560) { mode = 1; nh = HKVc; head = (gcol - 2048) >> 6; w = knw; }
  else                  { mode = 2; nh = HKVc; head = (gcol - 2560) >> 6; }

  float invf[8];
  if (mode < 2){
#pragma unroll
    for (int nt = 0; nt < 4; nt++){
      int d0 = nt*8 + 2*t;
      invf[2*nt]   = powf(1000000.0f, -((float)(2*d0))     * (1.0f/64.0f));
      invf[2*nt+1] = powf(1000000.0f, -((float)(2*(d0+1))) * (1.0f/64.0f));
    }
  }
  const float oscale = (mode == 0) ? QSCALE : 1.0f;

#pragma unroll
  for (int mt = 0; mt < 2; mt++){
    int r0 = row0 + wm + mt*16 + g;
    float rn0 = 0.f, rn1 = 0.f;
    if (mode < 2){
      float ss0 = 0.f, ss1 = 0.f;
#pragma unroll
      for (int nt = 0; nt < 8; nt++){
        ss0 += c[mt][nt][0]*c[mt][nt][0] + c[mt][nt][1]*c[mt][nt][1];
        ss1 += c[mt][nt][2]*c[mt][nt][2] + c[mt][nt][3]*c[mt][nt][3];
      }
      ss0 += __shfl_xor_sync(0xffffffffu, ss0, 1);
      ss0 += __shfl_xor_sync(0xffffffffu, ss0, 2);
      ss1 += __shfl_xor_sync(0xffffffffu, ss1, 1);
      ss1 += __shfl_xor_sync(0xffffffffu, ss1, 2);
      rn0 = rsqrtf(ss0 * (1.0f/64.0f) + 1e-5f);
      rn1 = rsqrtf(ss1 * (1.0f/64.0f) + 1e-5f);
    }

#pragma unroll
    for (int half2row = 0; half2row < 2; half2row++){
      int r = r0 + half2row*8;
      int e = half2row*2;
      float rn = half2row ? rn1 : rn0;
      int pos = r & (Lc-1);
      int b = r >> 11;
      size_t base = ((size_t)(b*nh + head)*Lc + pos) * HDc;

      if (mode == 2){
#pragma unroll
        for (int nt = 0; nt < 8; nt++){
          int d0 = nt*8 + 2*t;
          __half2 v2 = { __float2half_rn(c[mt][nt][e]), __float2half_rn(c[mt][nt][e+1]) };
          *(__half2*)(vv + base + d0) = v2;
        }
      } else {
        float fpos = (float)pos;
        half_t* dst = (mode == 0) ? qq : kk;
#pragma unroll
        for (int nt = 0; nt < 4; nt++){
          int d0 = nt*8 + 2*t;
          float x1a = c[mt][nt][e]   * rn * w[d0];
          float x1b = c[mt][nt][e+1] * rn * w[d0+1];
          float x2a = c[mt][nt+4][e]   * rn * w[d0+32];
          float x2b = c[mt][nt+4][e+1] * rn * w[d0+33];
          float anga = fpos * invf[2*nt],  angb = fpos * invf[2*nt+1];
          float ca = cosf(anga), sa = sinf(anga);
          float cb = cosf(angb), sb = sinf(angb);
          float y1a = (x1a*ca - x2a*sa) * oscale,  y1b = (x1b*cb - x2b*sb) * oscale;
          float y2a = (x2a*ca + x1a*sa) * oscale,  y2b = (x2b*cb + x1b*sb) * oscale;
          __half2 v1 = { __float2half_rn(y1a), __float2half_rn(y1b) };
          __half2 v2 = { __float2half_rn(y2a), __float2half_rn(y2b) };
          *(__half2*)(dst + base + d0)      = v1;
          *(__half2*)(dst + base + d0 + 32) = v2;
        }
      }
    }
  }
}

// ---------------- single fp16 tensor-core GEMM (Wo) -------------------------
__global__ __launch_bounds__(256) void gemm_fp16(
    const half_t* __restrict__ A, const half_t* __restrict__ B,
    float* __restrict__ C, int M, int N, int K)
{
  extern __shared__ char smraw[];
  const uint32_t smb = (uint32_t)__cvta_generic_to_shared(smraw);
  const int tid = threadIdx.x, lane = tid & 31, warp = tid >> 5;
  const int wm = (warp & 3) * 32, wn = (warp >> 2) * 64;
  const int g = lane >> 2, t = lane & 3;
  const int row0 = blockIdx.y * 128, col0 = blockIdx.x * 128;
  const int KI = K >> 6;

  const half_t* gsrc[2] = { A + (size_t)row0 * K, B + (size_t)col0 * K };

  auto stage = [&](int ki, int s){
#pragma unroll
    for (int q = 0; q < 2; q++)
#pragma unroll
      for (int it = 0; it < 4; it++){
        int fid = tid + it * 256;
        int row = fid >> 3, ch = fid & 7;
        cp16(smb + s*GSTG1 + q*16384 + row*128 + ((ch ^ (row & 7)) * 16),
             gsrc[q] + (size_t)row * K + ki*64 + ch*8);
      }
  };

  float c[2][8][4];
#pragma unroll
  for (int i=0;i<2;i++)
#pragma unroll
    for (int j=0;j<8;j++)
#pragma unroll
      for (int e=0;e<4;e++) c[i][j][e] = 0.f;

  stage(0, 0); CPCOMMIT();

  for (int ki = 0; ki < KI; ki++){
    int s = ki & 1;
    CPWAIT0();
    __syncthreads();
    if (ki + 1 < KI){ stage(ki + 1, s ^ 1); CPCOMMIT(); }

    const uint32_t ab = smb + s*GSTG1, bb = ab + 16384;
    const int rA  = (lane & 7) + ((lane >> 3) & 1) * 8;
    const int chA = (lane >> 4);
    const int rB  = (lane & 7) + ((lane >> 4) << 3);
    const int chB = (lane >> 3) & 1;
#pragma unroll
    for (int kc = 0; kc < 4; kc++){
      uint32_t ah[2][4];
#pragma unroll
      for (int mt = 0; mt < 2; mt++){
        int r = wm + mt*16 + rA;
        int ch = kc*2 + chA;
        uint32_t ad = ab + r*128 + ((ch ^ (r & 7)) * 16);
        LDSM4(ah[mt][0], ah[mt][1], ah[mt][2], ah[mt][3], ad);
      }
#pragma unroll
      for (int ntp = 0; ntp < 4; ntp++){
        int r = wn + ntp*16 + rB;
        int ch = kc*2 + chB;
        uint32_t ad = bb + r*128 + ((ch ^ (r & 7)) * 16);
        uint32_t b0,b1,b2,b3;
        LDSM4(b0,b1,b2,b3, ad);
#pragma unroll
        for (int mt = 0; mt < 2; mt++){
          MMAH(c[mt][2*ntp],   ah[mt], b0, b1);
          MMAH(c[mt][2*ntp+1], ah[mt], b2, b3);
        }
      }
    }
    __syncthreads();
  }

#pragma unroll
  for (int mt = 0; mt < 2; mt++)
#pragma unroll
    for (int nt = 0; nt < 8; nt++){
      int r = row0 + wm + mt*16 + g;
      int cc = col0 + wn + nt*8 + 2*t;
      float2 v0 = { c[mt][nt][0], c[mt][nt][1] };
      float2 v1 = { c[mt][nt][2], c[mt][nt][3] };
      *(float2*)(C + (size_t)r * N + cc) = v0;
      *(float2*)(C + (size_t)(r + 8) * N + cc) = v1;
    }
}

// ---------------- tensor-core flash attention (128-key tiles) ---------------
// smem: Q 8K | 2 stages x (K 16K | V 16K) = 72K total. 3 CTAs/SM.
#define FSM_KV  8192
#define KV_STG  32768
#define FLASH_SMEM (8192 + 2*KV_STG)

__global__ __launch_bounds__(128, 3) void flash_tc(
    const half_t* __restrict__ Qp, const half_t* __restrict__ Kp,
    const half_t* __restrict__ Vp, half_t* __restrict__ O)
{
  extern __shared__ char smraw[];
  const uint32_t smb = (uint32_t)__cvta_generic_to_shared(smraw);
  const int tid = threadIdx.x, lane = tid & 31, warp = tid >> 5;
  const int qt = gridDim.x - 1 - blockIdx.x;   // big tiles first
  const int h = blockIdx.y, b = blockIdx.z, hkv = h >> 2;
  const int g = lane >> 2, t = lane & 3;

  const half_t* qp = Qp + ((size_t)(b*Hc + h)*Lc + qt*64) * HDc;
  const size_t kvoff = (size_t)(b*HKVc + hkv) * Lc * HDc;
  const half_t* kvsrc[2] = { Kp + kvoff, Vp + kvoff };

  // stage Q (once): 64 rows x 64 cols fp16 (already * 0.125*log2e)
#pragma unroll
  for (int it = 0; it < 4; it++){
    int fid = tid + it * 128;
    int row = fid >> 3, ch = fid & 7;
    uint4 v4 = *(const uint4*)(qp + row*64 + ch*8);
    *(uint4*)(smraw + row*128 + ((ch ^ (row & 7)) * 16)) = v4;
  }

  // stage a 128-row KV block (K 16K + V 16K)
  auto stageKV = [&](int kt, int s){
#pragma unroll
    for (int q = 0; q < 2; q++)
#pragma unroll
      for (int it = 0; it < 8; it++){
        int fid = tid + it * 128;          // 0..1023: 128 rows x 8 chunks
        int row = fid >> 3, ch = fid & 7;
        cp16(smb + FSM_KV + s*KV_STG + q*16384 + row*128 + ((ch ^ (row & 7))*16),
             kvsrc[q] + (size_t)(kt*128 + row)*64 + ch*8);
      }
  };

  stageKV(0, 0); CPCOMMIT();
  __syncthreads();

  // Q fragments (persistent)
  uint32_t qf[4][4];
  {
    int r = warp*16 + (lane & 7) + ((lane >> 3) & 1) * 8;
#pragma unroll
    for (int kc = 0; kc < 4; kc++){
      int ch = kc*2 + (lane >> 4);
      uint32_t ad = smb + r*128 + ((ch ^ (r & 7)) * 16);
      LDSM4(qf[kc][0], qf[kc][1], qf[kc][2], qf[kc][3], ad);
    }
  }

  float o[8][4];
#pragma unroll
  for (int nt=0;nt<8;nt++)
#pragma unroll
    for (int e=0;e<4;e++) o[nt][e] = 0.f;
  float m0r = -1e30f, m1r = -1e30f, l0 = 0.f, l1 = 0.f;

  const int r0g = qt*64 + warp*16 + g;
  const int r1g = r0g + 8;
  const int rBv = (lane & 7) + ((lane >> 4) << 3);
  const int chBv = (lane >> 3) & 1;
  const int rVv = (lane & 7) + (((lane >> 3) & 1) << 3);
  const int chVv = lane >> 4;
  const int nkt = (qt + 2) >> 1;           // ceil((qt+1)/2) 128-key blocks

  for (int kt = 0; kt < nkt; kt++){
    int s = kt & 1;
    CPWAIT0();
    __syncthreads();
    if (kt + 1 < nkt){ stageKV(kt + 1, s ^ 1); CPCOMMIT(); }

    const uint32_t kb = smb + FSM_KV + s*KV_STG;

    float sf[16][4];
#pragma unroll
    for (int nt=0;nt<16;nt++)
#pragma unroll
      for (int e=0;e<4;e++) sf[nt][e] = 0.f;

    // S = Q K^T over 128 keys (log2 domain)
#pragma unroll
    for (int kc = 0; kc < 4; kc++){
#pragma unroll
      for (int ntp = 0; ntp < 8; ntp++){
        int r = ntp*16 + rBv;
        int ch = kc*2 + chBv;
        uint32_t ad = kb + r*128 + ((ch ^ (r & 7)) * 16);
        uint32_t b0,b1,b2,b3;
        LDSM4(b0,b1,b2,b3, ad);
        MMAH(sf[2*ntp],   qf[kc], b0, b1);
        MMAH(sf[2*ntp+1], qf[kc], b2, b3);
      }
    }

    // causal mask (only blocks overlapping/beyond the diagonal)
    if (kt*128 + 127 > r0g){
#pragma unroll
      for (int nt = 0; nt < 16; nt++){
        int c0 = kt*128 + nt*8 + 2*t;
        if (c0     > r0g) sf[nt][0] = -1e30f;
        if (c0 + 1 > r0g) sf[nt][1] = -1e30f;
        if (c0     > r1g) sf[nt][2] = -1e30f;
        if (c0 + 1 > r1g) sf[nt][3] = -1e30f;
      }
    }
    float tm0 = -1e30f, tm1 = -1e30f;
#pragma unroll
    for (int nt = 0; nt < 16; nt++){
      tm0 = fmaxf(tm0, fmaxf(sf[nt][0], sf[nt][1]));
      tm1 = fmaxf(tm1, fmaxf(sf[nt][2], sf[nt][3]));
    }
    tm0 = fmaxf(tm0, __shfl_xor_sync(0xffffffffu, tm0, 1));
    tm0 = fmaxf(tm0, __shfl_xor_sync(0xffffffffu, tm0, 2));
    tm1 = fmaxf(tm1, __shfl_xor_sync(0xffffffffu, tm1, 1));
    tm1 = fmaxf(tm1, __shfl_xor_sync(0xffffffffu, tm1, 2));

    float mn0 = fmaxf(m0r, tm0), mn1 = fmaxf(m1r, tm1);
    float corr0 = exp2f(m0r - mn0), corr1 = exp2f(m1r - mn1);

    // P = 2^(s - mn) in fp16x2 — output IS the packed A-fragment
    uint32_t pf[32];
    float s0 = 0.f, s1 = 0.f;
#pragma unroll
    for (int nt = 0; nt < 16; nt++){
      __half2 e0 = h2exp2(__floats2half2_rn(sf[nt][0]-mn0, sf[nt][1]-mn0));
      __half2 e1 = h2exp2(__floats2half2_rn(sf[nt][2]-mn1, sf[nt][3]-mn1));
      pf[2*nt]   = *(uint32_t*)&e0;
      pf[2*nt+1] = *(uint32_t*)&e1;
      float2 f0 = __half22float2(e0), f1 = __half22float2(e1);
      s0 += f0.x + f0.y;  s1 += f1.x + f1.y;
    }
    s0 += __shfl_xor_sync(0xffffffffu, s0, 1);
    s0 += __shfl_xor_sync(0xffffffffu, s0, 2);
    s1 += __shfl_xor_sync(0xffffffffu, s1, 1);
    s1 += __shfl_xor_sync(0xffffffffu, s1, 2);
    l0 = l0*corr0 + s0;  l1 = l1*corr1 + s1;
    m0r = mn0;  m1r = mn1;
#pragma unroll
    for (int nt = 0; nt < 8; nt++){
      o[nt][0] *= corr0; o[nt][1] *= corr0;
      o[nt][2] *= corr1; o[nt][3] *= corr1;
    }

    // O += P V over 128 keys (8 k-chunks of 16)
    const uint32_t vb = kb + 16384;
#pragma unroll
    for (int kc = 0; kc < 8; kc++){
      uint32_t ph[4] = { pf[4*kc], pf[4*kc+1], pf[4*kc+2], pf[4*kc+3] };
#pragma unroll
      for (int ntp = 0; ntp < 4; ntp++){
        int r = kc*16 + rVv;
        int ch = ntp*2 + chVv;
        uint32_t ad = vb + r*128 + ((ch ^ (r & 7)) * 16);
        uint32_t w0,w1,w2,w3;
        LDSM4T(w0,w1,w2,w3, ad);
        MMAH(o[2*ntp],   ph, w0, w1);
        MMAH(o[2*ntp+1], ph, w2, w3);
      }
    }
  }

  // epilogue: normalize, write single fp16 attn [b][l][h][d]
  float inv0 = 1.f / l0, inv1 = 1.f / l1;
  size_t ob0 = ((size_t)(b*Lc + qt*64 + warp*16 + g) * Hc + h) * HDc;
  size_t ob1 = ob0 + (size_t)8 * Hc * HDc;
#pragma unroll
  for (int nt = 0; nt < 8; nt++){
    int d = nt*8 + 2*t;
    __half2 a = { __float2half_rn(o[nt][0]*inv0), __float2half_rn(o[nt][1]*inv0) };
    __half2 c = { __float2half_rn(o[nt][2]*inv1), __float2half_rn(o[nt][3]*inv1) };
    *(__half2*)(O + ob0 + d) = a;
    *(__half2*)(O + ob1 + d) = c;
  }
}

// ---------------------------------------------------------------------------
extern "C" void kernel_launch(void* const* d_in, const int* in_sizes, int n_in,
                              void* d_out, int out_size)
{
  const float* x   = (const float*)d_in[0];
  const float* Wq  = (const float*)d_in[1];
  const float* Wk  = (const float*)d_in[2];
  const float* Wv  = (const float*)d_in[3];
  const float* Wo  = (const float*)d_in[4];
  const float* qnw = (const float*)d_in[5];
  const float* knw = (const float*)d_in[6];
  float* out = (float*)d_out;

  half_t *x16,*wqkv,*wo,*at,*qq,*kk,*vv;
  cudaGetSymbolAddress((void**)&x16, g_x16);
  cudaGetSymbolAddress((void**)&wqkv, g_wqkvT);
  cudaGetSymbolAddress((void**)&wo, g_woT);
  cudaGetSymbolAddress((void**)&qq, g_q);
  cudaGetSymbolAddress((void**)&kk, g_k);  cudaGetSymbolAddress((void**)&vv, g_v);
  cudaGetSymbolAddress((void**)&at, g_at);

  const int M = Mtok;

  // (1) activation convert
  xcvt<<<(M*Dc/4 + 255)/256, 256>>>(x, x16, M*Dc/4);
  // (2) all weight transposes in one launch
  wsplit_all<<<dim3(64, 64, 4), dim3(32,8)>>>(Wq, Wk, Wv, Wo, wqkv, wo);

  // (3) fused QKV projection + RMSNorm + RoPE -> head-major fp16
  cudaFuncSetAttribute(gemm_qkv, cudaFuncAttributeMaxDynamicSharedMemorySize, 2*GSTG1);
  gemm_qkv<<<dim3(QKVN/128, M/128), 256, 2*GSTG1>>>(x16, wqkv, qnw, knw, qq, kk, vv);

  // (4) flash attention
  cudaFuncSetAttribute(flash_tc, cudaFuncAttributeMaxDynamicSharedMemorySize, FLASH_SMEM);
  flash_tc<<<dim3(Lc/64, Hc, Bc), 128, FLASH_SMEM>>>(qq, kk, vv, at);

  // (5) output projection
  cudaFuncSetAttribute(gemm_fp16, cudaFuncAttributeMaxDynamicSharedMemorySize, 2*GSTG1);
  gemm_fp16<<<dim3(Dc/128, M/128), 256, 2*GSTG1>>>(at, wo, out, M, Dc, Dc);
}